// round 1
// baseline (speedup 1.0000x reference)
#include <cuda_runtime.h>
#include <cstdint>

#define BATCH   2
#define T_SEQ   2048
#define C_EMB   1024
#define NHEAD   16
#define HDIM    64
#define BT      (BATCH * T_SEQ)      // 4096
#define C3      (3 * C_EMB)          // 3072

// Scratch (allocation-free rule: device globals)
__device__ float g_qkv[(size_t)BT * C3];   // 48 MB
__device__ float g_y[(size_t)BT * C_EMB];  // 16 MB

// ---------------- packed f32x2 helpers (Blackwell FFMA2) ----------------
static __device__ __forceinline__ unsigned long long pack2(float x, float y) {
    unsigned long long r;
    asm("mov.b64 %0, {%1, %2};" : "=l"(r) : "f"(x), "f"(y));
    return r;
}
static __device__ __forceinline__ float2 unpack2(unsigned long long v) {
    float2 r;
    asm("mov.b64 {%0, %1}, %2;" : "=f"(r.x), "=f"(r.y) : "l"(v));
    return r;
}
static __device__ __forceinline__ unsigned long long ffma2(
    unsigned long long a, unsigned long long b, unsigned long long c) {
    unsigned long long d;
    asm("fma.rn.f32x2 %0, %1, %2, %3;" : "=l"(d) : "l"(a), "l"(b), "l"(c));
    return d;
}

// ---------------- GEMM: C = A @ B + bias (row-major) ----------------
// BM=128, BN=128, BK=16, 256 threads, 8x8 per-thread microtile via FFMA2.
__global__ __launch_bounds__(256, 2)
void gemm_bias_kernel(const float* __restrict__ A, const float* __restrict__ B,
                      const float* __restrict__ bias, float* __restrict__ C,
                      int M, int N, int K)
{
    __shared__ float As[16][128];   // As[k][m]
    __shared__ float Bs[16][128];   // Bs[k][n]

    const int t  = threadIdx.x;
    const int tx = t & 15;          // 0..15 -> cols tx*8
    const int ty = t >> 4;          // 0..15 -> rows ty*8
    const int bm = blockIdx.y * 128;
    const int bn = blockIdx.x * 128;

    unsigned long long acc[8][4] = {};   // 8 rows x 4 col-pairs

    // A loader mapping: row ar (+64), k-cols ak..ak+3
    const int ar = t >> 2;
    const int ak = (t & 3) << 2;
    // B loader mapping: k-row br (+8), cols bc..bc+3
    const int br = t >> 5;
    const int bc = (t & 31) << 2;

    const float* Aptr0 = A + (size_t)(bm + ar) * K + ak;
    const float* Aptr1 = A + (size_t)(bm + ar + 64) * K + ak;
    const float* Bptr0 = B + (size_t)br * N + bn + bc;
    const float* Bptr1 = B + (size_t)(br + 8) * N + bn + bc;

    for (int kt = 0; kt < K; kt += 16) {
        float4 a0 = *(const float4*)(Aptr0 + kt);
        float4 a1 = *(const float4*)(Aptr1 + kt);
        float4 b0 = *(const float4*)(Bptr0 + (size_t)kt * N);
        float4 b1 = *(const float4*)(Bptr1 + (size_t)kt * N);

        As[ak + 0][ar] = a0.x;  As[ak + 1][ar] = a0.y;
        As[ak + 2][ar] = a0.z;  As[ak + 3][ar] = a0.w;
        As[ak + 0][ar + 64] = a1.x;  As[ak + 1][ar + 64] = a1.y;
        As[ak + 2][ar + 64] = a1.z;  As[ak + 3][ar + 64] = a1.w;
        *(float4*)&Bs[br][bc]     = b0;
        *(float4*)&Bs[br + 8][bc] = b1;
        __syncthreads();

        #pragma unroll
        for (int k = 0; k < 16; k++) {
            float4 av0 = *(const float4*)&As[k][ty * 8];
            float4 av1 = *(const float4*)&As[k][ty * 8 + 4];
            unsigned long long a2[8];
            a2[0] = pack2(av0.x, av0.x); a2[1] = pack2(av0.y, av0.y);
            a2[2] = pack2(av0.z, av0.z); a2[3] = pack2(av0.w, av0.w);
            a2[4] = pack2(av1.x, av1.x); a2[5] = pack2(av1.y, av1.y);
            a2[6] = pack2(av1.z, av1.z); a2[7] = pack2(av1.w, av1.w);

            const ulonglong2* bp = (const ulonglong2*)&Bs[k][tx * 8];
            ulonglong2 bv0 = bp[0];
            ulonglong2 bv1 = bp[1];
            unsigned long long b2[4] = { bv0.x, bv0.y, bv1.x, bv1.y };

            #pragma unroll
            for (int i = 0; i < 8; i++) {
                #pragma unroll
                for (int j = 0; j < 4; j++) {
                    acc[i][j] = ffma2(a2[i], b2[j], acc[i][j]);
                }
            }
        }
        __syncthreads();
    }

    // Epilogue: add bias, store
    float bv[8];
    {
        float4 t0 = *(const float4*)&bias[bn + tx * 8];
        float4 t1 = *(const float4*)&bias[bn + tx * 8 + 4];
        bv[0] = t0.x; bv[1] = t0.y; bv[2] = t0.z; bv[3] = t0.w;
        bv[4] = t1.x; bv[5] = t1.y; bv[6] = t1.z; bv[7] = t1.w;
    }
    #pragma unroll
    for (int i = 0; i < 8; i++) {
        float2 p0 = unpack2(acc[i][0]);
        float2 p1 = unpack2(acc[i][1]);
        float2 p2 = unpack2(acc[i][2]);
        float2 p3 = unpack2(acc[i][3]);
        float4 o0 = make_float4(p0.x + bv[0], p0.y + bv[1], p1.x + bv[2], p1.y + bv[3]);
        float4 o1 = make_float4(p2.x + bv[4], p2.y + bv[5], p3.x + bv[6], p3.y + bv[7]);
        float* Crow = C + (size_t)(bm + ty * 8 + i) * N + bn + tx * 8;
        *(float4*)(Crow)     = o0;
        *(float4*)(Crow + 4) = o1;
    }
}

// ---------------- Flash attention (causal), fp32 ----------------
// One CTA = 64 query rows for one (b, h). Tiles of 64 keys.
// Qt[d][row], Kt[d][key] transposed in smem (conflict-free inner loops).
// P tile reuses the Kt buffer. 256 threads, 4x4 microtile.
__global__ __launch_bounds__(256)
void attn_kernel(const float* __restrict__ qkv, float* __restrict__ y)
{
    __shared__ float Qt[64][64];   // Qt[d][row]
    __shared__ float KtP[64][64];  // Kt[d][key] -> then P[row][key]
    __shared__ float Vs[64][64];   // Vs[key][d]

    const int t  = threadIdx.x;
    const int tx = t & 15;   // key/out-col group: cols tx*4..tx*4+3
    const int ty = t >> 4;   // row group: rows ty*4..ty*4+3
    const int qb = blockIdx.x;
    const int h  = blockIdx.y;
    const int b  = blockIdx.z;

    const int lr = t >> 4;        // loader row base 0..15 (+16 per iter)
    const int ld4 = (t & 15) * 4; // loader d offset

    // Load Q tile transposed
    #pragma unroll
    for (int it = 0; it < 4; it++) {
        int row = lr + it * 16;
        size_t g = (size_t)(b * T_SEQ + qb * 64 + row) * C3 + h * HDIM + ld4;
        float4 v = *(const float4*)(qkv + g);
        Qt[ld4 + 0][row] = v.x; Qt[ld4 + 1][row] = v.y;
        Qt[ld4 + 2][row] = v.z; Qt[ld4 + 3][row] = v.w;
    }

    float acc[4][4] = {};
    float mprev[4] = {-1e30f, -1e30f, -1e30f, -1e30f};
    float lsum[4]  = {0.f, 0.f, 0.f, 0.f};

    for (int kt = 0; kt <= qb; kt++) {
        __syncthreads();   // previous AV done with KtP/Vs
        // Load K transposed + V direct
        #pragma unroll
        for (int it = 0; it < 4; it++) {
            int row = lr + it * 16;
            size_t g = (size_t)(b * T_SEQ + kt * 64 + row) * C3 + h * HDIM + ld4;
            float4 kv = *(const float4*)(qkv + g + C_EMB);
            KtP[ld4 + 0][row] = kv.x; KtP[ld4 + 1][row] = kv.y;
            KtP[ld4 + 2][row] = kv.z; KtP[ld4 + 3][row] = kv.w;
            float4 vv = *(const float4*)(qkv + g + 2 * C_EMB);
            *(float4*)&Vs[row][ld4] = vv;
        }
        __syncthreads();

        // S = Q K^T  (64x64, inner d=64)
        float s[4][4] = {};
        #pragma unroll 16
        for (int d = 0; d < 64; d++) {
            float4 q4 = *(const float4*)&Qt[d][ty * 4];
            float4 k4 = *(const float4*)&KtP[d][tx * 4];
            s[0][0] += q4.x * k4.x; s[0][1] += q4.x * k4.y; s[0][2] += q4.x * k4.z; s[0][3] += q4.x * k4.w;
            s[1][0] += q4.y * k4.x; s[1][1] += q4.y * k4.y; s[1][2] += q4.y * k4.z; s[1][3] += q4.y * k4.w;
            s[2][0] += q4.z * k4.x; s[2][1] += q4.z * k4.y; s[2][2] += q4.z * k4.z; s[2][3] += q4.z * k4.w;
            s[3][0] += q4.w * k4.x; s[3][1] += q4.w * k4.y; s[3][2] += q4.w * k4.z; s[3][3] += q4.w * k4.w;
        }

        // scale + causal mask
        #pragma unroll
        for (int i = 0; i < 4; i++) {
            int qq = qb * 64 + ty * 4 + i;
            #pragma unroll
            for (int j = 0; j < 4; j++) {
                int kk = kt * 64 + tx * 4 + j;
                s[i][j] = (kk <= qq) ? s[i][j] * 0.125f : -1e30f;
            }
        }
        __syncthreads();   // everyone done reading Kt

        // online softmax update (per row, reduced across 16 tx lanes)
        float p[4][4];
        #pragma unroll
        for (int i = 0; i < 4; i++) {
            float mt = fmaxf(fmaxf(s[i][0], s[i][1]), fmaxf(s[i][2], s[i][3]));
            mt = fmaxf(mt, __shfl_xor_sync(0xffffffffu, mt, 1));
            mt = fmaxf(mt, __shfl_xor_sync(0xffffffffu, mt, 2));
            mt = fmaxf(mt, __shfl_xor_sync(0xffffffffu, mt, 4));
            mt = fmaxf(mt, __shfl_xor_sync(0xffffffffu, mt, 8));
            float mnew = fmaxf(mprev[i], mt);
            float ls = 0.f;
            #pragma unroll
            for (int j = 0; j < 4; j++) {
                p[i][j] = __expf(s[i][j] - mnew);
                ls += p[i][j];
            }
            ls += __shfl_xor_sync(0xffffffffu, ls, 1);
            ls += __shfl_xor_sync(0xffffffffu, ls, 2);
            ls += __shfl_xor_sync(0xffffffffu, ls, 4);
            ls += __shfl_xor_sync(0xffffffffu, ls, 8);
            float cf = __expf(mprev[i] - mnew);
            lsum[i] = lsum[i] * cf + ls;
            mprev[i] = mnew;
            #pragma unroll
            for (int c = 0; c < 4; c++) acc[i][c] *= cf;
        }

        // write P into KtP buffer: P[row][key]
        #pragma unroll
        for (int i = 0; i < 4; i++)
            #pragma unroll
            for (int j = 0; j < 4; j++)
                KtP[ty * 4 + i][tx * 4 + j] = p[i][j];
        __syncthreads();

        // O += P @ V  (rows ty*4.., cols tx*4.., inner k=64)
        #pragma unroll 8
        for (int k = 0; k < 64; k++) {
            float4 v4 = *(const float4*)&Vs[k][tx * 4];
            #pragma unroll
            for (int i = 0; i < 4; i++) {
                float pv = KtP[ty * 4 + i][k];
                acc[i][0] += pv * v4.x;
                acc[i][1] += pv * v4.y;
                acc[i][2] += pv * v4.z;
                acc[i][3] += pv * v4.w;
            }
        }
    }

    // write output y[b*T + q, h*64 + col]
    #pragma unroll
    for (int i = 0; i < 4; i++) {
        float inv = 1.f / lsum[i];
        float4 o = make_float4(acc[i][0] * inv, acc[i][1] * inv,
                               acc[i][2] * inv, acc[i][3] * inv);
        size_t orow = (size_t)(b * T_SEQ + qb * 64 + ty * 4 + i);
        *(float4*)(y + orow * C_EMB + h * HDIM + tx * 4) = o;
    }
}

// ---------------- launch ----------------
extern "C" void kernel_launch(void* const* d_in, const int* in_sizes, int n_in,
                              void* d_out, int out_size)
{
    const float* x      = (const float*)d_in[0];
    const float* W_attn = (const float*)d_in[1];
    const float* b_attn = (const float*)d_in[2];
    const float* W_proj = (const float*)d_in[3];
    const float* b_proj = (const float*)d_in[4];
    float* out = (float*)d_out;

    float* qkv = nullptr;
    float* y   = nullptr;
    cudaGetSymbolAddress((void**)&qkv, g_qkv);
    cudaGetSymbolAddress((void**)&y, g_y);

    dim3 blk(256);

    // qkv = x @ W_attn + b_attn   [4096, 3072]
    gemm_bias_kernel<<<dim3(C3 / 128, BT / 128), blk>>>(
        x, W_attn, b_attn, qkv, BT, C3, C_EMB);

    // y = attention(qkv)          [4096, 1024]
    attn_kernel<<<dim3(T_SEQ / 64, NHEAD, BATCH), blk>>>(qkv, y);

    // out = y @ W_proj + b_proj   [4096, 1024]
    gemm_bias_kernel<<<dim3(C_EMB / 128, BT / 128), blk>>>(
        y, W_proj, b_proj, out, BT, C_EMB, C_EMB);
}

// round 3
// speedup vs baseline: 1.4640x; 1.4640x over previous
#include <cuda_runtime.h>
#include <cuda_bf16.h>
#include <cstdint>

#define BATCH   2
#define T_SEQ   2048
#define C_EMB   1024
#define NHEAD   16
#define HDIM    64
#define BT      (BATCH * T_SEQ)      // 4096
#define C3      (3 * C_EMB)          // 3072

// ---------------- scratch (device globals: allocation-free rule) ----------------
__device__ float g_qkv[(size_t)BT * C3];             // 48 MB
__device__ float g_y[(size_t)BT * C_EMB];            // 16 MB
__device__ __nv_bfloat16 g_ah[(size_t)BT * C_EMB];   // A hi
__device__ __nv_bfloat16 g_al[(size_t)BT * C_EMB];   // A lo
__device__ __nv_bfloat16 g_bh[(size_t)C3 * C_EMB];   // W^T hi
__device__ __nv_bfloat16 g_bl[(size_t)C3 * C_EMB];   // W^T lo

// ---------------- PTX helpers (all base-target sm_80+ instructions) ----------------
static __device__ __forceinline__ uint32_t smem_u32(const void* p) {
    uint32_t a;
    asm("{ .reg .u64 t; cvta.to.shared.u64 t, %1; cvt.u32.u64 %0, t; }" : "=r"(a) : "l"(p));
    return a;
}
static __device__ __forceinline__ void cp_async16(uint32_t dst, const void* src) {
    asm volatile("cp.async.cg.shared.global [%0], [%1], 16;" :: "r"(dst), "l"(src) : "memory");
}
static __device__ __forceinline__ void cp_commit() {
    asm volatile("cp.async.commit_group;" ::: "memory");
}
static __device__ __forceinline__ void cp_wait1() {
    asm volatile("cp.async.wait_group 1;" ::: "memory");
}
static __device__ __forceinline__ void ldsm_x4(uint32_t& r0, uint32_t& r1, uint32_t& r2,
                                               uint32_t& r3, uint32_t addr) {
    asm volatile("ldmatrix.sync.aligned.m8n8.x4.shared.b16 {%0,%1,%2,%3}, [%4];"
                 : "=r"(r0), "=r"(r1), "=r"(r2), "=r"(r3) : "r"(addr));
}
static __device__ __forceinline__ void mma_bf16(float* d, const uint32_t* a,
                                                uint32_t b0, uint32_t b1) {
    asm volatile(
        "mma.sync.aligned.m16n8k16.row.col.f32.bf16.bf16.f32 "
        "{%0,%1,%2,%3}, {%4,%5,%6,%7}, {%8,%9}, {%0,%1,%2,%3};"
        : "+f"(d[0]), "+f"(d[1]), "+f"(d[2]), "+f"(d[3])
        : "r"(a[0]), "r"(a[1]), "r"(a[2]), "r"(a[3]), "r"(b0), "r"(b1));
}
static __device__ __forceinline__ uint32_t sw128(uint32_t o) {
    return o ^ ((o >> 3) & 0x70);
}

// ---------------- HMMA GEMM: C = A @ B^T + bias ----------------
// A (hi/lo): [M,K] bf16 K-major; B (hi/lo): [N,K] bf16 K-major.
// CTA 128x128, BK=64, 8 warps (4Mx2N), warp tile 32x64, 2-stage cp.async pipeline.
// 3 MMA terms: AhBh + AhBl + AlBh (fp32 accum; dropped AlBl ~ 2^-16 relative).
#define GBM 128
#define GBN 128
#define GBK 64
#define STAGE_BYTES 65536           // 4 tiles x 16 KB (Ah, Al, Bh, Bl)
#define SM_TOTAL (2 * STAGE_BYTES)  // 128 KB

__global__ __launch_bounds__(256, 1)
void gemm_hmma(const __nv_bfloat16* __restrict__ Ah, const __nv_bfloat16* __restrict__ Al,
               const __nv_bfloat16* __restrict__ Bh, const __nv_bfloat16* __restrict__ Bl,
               const float* __restrict__ bias, float* __restrict__ C,
               int M, int N, int K)
{
    extern __shared__ char smem[];
    const uint32_t sbase = smem_u32(smem);
    const int t = threadIdx.x, lane = t & 31, w = t >> 5;
    const int wm = (w >> 1) * 32;       // warp M offset within CTA tile
    const int wn = (w & 1) * 64;        // warp N offset
    const int bm = blockIdx.y * GBM, bn = blockIdx.x * GBN;

    // loader mapping: each thread copies 16B at row lr (+32,+64,+96), byte col lc
    const int lr = t >> 3;
    const int lc = (t & 7) * 16;
    const size_t Kb = (size_t)K * 2;    // row stride in bytes
    const char* pAh = (const char*)Ah + (size_t)(bm + lr) * Kb + lc;
    const char* pAl = (const char*)Al + (size_t)(bm + lr) * Kb + lc;
    const char* pBh = (const char*)Bh + (size_t)(bn + lr) * Kb + lc;
    const char* pBl = (const char*)Bl + (size_t)(bn + lr) * Kb + lc;

    auto issue = [&](int c) {
        const uint32_t sb = sbase + (c & 1) * STAGE_BYTES;
        const size_t go = (size_t)c * 128;   // 64 bf16 = 128 bytes per chunk
        #pragma unroll
        for (int rr = 0; rr < 4; rr++) {
            uint32_t so = sw128((uint32_t)(lr + rr * 32) * 128 + lc);
            size_t gr = (size_t)rr * 32 * Kb + go;
            cp_async16(sb + so,         pAh + gr);
            cp_async16(sb + 16384 + so, pAl + gr);
            cp_async16(sb + 32768 + so, pBh + gr);
            cp_async16(sb + 49152 + so, pBl + gr);
        }
    };

    float acc[2][8][4] = {};
    const int nc = K / GBK;

    issue(0); cp_commit();
    issue(1); cp_commit();

    // fragment address components (lane-invariant parts precomputed)
    const int frow = lane & 15;          // ldmatrix row within 16-row tile
    const int fcol = (lane >> 4) * 16;   // 16B-chunk select

    for (int c = 0; c < nc; c++) {
        cp_wait1();
        __syncthreads();
        const uint32_t sb = sbase + (c & 1) * STAGE_BYTES;

        #pragma unroll
        for (int ks = 0; ks < GBK / 16; ks++) {
            const int kb = ks * 32 + fcol;
            uint32_t ah[2][4], al[2][4];
            #pragma unroll
            for (int mt = 0; mt < 2; mt++) {
                uint32_t o = sw128((uint32_t)(wm + mt * 16 + frow) * 128 + kb);
                ldsm_x4(ah[mt][0], ah[mt][1], ah[mt][2], ah[mt][3], sb + o);
                ldsm_x4(al[mt][0], al[mt][1], al[mt][2], al[mt][3], sb + 16384 + o);
            }
            uint32_t bh[4][4], bl[4][4];
            #pragma unroll
            for (int nt = 0; nt < 4; nt++) {
                uint32_t o = sw128((uint32_t)(wn + nt * 16 + frow) * 128 + kb);
                ldsm_x4(bh[nt][0], bh[nt][1], bh[nt][2], bh[nt][3], sb + 32768 + o);
                ldsm_x4(bl[nt][0], bl[nt][1], bl[nt][2], bl[nt][3], sb + 49152 + o);
            }
            #pragma unroll
            for (int mt = 0; mt < 2; mt++) {
                #pragma unroll
                for (int nt = 0; nt < 4; nt++) {
                    #pragma unroll
                    for (int hf = 0; hf < 2; hf++) {
                        float* d = acc[mt][nt * 2 + hf];
                        // n8 b-pair: k0-7 = reg hf, k8-15 = reg hf+2
                        mma_bf16(d, ah[mt], bh[nt][hf], bh[nt][hf + 2]);
                        mma_bf16(d, ah[mt], bl[nt][hf], bl[nt][hf + 2]);
                        mma_bf16(d, al[mt], bh[nt][hf], bh[nt][hf + 2]);
                    }
                }
            }
        }
        __syncthreads();
        if (c + 2 < nc) issue(c + 2);
        cp_commit();
    }

    // epilogue: register accumulators -> gmem with bias
    const int g = lane >> 2, tc = lane & 3;
    #pragma unroll
    for (int mt = 0; mt < 2; mt++) {
        const int row0 = bm + wm + mt * 16 + g;
        #pragma unroll
        for (int j = 0; j < 8; j++) {
            const int col = bn + wn + j * 8 + tc * 2;
            float b0 = bias[col], b1 = bias[col + 1];
            float* d = acc[mt][j];
            *(float2*)(C + (size_t)row0 * N + col) =
                make_float2(d[0] + b0, d[1] + b1);
            *(float2*)(C + (size_t)(row0 + 8) * N + col) =
                make_float2(d[2] + b0, d[3] + b1);
        }
    }
}

// ---------------- fp32 -> bf16 hi/lo split ----------------
__global__ void conv_hilo(const float* __restrict__ x, __nv_bfloat16* __restrict__ h,
                          __nv_bfloat16* __restrict__ l, int n)
{
    int i = (blockIdx.x * blockDim.x + threadIdx.x) * 4;
    if (i >= n) return;
    float4 v = *(const float4*)(x + i);
    __nv_bfloat16 h0 = __float2bfloat16(v.x), h1 = __float2bfloat16(v.y);
    __nv_bfloat16 h2 = __float2bfloat16(v.z), h3 = __float2bfloat16(v.w);
    __nv_bfloat16 l0 = __float2bfloat16(v.x - __bfloat162float(h0));
    __nv_bfloat16 l1 = __float2bfloat16(v.y - __bfloat162float(h1));
    __nv_bfloat16 l2 = __float2bfloat16(v.z - __bfloat162float(h2));
    __nv_bfloat16 l3 = __float2bfloat16(v.w - __bfloat162float(h3));
    *(__nv_bfloat162*)(h + i)     = __nv_bfloat162(h0, h1);
    *(__nv_bfloat162*)(h + i + 2) = __nv_bfloat162(h2, h3);
    *(__nv_bfloat162*)(l + i)     = __nv_bfloat162(l0, l1);
    *(__nv_bfloat162*)(l + i + 2) = __nv_bfloat162(l2, l3);
}

// ---------------- W [K,N] -> W^T [N,K] bf16 hi/lo ----------------
__global__ void conv_t_hilo(const float* __restrict__ W, __nv_bfloat16* __restrict__ th,
                            __nv_bfloat16* __restrict__ tl, int K, int N)
{
    __shared__ float tile[32][33];
    const int n0 = blockIdx.x * 32, k0 = blockIdx.y * 32;
    const int tx = threadIdx.x, ty = threadIdx.y;   // 32 x 8
    #pragma unroll
    for (int j = 0; j < 32; j += 8)
        tile[ty + j][tx] = W[(size_t)(k0 + ty + j) * N + n0 + tx];
    __syncthreads();
    #pragma unroll
    for (int j = 0; j < 32; j += 8) {
        float v = tile[tx][ty + j];
        __nv_bfloat16 h = __float2bfloat16(v);
        __nv_bfloat16 l = __float2bfloat16(v - __bfloat162float(h));
        size_t o = (size_t)(n0 + ty + j) * K + k0 + tx;
        th[o] = h;
        tl[o] = l;
    }
}

// ---------------- Flash attention (causal), fp32 (unchanged from R1) ----------------
__global__ __launch_bounds__(256)
void attn_kernel(const float* __restrict__ qkv, float* __restrict__ y)
{
    __shared__ float Qt[64][64];
    __shared__ float KtP[64][64];
    __shared__ float Vs[64][64];

    const int t  = threadIdx.x;
    const int tx = t & 15;
    const int ty = t >> 4;
    const int qb = blockIdx.x;
    const int h  = blockIdx.y;
    const int b  = blockIdx.z;

    const int lr  = t >> 4;
    const int ld4 = (t & 15) * 4;

    #pragma unroll
    for (int it = 0; it < 4; it++) {
        int row = lr + it * 16;
        size_t g = (size_t)(b * T_SEQ + qb * 64 + row) * C3 + h * HDIM + ld4;
        float4 v = *(const float4*)(qkv + g);
        Qt[ld4 + 0][row] = v.x; Qt[ld4 + 1][row] = v.y;
        Qt[ld4 + 2][row] = v.z; Qt[ld4 + 3][row] = v.w;
    }

    float acc[4][4] = {};
    float mprev[4] = {-1e30f, -1e30f, -1e30f, -1e30f};
    float lsum[4]  = {0.f, 0.f, 0.f, 0.f};

    for (int kt = 0; kt <= qb; kt++) {
        __syncthreads();
        #pragma unroll
        for (int it = 0; it < 4; it++) {
            int row = lr + it * 16;
            size_t g = (size_t)(b * T_SEQ + kt * 64 + row) * C3 + h * HDIM + ld4;
            float4 kv = *(const float4*)(qkv + g + C_EMB);
            KtP[ld4 + 0][row] = kv.x; KtP[ld4 + 1][row] = kv.y;
            KtP[ld4 + 2][row] = kv.z; KtP[ld4 + 3][row] = kv.w;
            float4 vv = *(const float4*)(qkv + g + 2 * C_EMB);
            *(float4*)&Vs[row][ld4] = vv;
        }
        __syncthreads();

        float s[4][4] = {};
        #pragma unroll 16
        for (int d = 0; d < 64; d++) {
            float4 q4 = *(const float4*)&Qt[d][ty * 4];
            float4 k4 = *(const float4*)&KtP[d][tx * 4];
            s[0][0] += q4.x * k4.x; s[0][1] += q4.x * k4.y; s[0][2] += q4.x * k4.z; s[0][3] += q4.x * k4.w;
            s[1][0] += q4.y * k4.x; s[1][1] += q4.y * k4.y; s[1][2] += q4.y * k4.z; s[1][3] += q4.y * k4.w;
            s[2][0] += q4.z * k4.x; s[2][1] += q4.z * k4.y; s[2][2] += q4.z * k4.z; s[2][3] += q4.z * k4.w;
            s[3][0] += q4.w * k4.x; s[3][1] += q4.w * k4.y; s[3][2] += q4.w * k4.z; s[3][3] += q4.w * k4.w;
        }

        #pragma unroll
        for (int i = 0; i < 4; i++) {
            int qq = qb * 64 + ty * 4 + i;
            #pragma unroll
            for (int j = 0; j < 4; j++) {
                int kk = kt * 64 + tx * 4 + j;
                s[i][j] = (kk <= qq) ? s[i][j] * 0.125f : -1e30f;
            }
        }
        __syncthreads();

        float p[4][4];
        #pragma unroll
        for (int i = 0; i < 4; i++) {
            float mt = fmaxf(fmaxf(s[i][0], s[i][1]), fmaxf(s[i][2], s[i][3]));
            mt = fmaxf(mt, __shfl_xor_sync(0xffffffffu, mt, 1));
            mt = fmaxf(mt, __shfl_xor_sync(0xffffffffu, mt, 2));
            mt = fmaxf(mt, __shfl_xor_sync(0xffffffffu, mt, 4));
            mt = fmaxf(mt, __shfl_xor_sync(0xffffffffu, mt, 8));
            float mnew = fmaxf(mprev[i], mt);
            float ls = 0.f;
            #pragma unroll
            for (int j = 0; j < 4; j++) {
                p[i][j] = __expf(s[i][j] - mnew);
                ls += p[i][j];
            }
            ls += __shfl_xor_sync(0xffffffffu, ls, 1);
            ls += __shfl_xor_sync(0xffffffffu, ls, 2);
            ls += __shfl_xor_sync(0xffffffffu, ls, 4);
            ls += __shfl_xor_sync(0xffffffffu, ls, 8);
            float cf = __expf(mprev[i] - mnew);
            lsum[i] = lsum[i] * cf + ls;
            mprev[i] = mnew;
            #pragma unroll
            for (int cjj = 0; cjj < 4; cjj++) acc[i][cjj] *= cf;
        }

        #pragma unroll
        for (int i = 0; i < 4; i++)
            #pragma unroll
            for (int j = 0; j < 4; j++)
                KtP[ty * 4 + i][tx * 4 + j] = p[i][j];
        __syncthreads();

        #pragma unroll 8
        for (int k = 0; k < 64; k++) {
            float4 v4 = *(const float4*)&Vs[k][tx * 4];
            #pragma unroll
            for (int i = 0; i < 4; i++) {
                float pv = KtP[ty * 4 + i][k];
                acc[i][0] += pv * v4.x;
                acc[i][1] += pv * v4.y;
                acc[i][2] += pv * v4.z;
                acc[i][3] += pv * v4.w;
            }
        }
    }

    #pragma unroll
    for (int i = 0; i < 4; i++) {
        float inv = 1.f / lsum[i];
        float4 o = make_float4(acc[i][0] * inv, acc[i][1] * inv,
                               acc[i][2] * inv, acc[i][3] * inv);
        size_t orow = (size_t)(b * T_SEQ + qb * 64 + ty * 4 + i);
        *(float4*)(y + orow * C_EMB + h * HDIM + tx * 4) = o;
    }
}

// ---------------- launch ----------------
extern "C" void kernel_launch(void* const* d_in, const int* in_sizes, int n_in,
                              void* d_out, int out_size)
{
    const float* x      = (const float*)d_in[0];
    const float* W_attn = (const float*)d_in[1];
    const float* b_attn = (const float*)d_in[2];
    const float* W_proj = (const float*)d_in[3];
    const float* b_proj = (const float*)d_in[4];
    float* out = (float*)d_out;

    float *qkv = nullptr, *y = nullptr;
    __nv_bfloat16 *ah = nullptr, *al = nullptr, *bh = nullptr, *bl = nullptr;
    cudaGetSymbolAddress((void**)&qkv, g_qkv);
    cudaGetSymbolAddress((void**)&y, g_y);
    cudaGetSymbolAddress((void**)&ah, g_ah);
    cudaGetSymbolAddress((void**)&al, g_al);
    cudaGetSymbolAddress((void**)&bh, g_bh);
    cudaGetSymbolAddress((void**)&bl, g_bl);

    cudaFuncSetAttribute(gemm_hmma, cudaFuncAttributeMaxDynamicSharedMemorySize, SM_TOTAL);

    const int nx = BT * C_EMB;

    // 1) split x -> bf16 hi/lo
    conv_hilo<<<nx / 4 / 256, 256>>>(x, ah, al, nx);
    // 2) W_attn [1024, 3072] -> W^T hi/lo [3072, 1024]
    conv_t_hilo<<<dim3(C3 / 32, C_EMB / 32), dim3(32, 8)>>>(W_attn, bh, bl, C_EMB, C3);
    // 3) qkv = x @ W_attn + b_attn  (HMMA)
    gemm_hmma<<<dim3(C3 / GBN, BT / GBM), 256, SM_TOTAL>>>(ah, al, bh, bl, b_attn, qkv, BT, C3, C_EMB);
    // 4) attention
    attn_kernel<<<dim3(T_SEQ / 64, NHEAD, BATCH), 256>>>(qkv, y);
    // 5) split y
    conv_hilo<<<nx / 4 / 256, 256>>>(y, ah, al, nx);
    // 6) W_proj [1024, 1024] -> W^T hi/lo
    conv_t_hilo<<<dim3(C_EMB / 32, C_EMB / 32), dim3(32, 8)>>>(W_proj, bh, bl, C_EMB, C_EMB);
    // 7) out = y @ W_proj + b_proj  (HMMA)
    gemm_hmma<<<dim3(C_EMB / GBN, BT / GBM), 256, SM_TOTAL>>>(ah, al, bh, bl, b_proj, out, BT, C_EMB, C_EMB);
}

// round 4
// speedup vs baseline: 2.8051x; 1.9160x over previous
#include <cuda_runtime.h>
#include <cuda_bf16.h>
#include <cstdint>

#define BATCH   2
#define T_SEQ   2048
#define C_EMB   1024
#define NHEAD   16
#define HDIM    64
#define BT      (BATCH * T_SEQ)      // 4096
#define C3      (3 * C_EMB)          // 3072

// ---------------- scratch (device globals: allocation-free rule) ----------------
__device__ __nv_bfloat16 g_qkvh[(size_t)BT * C3];    // qkv hi (25.2 MB)
__device__ __nv_bfloat16 g_qkvl[(size_t)BT * C3];    // qkv lo
__device__ __nv_bfloat16 g_vth[(size_t)BATCH * NHEAD * HDIM * T_SEQ];  // V^T hi
__device__ __nv_bfloat16 g_vtl[(size_t)BATCH * NHEAD * HDIM * T_SEQ];  // V^T lo
__device__ __nv_bfloat16 g_ah[(size_t)BT * C_EMB];   // activation hi (x, then y)
__device__ __nv_bfloat16 g_al[(size_t)BT * C_EMB];   // activation lo
__device__ __nv_bfloat16 g_bh[(size_t)C3 * C_EMB];   // W^T hi
__device__ __nv_bfloat16 g_bl[(size_t)C3 * C_EMB];   // W^T lo

// ---------------- PTX helpers (base-target sm_80+ instructions only) ----------------
static __device__ __forceinline__ uint32_t smem_u32(const void* p) {
    uint32_t a;
    asm("{ .reg .u64 t; cvta.to.shared.u64 t, %1; cvt.u32.u64 %0, t; }" : "=r"(a) : "l"(p));
    return a;
}
static __device__ __forceinline__ void cp_async16(uint32_t dst, const void* src) {
    asm volatile("cp.async.cg.shared.global [%0], [%1], 16;" :: "r"(dst), "l"(src) : "memory");
}
static __device__ __forceinline__ void cp_commit() {
    asm volatile("cp.async.commit_group;" ::: "memory");
}
static __device__ __forceinline__ void cp_wait1() {
    asm volatile("cp.async.wait_group 1;" ::: "memory");
}
static __device__ __forceinline__ void ldsm_x4(uint32_t& r0, uint32_t& r1, uint32_t& r2,
                                               uint32_t& r3, uint32_t addr) {
    asm volatile("ldmatrix.sync.aligned.m8n8.x4.shared.b16 {%0,%1,%2,%3}, [%4];"
                 : "=r"(r0), "=r"(r1), "=r"(r2), "=r"(r3) : "r"(addr));
}
static __device__ __forceinline__ void mma_bf16(float* d, const uint32_t* a,
                                                uint32_t b0, uint32_t b1) {
    asm volatile(
        "mma.sync.aligned.m16n8k16.row.col.f32.bf16.bf16.f32 "
        "{%0,%1,%2,%3}, {%4,%5,%6,%7}, {%8,%9}, {%0,%1,%2,%3};"
        : "+f"(d[0]), "+f"(d[1]), "+f"(d[2]), "+f"(d[3])
        : "r"(a[0]), "r"(a[1]), "r"(a[2]), "r"(a[3]), "r"(b0), "r"(b1));
}
static __device__ __forceinline__ uint32_t sw128(uint32_t o) {
    return o ^ ((o >> 3) & 0x70);
}
static __device__ __forceinline__ uint32_t bf2u(__nv_bfloat162 v) {
    return *reinterpret_cast<uint32_t*>(&v);
}

// ---------------- HMMA GEMM: C = A @ B^T + bias ----------------
// SPLIT=true: output written as bf16 hi/lo pair (Ch, Cl); else fp32 C.
#define GBM 128
#define GBN 128
#define GBK 64
#define STAGE_BYTES 65536
#define SM_TOTAL (2 * STAGE_BYTES)

template <bool SPLIT>
__global__ __launch_bounds__(256, 1)
void gemm_hmma(const __nv_bfloat16* __restrict__ Ah, const __nv_bfloat16* __restrict__ Al,
               const __nv_bfloat16* __restrict__ Bh, const __nv_bfloat16* __restrict__ Bl,
               const float* __restrict__ bias, float* __restrict__ C,
               __nv_bfloat16* __restrict__ Ch, __nv_bfloat16* __restrict__ Cl,
               int M, int N, int K)
{
    extern __shared__ char smem[];
    const uint32_t sbase = smem_u32(smem);
    const int t = threadIdx.x, lane = t & 31, w = t >> 5;
    const int wm = (w >> 1) * 32;
    const int wn = (w & 1) * 64;
    const int bm = blockIdx.y * GBM, bn = blockIdx.x * GBN;

    const int lr = t >> 3;
    const int lc = (t & 7) * 16;
    const size_t Kb = (size_t)K * 2;
    const char* pAh = (const char*)Ah + (size_t)(bm + lr) * Kb + lc;
    const char* pAl = (const char*)Al + (size_t)(bm + lr) * Kb + lc;
    const char* pBh = (const char*)Bh + (size_t)(bn + lr) * Kb + lc;
    const char* pBl = (const char*)Bl + (size_t)(bn + lr) * Kb + lc;

    auto issue = [&](int c) {
        const uint32_t sb = sbase + (c & 1) * STAGE_BYTES;
        const size_t go = (size_t)c * 128;
        #pragma unroll
        for (int rr = 0; rr < 4; rr++) {
            uint32_t so = sw128((uint32_t)(lr + rr * 32) * 128 + lc);
            size_t gr = (size_t)rr * 32 * Kb + go;
            cp_async16(sb + so,         pAh + gr);
            cp_async16(sb + 16384 + so, pAl + gr);
            cp_async16(sb + 32768 + so, pBh + gr);
            cp_async16(sb + 49152 + so, pBl + gr);
        }
    };

    float acc[2][8][4] = {};
    const int nc = K / GBK;

    issue(0); cp_commit();
    issue(1); cp_commit();

    const int frow = lane & 15;
    const int fcol = (lane >> 4) * 16;

    for (int c = 0; c < nc; c++) {
        cp_wait1();
        __syncthreads();
        const uint32_t sb = sbase + (c & 1) * STAGE_BYTES;

        #pragma unroll
        for (int ks = 0; ks < GBK / 16; ks++) {
            const int kb = ks * 32 + fcol;
            uint32_t ah[2][4], al[2][4];
            #pragma unroll
            for (int mt = 0; mt < 2; mt++) {
                uint32_t o = sw128((uint32_t)(wm + mt * 16 + frow) * 128 + kb);
                ldsm_x4(ah[mt][0], ah[mt][1], ah[mt][2], ah[mt][3], sb + o);
                ldsm_x4(al[mt][0], al[mt][1], al[mt][2], al[mt][3], sb + 16384 + o);
            }
            uint32_t bh[4][4], bl[4][4];
            #pragma unroll
            for (int nt = 0; nt < 4; nt++) {
                uint32_t o = sw128((uint32_t)(wn + nt * 16 + frow) * 128 + kb);
                ldsm_x4(bh[nt][0], bh[nt][1], bh[nt][2], bh[nt][3], sb + 32768 + o);
                ldsm_x4(bl[nt][0], bl[nt][1], bl[nt][2], bl[nt][3], sb + 49152 + o);
            }
            #pragma unroll
            for (int mt = 0; mt < 2; mt++) {
                #pragma unroll
                for (int nt = 0; nt < 4; nt++) {
                    #pragma unroll
                    for (int hf = 0; hf < 2; hf++) {
                        float* d = acc[mt][nt * 2 + hf];
                        mma_bf16(d, ah[mt], bh[nt][hf], bh[nt][hf + 2]);
                        mma_bf16(d, ah[mt], bl[nt][hf], bl[nt][hf + 2]);
                        mma_bf16(d, al[mt], bh[nt][hf], bh[nt][hf + 2]);
                    }
                }
            }
        }
        __syncthreads();
        if (c + 2 < nc) issue(c + 2);
        cp_commit();
    }

    const int g = lane >> 2, tc = lane & 3;
    #pragma unroll
    for (int mt = 0; mt < 2; mt++) {
        const int row0 = bm + wm + mt * 16 + g;
        #pragma unroll
        for (int j = 0; j < 8; j++) {
            const int col = bn + wn + j * 8 + tc * 2;
            float b0 = bias[col], b1 = bias[col + 1];
            float* d = acc[mt][j];
            float v00 = d[0] + b0, v01 = d[1] + b1;
            float v10 = d[2] + b0, v11 = d[3] + b1;
            if constexpr (SPLIT) {
                __nv_bfloat162 h0 = __floats2bfloat162_rn(v00, v01);
                __nv_bfloat162 l0 = __floats2bfloat162_rn(v00 - __low2float(h0),
                                                          v01 - __high2float(h0));
                __nv_bfloat162 h1 = __floats2bfloat162_rn(v10, v11);
                __nv_bfloat162 l1 = __floats2bfloat162_rn(v10 - __low2float(h1),
                                                          v11 - __high2float(h1));
                *(__nv_bfloat162*)(Ch + (size_t)row0 * N + col) = h0;
                *(__nv_bfloat162*)(Cl + (size_t)row0 * N + col) = l0;
                *(__nv_bfloat162*)(Ch + (size_t)(row0 + 8) * N + col) = h1;
                *(__nv_bfloat162*)(Cl + (size_t)(row0 + 8) * N + col) = l1;
            } else {
                *(float2*)(C + (size_t)row0 * N + col) = make_float2(v00, v01);
                *(float2*)(C + (size_t)(row0 + 8) * N + col) = make_float2(v10, v11);
            }
        }
    }
}

// ---------------- fp32 -> bf16 hi/lo split ----------------
__global__ void conv_hilo(const float* __restrict__ x, __nv_bfloat16* __restrict__ h,
                          __nv_bfloat16* __restrict__ l, int n)
{
    int i = (blockIdx.x * blockDim.x + threadIdx.x) * 4;
    if (i >= n) return;
    float4 v = *(const float4*)(x + i);
    __nv_bfloat16 h0 = __float2bfloat16(v.x), h1 = __float2bfloat16(v.y);
    __nv_bfloat16 h2 = __float2bfloat16(v.z), h3 = __float2bfloat16(v.w);
    __nv_bfloat16 l0 = __float2bfloat16(v.x - __bfloat162float(h0));
    __nv_bfloat16 l1 = __float2bfloat16(v.y - __bfloat162float(h1));
    __nv_bfloat16 l2 = __float2bfloat16(v.z - __bfloat162float(h2));
    __nv_bfloat16 l3 = __float2bfloat16(v.w - __bfloat162float(h3));
    *(__nv_bfloat162*)(h + i)     = __nv_bfloat162(h0, h1);
    *(__nv_bfloat162*)(h + i + 2) = __nv_bfloat162(h2, h3);
    *(__nv_bfloat162*)(l + i)     = __nv_bfloat162(l0, l1);
    *(__nv_bfloat162*)(l + i + 2) = __nv_bfloat162(l2, l3);
}

// ---------------- W [K,N] -> W^T [N,K] bf16 hi/lo ----------------
__global__ void conv_t_hilo(const float* __restrict__ W, __nv_bfloat16* __restrict__ th,
                            __nv_bfloat16* __restrict__ tl, int K, int N)
{
    __shared__ float tile[32][33];
    const int n0 = blockIdx.x * 32, k0 = blockIdx.y * 32;
    const int tx = threadIdx.x, ty = threadIdx.y;
    #pragma unroll
    for (int j = 0; j < 32; j += 8)
        tile[ty + j][tx] = W[(size_t)(k0 + ty + j) * N + n0 + tx];
    __syncthreads();
    #pragma unroll
    for (int j = 0; j < 32; j += 8) {
        float v = tile[tx][ty + j];
        __nv_bfloat16 h = __float2bfloat16(v);
        __nv_bfloat16 l = __float2bfloat16(v - __bfloat162float(h));
        size_t o = (size_t)(n0 + ty + j) * K + k0 + tx;
        th[o] = h;
        tl[o] = l;
    }
}

// ---------------- V part of qkv (bf16) -> V^T [b][h][d][T] ----------------
__global__ void vtrans(const __nv_bfloat16* __restrict__ qh, const __nv_bfloat16* __restrict__ ql,
                       __nv_bfloat16* __restrict__ vh, __nv_bfloat16* __restrict__ vl)
{
    __shared__ __nv_bfloat16 th[32][33], tl[32][33];
    const int bh = blockIdx.z, b = bh >> 4, h = bh & 15;
    const int t0 = blockIdx.x * 32, d0 = blockIdx.y * 32;
    const int tx = threadIdx.x, ty = threadIdx.y;
    #pragma unroll
    for (int j = 0; j < 32; j += 8) {
        size_t g = (size_t)(b * T_SEQ + t0 + ty + j) * C3 + 2 * C_EMB + h * HDIM + d0 + tx;
        th[ty + j][tx] = qh[g];
        tl[ty + j][tx] = ql[g];
    }
    __syncthreads();
    #pragma unroll
    for (int j = 0; j < 32; j += 8) {
        size_t o = ((size_t)(b * NHEAD + h) * HDIM + d0 + ty + j) * T_SEQ + t0 + tx;
        vh[o] = th[tx][ty + j];
        vl[o] = tl[tx][ty + j];
    }
}

// ---------------- HMMA flash attention (causal), hi/lo bf16 ----------------
// CTA: 128 q rows x one (b,h); 8 warps x 16 rows; 64-key tiles, 2-stage pipeline.
// Output y written directly as bf16 hi/lo.
#define A_SQH 0
#define A_SQL 16384
#define A_SK  32768            // stage base; per stage: Kh 8K, Kl 8K, Vth 8K, Vtl 8K
#define A_STG 32768
#define A_SMEM (A_SK + 2 * A_STG)   // 98304

__global__ __launch_bounds__(256, 1)
void attn_hmma(const __nv_bfloat16* __restrict__ qkvh, const __nv_bfloat16* __restrict__ qkvl,
               const __nv_bfloat16* __restrict__ vth, const __nv_bfloat16* __restrict__ vtl,
               __nv_bfloat16* __restrict__ yh, __nv_bfloat16* __restrict__ yl)
{
    extern __shared__ char smem[];
    const uint32_t sb = smem_u32(smem);
    const int t = threadIdx.x, lane = t & 31, w = t >> 5;
    const int qb = gridDim.x - 1 - blockIdx.x;   // heavy blocks first
    const int h = blockIdx.y, b = blockIdx.z;
    const int Q0 = qb * 128;
    const int nkt = (Q0 + 128) / 64;             // 2*qb + 2

    const int lr = t >> 3;          // 0..31
    const int lc = (t & 7) * 16;    // byte col within 128B row
    const char* qhb = (const char*)qkvh;
    const char* qlb = (const char*)qkvl;
    const char* vhb = (const char*)vth;
    const char* vlb = (const char*)vtl;

    auto issueQ = [&]() {
        #pragma unroll
        for (int rr = 0; rr < 4; rr++) {
            int row = lr + rr * 32;
            size_t g = ((size_t)(b * T_SEQ + Q0 + row) * C3 + h * HDIM) * 2 + lc;
            uint32_t so = sw128((uint32_t)row * 128 + lc);
            cp_async16(sb + A_SQH + so, qhb + g);
            cp_async16(sb + A_SQL + so, qlb + g);
        }
    };
    auto issueKV = [&](int kt, int st) {
        uint32_t s0 = sb + A_SK + st * A_STG;
        #pragma unroll
        for (int rr = 0; rr < 2; rr++) {
            int row = lr + rr * 32;
            uint32_t so = sw128((uint32_t)row * 128 + lc);
            size_t gk = ((size_t)(b * T_SEQ + kt * 64 + row) * C3 + C_EMB + h * HDIM) * 2 + lc;
            cp_async16(s0 + so,         qhb + gk);
            cp_async16(s0 + 8192 + so,  qlb + gk);
            size_t gv = (((size_t)(b * NHEAD + h) * HDIM + row) * T_SEQ + kt * 64) * 2 + lc;
            cp_async16(s0 + 16384 + so, vhb + gv);
            cp_async16(s0 + 24576 + so, vlb + gv);
        }
    };

    issueQ(); issueKV(0, 0); cp_commit();
    issueKV(1, 1); cp_commit();

    const int frow = lane & 15;
    const int fcol = (lane >> 4) * 16;
    const int g = lane >> 2, tc = lane & 3;

    cp_wait1();
    __syncthreads();

    // Q fragments, held in registers for all k-tiles
    uint32_t qfh[4][4], qfl[4][4];
    #pragma unroll
    for (int ks = 0; ks < 4; ks++) {
        uint32_t o = sw128((uint32_t)(w * 16 + frow) * 128 + ks * 32 + fcol);
        ldsm_x4(qfh[ks][0], qfh[ks][1], qfh[ks][2], qfh[ks][3], sb + A_SQH + o);
        ldsm_x4(qfl[ks][0], qfl[ks][1], qfl[ks][2], qfl[ks][3], sb + A_SQL + o);
    }

    float oacc[8][4] = {};
    float mprev0 = -1e30f, mprev1 = -1e30f;
    float lsum0 = 0.f, lsum1 = 0.f;
    const int r0 = Q0 + w * 16 + g;
    const int r1 = r0 + 8;

    for (int kt = 0; kt < nkt; kt++) {
        if (kt > 0) { cp_wait1(); __syncthreads(); }
        const uint32_t s0 = sb + A_SK + (kt & 1) * A_STG;

        // ---- S = Q K^T (3-term hi/lo) ----
        float s[8][4] = {};
        #pragma unroll
        for (int ks = 0; ks < 4; ks++) {
            #pragma unroll
            for (int ng = 0; ng < 4; ng++) {
                uint32_t o = sw128((uint32_t)(ng * 16 + frow) * 128 + ks * 32 + fcol);
                uint32_t kh[4], kl[4];
                ldsm_x4(kh[0], kh[1], kh[2], kh[3], s0 + o);
                ldsm_x4(kl[0], kl[1], kl[2], kl[3], s0 + 8192 + o);
                #pragma unroll
                for (int hf = 0; hf < 2; hf++) {
                    float* d = s[ng * 2 + hf];
                    mma_bf16(d, qfh[ks], kh[hf], kh[hf + 2]);
                    mma_bf16(d, qfh[ks], kl[hf], kl[hf + 2]);
                    mma_bf16(d, qfl[ks], kh[hf], kh[hf + 2]);
                }
            }
        }

        // ---- scale + causal mask ----
        if (kt * 64 + 63 > Q0 + w * 16) {
            #pragma unroll
            for (int i = 0; i < 8; i++) {
                int kk = kt * 64 + i * 8 + tc * 2;
                s[i][0] = (kk     <= r0) ? s[i][0] * 0.125f : -1e30f;
                s[i][1] = (kk + 1 <= r0) ? s[i][1] * 0.125f : -1e30f;
                s[i][2] = (kk     <= r1) ? s[i][2] * 0.125f : -1e30f;
                s[i][3] = (kk + 1 <= r1) ? s[i][3] * 0.125f : -1e30f;
            }
        } else {
            #pragma unroll
            for (int i = 0; i < 8; i++) {
                s[i][0] *= 0.125f; s[i][1] *= 0.125f;
                s[i][2] *= 0.125f; s[i][3] *= 0.125f;
            }
        }

        // ---- online softmax (rows r0, r1; quad reduction over tc) ----
        float mx0 = -1e30f, mx1 = -1e30f;
        #pragma unroll
        for (int i = 0; i < 8; i++) {
            mx0 = fmaxf(mx0, fmaxf(s[i][0], s[i][1]));
            mx1 = fmaxf(mx1, fmaxf(s[i][2], s[i][3]));
        }
        mx0 = fmaxf(mx0, __shfl_xor_sync(0xffffffffu, mx0, 1));
        mx0 = fmaxf(mx0, __shfl_xor_sync(0xffffffffu, mx0, 2));
        mx1 = fmaxf(mx1, __shfl_xor_sync(0xffffffffu, mx1, 1));
        mx1 = fmaxf(mx1, __shfl_xor_sync(0xffffffffu, mx1, 2));
        float mn0 = fmaxf(mprev0, mx0), mn1 = fmaxf(mprev1, mx1);
        float cf0 = __expf(mprev0 - mn0), cf1 = __expf(mprev1 - mn1);
        mprev0 = mn0; mprev1 = mn1;

        float ls0 = 0.f, ls1 = 0.f;
        #pragma unroll
        for (int i = 0; i < 8; i++) {
            s[i][0] = __expf(s[i][0] - mn0); ls0 += s[i][0];
            s[i][1] = __expf(s[i][1] - mn0); ls0 += s[i][1];
            s[i][2] = __expf(s[i][2] - mn1); ls1 += s[i][2];
            s[i][3] = __expf(s[i][3] - mn1); ls1 += s[i][3];
        }
        ls0 += __shfl_xor_sync(0xffffffffu, ls0, 1);
        ls0 += __shfl_xor_sync(0xffffffffu, ls0, 2);
        ls1 += __shfl_xor_sync(0xffffffffu, ls1, 1);
        ls1 += __shfl_xor_sync(0xffffffffu, ls1, 2);
        lsum0 = lsum0 * cf0 + ls0;
        lsum1 = lsum1 * cf1 + ls1;
        #pragma unroll
        for (int i = 0; i < 8; i++) {
            oacc[i][0] *= cf0; oacc[i][1] *= cf0;
            oacc[i][2] *= cf1; oacc[i][3] *= cf1;
        }

        // ---- O += P @ V (3-term, P split hi/lo in registers) ----
        #pragma unroll
        for (int ks = 0; ks < 4; ks++) {
            const float* sa = s[2 * ks];
            const float* sc = s[2 * ks + 1];
            __nv_bfloat162 h0 = __floats2bfloat162_rn(sa[0], sa[1]);
            __nv_bfloat162 h1 = __floats2bfloat162_rn(sa[2], sa[3]);
            __nv_bfloat162 h2 = __floats2bfloat162_rn(sc[0], sc[1]);
            __nv_bfloat162 h3 = __floats2bfloat162_rn(sc[2], sc[3]);
            uint32_t ph[4] = { bf2u(h0), bf2u(h1), bf2u(h2), bf2u(h3) };
            __nv_bfloat162 e0 = __floats2bfloat162_rn(sa[0] - __low2float(h0), sa[1] - __high2float(h0));
            __nv_bfloat162 e1 = __floats2bfloat162_rn(sa[2] - __low2float(h1), sa[3] - __high2float(h1));
            __nv_bfloat162 e2 = __floats2bfloat162_rn(sc[0] - __low2float(h2), sc[1] - __high2float(h2));
            __nv_bfloat162 e3 = __floats2bfloat162_rn(sc[2] - __low2float(h3), sc[3] - __high2float(h3));
            uint32_t pl[4] = { bf2u(e0), bf2u(e1), bf2u(e2), bf2u(e3) };

            #pragma unroll
            for (int ng = 0; ng < 4; ng++) {
                uint32_t o = sw128((uint32_t)(ng * 16 + frow) * 128 + ks * 32 + fcol);
                uint32_t vh4[4], vl4[4];
                ldsm_x4(vh4[0], vh4[1], vh4[2], vh4[3], s0 + 16384 + o);
                ldsm_x4(vl4[0], vl4[1], vl4[2], vl4[3], s0 + 24576 + o);
                #pragma unroll
                for (int hf = 0; hf < 2; hf++) {
                    float* d = oacc[ng * 2 + hf];
                    mma_bf16(d, ph, vh4[hf], vh4[hf + 2]);
                    mma_bf16(d, ph, vl4[hf], vl4[hf + 2]);
                    mma_bf16(d, pl, vh4[hf], vh4[hf + 2]);
                }
            }
        }

        __syncthreads();
        if (kt + 2 < nkt) issueKV(kt + 2, kt & 1);
        cp_commit();
    }

    // ---- epilogue: O / lsum -> y (bf16 hi/lo) ----
    float inv0 = 1.f / lsum0, inv1 = 1.f / lsum1;
    size_t row0 = (size_t)(b * T_SEQ + Q0 + w * 16 + g);
    #pragma unroll
    for (int i = 0; i < 8; i++) {
        int col = h * HDIM + i * 8 + tc * 2;
        float v0 = oacc[i][0] * inv0, v1 = oacc[i][1] * inv0;
        __nv_bfloat162 hv = __floats2bfloat162_rn(v0, v1);
        __nv_bfloat162 lv = __floats2bfloat162_rn(v0 - __low2float(hv), v1 - __high2float(hv));
        *(__nv_bfloat162*)(yh + row0 * C_EMB + col) = hv;
        *(__nv_bfloat162*)(yl + row0 * C_EMB + col) = lv;
        float v2 = oacc[i][2] * inv1, v3 = oacc[i][3] * inv1;
        hv = __floats2bfloat162_rn(v2, v3);
        lv = __floats2bfloat162_rn(v2 - __low2float(hv), v3 - __high2float(hv));
        *(__nv_bfloat162*)(yh + (row0 + 8) * C_EMB + col) = hv;
        *(__nv_bfloat162*)(yl + (row0 + 8) * C_EMB + col) = lv;
    }
}

// ---------------- launch ----------------
extern "C" void kernel_launch(void* const* d_in, const int* in_sizes, int n_in,
                              void* d_out, int out_size)
{
    const float* x      = (const float*)d_in[0];
    const float* W_attn = (const float*)d_in[1];
    const float* b_attn = (const float*)d_in[2];
    const float* W_proj = (const float*)d_in[3];
    const float* b_proj = (const float*)d_in[4];
    float* out = (float*)d_out;

    __nv_bfloat16 *qkvh, *qkvl, *vth, *vtl, *ah, *al, *bh, *bl;
    cudaGetSymbolAddress((void**)&qkvh, g_qkvh);
    cudaGetSymbolAddress((void**)&qkvl, g_qkvl);
    cudaGetSymbolAddress((void**)&vth, g_vth);
    cudaGetSymbolAddress((void**)&vtl, g_vtl);
    cudaGetSymbolAddress((void**)&ah, g_ah);
    cudaGetSymbolAddress((void**)&al, g_al);
    cudaGetSymbolAddress((void**)&bh, g_bh);
    cudaGetSymbolAddress((void**)&bl, g_bl);

    cudaFuncSetAttribute(gemm_hmma<true>,  cudaFuncAttributeMaxDynamicSharedMemorySize, SM_TOTAL);
    cudaFuncSetAttribute(gemm_hmma<false>, cudaFuncAttributeMaxDynamicSharedMemorySize, SM_TOTAL);
    cudaFuncSetAttribute(attn_hmma, cudaFuncAttributeMaxDynamicSharedMemorySize, A_SMEM);

    const int nx = BT * C_EMB;

    // 1) x -> bf16 hi/lo
    conv_hilo<<<nx / 4 / 256, 256>>>(x, ah, al, nx);
    // 2) W_attn -> W^T hi/lo
    conv_t_hilo<<<dim3(C3 / 32, C_EMB / 32), dim3(32, 8)>>>(W_attn, bh, bl, C_EMB, C3);
    // 3) qkv = x @ W_attn + b_attn  (HMMA, split bf16 output)
    gemm_hmma<true><<<dim3(C3 / GBN, BT / GBM), 256, SM_TOTAL>>>(
        ah, al, bh, bl, b_attn, nullptr, qkvh, qkvl, BT, C3, C_EMB);
    // 4) V -> V^T
    vtrans<<<dim3(T_SEQ / 32, HDIM / 32, BATCH * NHEAD), dim3(32, 8)>>>(qkvh, qkvl, vth, vtl);
    // 5) attention (HMMA flash), writes y as bf16 hi/lo
    attn_hmma<<<dim3(T_SEQ / 128, NHEAD, BATCH), 256, A_SMEM>>>(qkvh, qkvl, vth, vtl, ah, al);
    // 6) W_proj -> W^T hi/lo
    conv_t_hilo<<<dim3(C_EMB / 32, C_EMB / 32), dim3(32, 8)>>>(W_proj, bh, bl, C_EMB, C_EMB);
    // 7) out = y @ W_proj + b_proj  (HMMA, fp32 output)
    gemm_hmma<false><<<dim3(C_EMB / GBN, BT / GBM), 256, SM_TOTAL>>>(
        ah, al, bh, bl, b_proj, out, nullptr, nullptr, BT, C_EMB, C_EMB);
}

// round 5
// speedup vs baseline: 2.8829x; 1.0277x over previous
#include <cuda_runtime.h>
#include <cuda_bf16.h>
#include <cstdint>

#define BATCH   2
#define T_SEQ   2048
#define C_EMB   1024
#define NHEAD   16
#define HDIM    64
#define BT      (BATCH * T_SEQ)      // 4096
#define C3      (3 * C_EMB)          // 3072

// ---------------- scratch (device globals: allocation-free rule) ----------------
__device__ __nv_bfloat16 g_qkvh[(size_t)BT * C3];
__device__ __nv_bfloat16 g_qkvl[(size_t)BT * C3];
__device__ __nv_bfloat16 g_vth[(size_t)BATCH * NHEAD * HDIM * T_SEQ];
__device__ __nv_bfloat16 g_vtl[(size_t)BATCH * NHEAD * HDIM * T_SEQ];
__device__ __nv_bfloat16 g_ah[(size_t)BT * C_EMB];
__device__ __nv_bfloat16 g_al[(size_t)BT * C_EMB];
__device__ __nv_bfloat16 g_bh[(size_t)C3 * C_EMB];
__device__ __nv_bfloat16 g_bl[(size_t)C3 * C_EMB];

// ---------------- PTX helpers (base-target sm_80+ only) ----------------
static __device__ __forceinline__ uint32_t smem_u32(const void* p) {
    uint32_t a;
    asm("{ .reg .u64 t; cvta.to.shared.u64 t, %1; cvt.u32.u64 %0, t; }" : "=r"(a) : "l"(p));
    return a;
}
static __device__ __forceinline__ void cp_async16(uint32_t dst, const void* src) {
    asm volatile("cp.async.cg.shared.global [%0], [%1], 16;" :: "r"(dst), "l"(src) : "memory");
}
static __device__ __forceinline__ void cp_commit() {
    asm volatile("cp.async.commit_group;" ::: "memory");
}
static __device__ __forceinline__ void cp_wait1() {
    asm volatile("cp.async.wait_group 1;" ::: "memory");
}
static __device__ __forceinline__ void ldsm_x4(uint32_t& r0, uint32_t& r1, uint32_t& r2,
                                               uint32_t& r3, uint32_t addr) {
    asm volatile("ldmatrix.sync.aligned.m8n8.x4.shared.b16 {%0,%1,%2,%3}, [%4];"
                 : "=r"(r0), "=r"(r1), "=r"(r2), "=r"(r3) : "r"(addr));
}
static __device__ __forceinline__ void mma_bf16(float* d, const uint32_t* a,
                                                uint32_t b0, uint32_t b1) {
    asm volatile(
        "mma.sync.aligned.m16n8k16.row.col.f32.bf16.bf16.f32 "
        "{%0,%1,%2,%3}, {%4,%5,%6,%7}, {%8,%9}, {%0,%1,%2,%3};"
        : "+f"(d[0]), "+f"(d[1]), "+f"(d[2]), "+f"(d[3])
        : "r"(a[0]), "r"(a[1]), "r"(a[2]), "r"(a[3]), "r"(b0), "r"(b1));
}
static __device__ __forceinline__ uint32_t sw128(uint32_t o) {
    return o ^ ((o >> 3) & 0x70);
}
static __device__ __forceinline__ uint32_t bf2u(__nv_bfloat162 v) {
    return *reinterpret_cast<uint32_t*>(&v);
}

// ---------------- HMMA GEMM: C = A @ B^T + bias ----------------
// CTA 128x256, warps 2Mx4N (warp tile 64x64), BK=64, 2-stage cp.async.
// Stage layout: Ah 16K | Al 16K | Bh 32K | Bl 32K  = 96 KB
#define GBM 128
#define GBN 256
#define GBK 64
#define STAGE_BYTES 98304
#define SM_TOTAL (2 * STAGE_BYTES)   // 192 KB

template <bool SPLIT>
__global__ __launch_bounds__(256, 1)
void gemm_hmma(const __nv_bfloat16* __restrict__ Ah, const __nv_bfloat16* __restrict__ Al,
               const __nv_bfloat16* __restrict__ Bh, const __nv_bfloat16* __restrict__ Bl,
               const float* __restrict__ bias, float* __restrict__ C,
               __nv_bfloat16* __restrict__ Ch, __nv_bfloat16* __restrict__ Cl,
               int M, int N, int K)
{
    extern __shared__ char smem[];
    const uint32_t sbase = smem_u32(smem);
    const int t = threadIdx.x, lane = t & 31, w = t >> 5;
    const int wm = (w >> 2) * 64;       // 0 or 64
    const int wn = (w & 3) * 64;        // 0,64,128,192
    const int bm = blockIdx.y * GBM, bn = blockIdx.x * GBN;

    const int lr = t >> 3;              // 0..31
    const int lc = (t & 7) * 16;
    const size_t Kb = (size_t)K * 2;
    const char* pAh = (const char*)Ah + (size_t)(bm + lr) * Kb + lc;
    const char* pAl = (const char*)Al + (size_t)(bm + lr) * Kb + lc;
    const char* pBh = (const char*)Bh + (size_t)(bn + lr) * Kb + lc;
    const char* pBl = (const char*)Bl + (size_t)(bn + lr) * Kb + lc;

    auto issue = [&](int c) {
        const uint32_t sb = sbase + (c & 1) * STAGE_BYTES;
        const size_t go = (size_t)c * 128;
        #pragma unroll
        for (int rr = 0; rr < 4; rr++) {
            uint32_t so = sw128((uint32_t)(lr + rr * 32) * 128 + lc);
            size_t gr = (size_t)rr * 32 * Kb + go;
            cp_async16(sb + so,         pAh + gr);
            cp_async16(sb + 16384 + so, pAl + gr);
        }
        #pragma unroll
        for (int rr = 0; rr < 8; rr++) {
            uint32_t so = sw128((uint32_t)(lr + rr * 32) * 128 + lc);
            size_t gr = (size_t)rr * 32 * Kb + go;
            cp_async16(sb + 32768 + so, pBh + gr);
            cp_async16(sb + 65536 + so, pBl + gr);
        }
    };

    float acc[4][8][4] = {};
    const int nc = K / GBK;

    issue(0); cp_commit();
    issue(1); cp_commit();

    const int frow = lane & 15;
    const int fcol = (lane >> 4) * 16;

    for (int c = 0; c < nc; c++) {
        cp_wait1();
        __syncthreads();
        const uint32_t sb = sbase + (c & 1) * STAGE_BYTES;

        #pragma unroll
        for (int ks = 0; ks < GBK / 16; ks++) {
            const int kb = ks * 32 + fcol;
            uint32_t ah[4][4], al[4][4];
            #pragma unroll
            for (int mt = 0; mt < 4; mt++) {
                uint32_t o = sw128((uint32_t)(wm + mt * 16 + frow) * 128 + kb);
                ldsm_x4(ah[mt][0], ah[mt][1], ah[mt][2], ah[mt][3], sb + o);
                ldsm_x4(al[mt][0], al[mt][1], al[mt][2], al[mt][3], sb + 16384 + o);
            }
            #pragma unroll
            for (int nt = 0; nt < 4; nt++) {
                uint32_t o = sw128((uint32_t)(wn + nt * 16 + frow) * 128 + kb);
                uint32_t bh4[4], bl4[4];
                ldsm_x4(bh4[0], bh4[1], bh4[2], bh4[3], sb + 32768 + o);
                ldsm_x4(bl4[0], bl4[1], bl4[2], bl4[3], sb + 65536 + o);
                #pragma unroll
                for (int mt = 0; mt < 4; mt++) {
                    #pragma unroll
                    for (int hf = 0; hf < 2; hf++) {
                        float* d = acc[mt][nt * 2 + hf];
                        mma_bf16(d, ah[mt], bh4[hf], bh4[hf + 2]);
                        mma_bf16(d, ah[mt], bl4[hf], bl4[hf + 2]);
                        mma_bf16(d, al[mt], bh4[hf], bh4[hf + 2]);
                    }
                }
            }
        }
        __syncthreads();
        if (c + 2 < nc) issue(c + 2);
        cp_commit();
    }

    const int g = lane >> 2, tc = lane & 3;
    #pragma unroll
    for (int mt = 0; mt < 4; mt++) {
        const int row0 = bm + wm + mt * 16 + g;
        #pragma unroll
        for (int j = 0; j < 8; j++) {
            const int col = bn + wn + j * 8 + tc * 2;
            float b0 = bias[col], b1 = bias[col + 1];
            float* d = acc[mt][j];
            float v00 = d[0] + b0, v01 = d[1] + b1;
            float v10 = d[2] + b0, v11 = d[3] + b1;
            if constexpr (SPLIT) {
                __nv_bfloat162 h0 = __floats2bfloat162_rn(v00, v01);
                __nv_bfloat162 l0 = __floats2bfloat162_rn(v00 - __low2float(h0),
                                                          v01 - __high2float(h0));
                __nv_bfloat162 h1 = __floats2bfloat162_rn(v10, v11);
                __nv_bfloat162 l1 = __floats2bfloat162_rn(v10 - __low2float(h1),
                                                          v11 - __high2float(h1));
                *(__nv_bfloat162*)(Ch + (size_t)row0 * N + col) = h0;
                *(__nv_bfloat162*)(Cl + (size_t)row0 * N + col) = l0;
                *(__nv_bfloat162*)(Ch + (size_t)(row0 + 8) * N + col) = h1;
                *(__nv_bfloat162*)(Cl + (size_t)(row0 + 8) * N + col) = l1;
            } else {
                *(float2*)(C + (size_t)row0 * N + col) = make_float2(v00, v01);
                *(float2*)(C + (size_t)(row0 + 8) * N + col) = make_float2(v10, v11);
            }
        }
    }
}

// ---------------- fp32 -> bf16 hi/lo split ----------------
__global__ void conv_hilo(const float* __restrict__ x, __nv_bfloat16* __restrict__ h,
                          __nv_bfloat16* __restrict__ l, int n)
{
    int i = (blockIdx.x * blockDim.x + threadIdx.x) * 4;
    if (i >= n) return;
    float4 v = *(const float4*)(x + i);
    __nv_bfloat16 h0 = __float2bfloat16(v.x), h1 = __float2bfloat16(v.y);
    __nv_bfloat16 h2 = __float2bfloat16(v.z), h3 = __float2bfloat16(v.w);
    __nv_bfloat16 l0 = __float2bfloat16(v.x - __bfloat162float(h0));
    __nv_bfloat16 l1 = __float2bfloat16(v.y - __bfloat162float(h1));
    __nv_bfloat16 l2 = __float2bfloat16(v.z - __bfloat162float(h2));
    __nv_bfloat16 l3 = __float2bfloat16(v.w - __bfloat162float(h3));
    *(__nv_bfloat162*)(h + i)     = __nv_bfloat162(h0, h1);
    *(__nv_bfloat162*)(h + i + 2) = __nv_bfloat162(h2, h3);
    *(__nv_bfloat162*)(l + i)     = __nv_bfloat162(l0, l1);
    *(__nv_bfloat162*)(l + i + 2) = __nv_bfloat162(l2, l3);
}

// ---------------- W [K,N] -> W^T [N,K] bf16 hi/lo ----------------
__global__ void conv_t_hilo(const float* __restrict__ W, __nv_bfloat16* __restrict__ th,
                            __nv_bfloat16* __restrict__ tl, int K, int N)
{
    __shared__ float tile[32][33];
    const int n0 = blockIdx.x * 32, k0 = blockIdx.y * 32;
    const int tx = threadIdx.x, ty = threadIdx.y;
    #pragma unroll
    for (int j = 0; j < 32; j += 8)
        tile[ty + j][tx] = W[(size_t)(k0 + ty + j) * N + n0 + tx];
    __syncthreads();
    #pragma unroll
    for (int j = 0; j < 32; j += 8) {
        float v = tile[tx][ty + j];
        __nv_bfloat16 h = __float2bfloat16(v);
        __nv_bfloat16 l = __float2bfloat16(v - __bfloat162float(h));
        size_t o = (size_t)(n0 + ty + j) * K + k0 + tx;
        th[o] = h;
        tl[o] = l;
    }
}

// ---------------- V part of qkv (bf16) -> V^T [b][h][d][T] ----------------
__global__ void vtrans(const __nv_bfloat16* __restrict__ qh, const __nv_bfloat16* __restrict__ ql,
                       __nv_bfloat16* __restrict__ vh, __nv_bfloat16* __restrict__ vl)
{
    __shared__ __nv_bfloat16 th[32][33], tl[32][33];
    const int bh = blockIdx.z, b = bh >> 4, h = bh & 15;
    const int t0 = blockIdx.x * 32, d0 = blockIdx.y * 32;
    const int tx = threadIdx.x, ty = threadIdx.y;
    #pragma unroll
    for (int j = 0; j < 32; j += 8) {
        size_t g = (size_t)(b * T_SEQ + t0 + ty + j) * C3 + 2 * C_EMB + h * HDIM + d0 + tx;
        th[ty + j][tx] = qh[g];
        tl[ty + j][tx] = ql[g];
    }
    __syncthreads();
    #pragma unroll
    for (int j = 0; j < 32; j += 8) {
        size_t o = ((size_t)(b * NHEAD + h) * HDIM + d0 + ty + j) * T_SEQ + t0 + tx;
        vh[o] = th[tx][ty + j];
        vl[o] = tl[tx][ty + j];
    }
}

// ---------------- HMMA flash attention (causal), hi/lo bf16 ----------------
// CTA: 128 q rows x (b,h); 8 warps x 16 rows; 128-key tiles, 2-stage pipeline.
// Stage: Kh 16K | Kl 16K | Vh 2x8K | Vl 2x8K = 64 KB. Q: 32 KB. Total 160 KB.
#define A_SQH 0
#define A_SQL 16384
#define A_SK  32768
#define A_STG 65536
#define A_SMEM (A_SK + 2 * A_STG)   // 163840

__global__ __launch_bounds__(256, 1)
void attn_hmma(const __nv_bfloat16* __restrict__ qkvh, const __nv_bfloat16* __restrict__ qkvl,
               const __nv_bfloat16* __restrict__ vth, const __nv_bfloat16* __restrict__ vtl,
               __nv_bfloat16* __restrict__ yh, __nv_bfloat16* __restrict__ yl)
{
    extern __shared__ char smem[];
    const uint32_t sb = smem_u32(smem);
    const int t = threadIdx.x, lane = t & 31, w = t >> 5;
    const int qb = gridDim.x - 1 - blockIdx.x;   // heavy blocks first
    const int h = blockIdx.y, b = blockIdx.z;
    const int Q0 = qb * 128;
    const int nkt = qb + 1;                      // 128-key tiles

    const int lr = t >> 3;
    const int lc = (t & 7) * 16;
    const char* qhb = (const char*)qkvh;
    const char* qlb = (const char*)qkvl;
    const char* vhb = (const char*)vth;
    const char* vlb = (const char*)vtl;

    auto issueQ = [&]() {
        #pragma unroll
        for (int rr = 0; rr < 4; rr++) {
            int row = lr + rr * 32;
            size_t g = ((size_t)(b * T_SEQ + Q0 + row) * C3 + h * HDIM) * 2 + lc;
            uint32_t so = sw128((uint32_t)row * 128 + lc);
            cp_async16(sb + A_SQH + so, qhb + g);
            cp_async16(sb + A_SQL + so, qlb + g);
        }
    };
    auto issueKV = [&](int kt, int st) {
        uint32_t s0 = sb + A_SK + st * A_STG;
        // K: 128 key-rows x 128B (hi/lo)
        #pragma unroll
        for (int rr = 0; rr < 4; rr++) {
            int row = lr + rr * 32;
            uint32_t so = sw128((uint32_t)row * 128 + lc);
            size_t gk = ((size_t)(b * T_SEQ + kt * 128 + row) * C3 + C_EMB + h * HDIM) * 2 + lc;
            cp_async16(s0 + so,         qhb + gk);
            cp_async16(s0 + 16384 + so, qlb + gk);
        }
        // V^T: two 64-key subtiles, each 64 d-rows x 128B
        #pragma unroll
        for (int j = 0; j < 2; j++) {
            #pragma unroll
            for (int rr = 0; rr < 2; rr++) {
                int row = lr + rr * 32;
                uint32_t so = sw128((uint32_t)row * 128 + lc) + j * 8192;
                size_t gv = (((size_t)(b * NHEAD + h) * HDIM + row) * T_SEQ
                             + kt * 128 + j * 64) * 2 + lc;
                cp_async16(s0 + 32768 + so, vhb + gv);
                cp_async16(s0 + 49152 + so, vlb + gv);
            }
        }
    };

    issueQ(); issueKV(0, 0); cp_commit();
    if (nkt > 1) issueKV(1, 1);
    cp_commit();

    const int frow = lane & 15;
    const int fcol = (lane >> 4) * 16;
    const int g = lane >> 2, tc = lane & 3;

    cp_wait1();
    __syncthreads();

    uint32_t qfh[4][4], qfl[4][4];
    #pragma unroll
    for (int ks = 0; ks < 4; ks++) {
        uint32_t o = sw128((uint32_t)(w * 16 + frow) * 128 + ks * 32 + fcol);
        ldsm_x4(qfh[ks][0], qfh[ks][1], qfh[ks][2], qfh[ks][3], sb + A_SQH + o);
        ldsm_x4(qfl[ks][0], qfl[ks][1], qfl[ks][2], qfl[ks][3], sb + A_SQL + o);
    }

    float oacc[8][4] = {};
    float mprev0 = -1e30f, mprev1 = -1e30f;
    float lsum0 = 0.f, lsum1 = 0.f;
    const int r0 = Q0 + w * 16 + g;
    const int r1 = r0 + 8;

    for (int kt = 0; kt < nkt; kt++) {
        if (kt > 0) { cp_wait1(); __syncthreads(); }
        const uint32_t s0 = sb + A_SK + (kt & 1) * A_STG;

        // ---- S = Q K^T over 128 keys (3-term hi/lo) ----
        float s[16][4] = {};
        #pragma unroll
        for (int ks = 0; ks < 4; ks++) {
            #pragma unroll
            for (int ng = 0; ng < 8; ng++) {
                uint32_t o = sw128((uint32_t)(ng * 16 + frow) * 128 + ks * 32 + fcol);
                uint32_t kh[4], kl[4];
                ldsm_x4(kh[0], kh[1], kh[2], kh[3], s0 + o);
                ldsm_x4(kl[0], kl[1], kl[2], kl[3], s0 + 16384 + o);
                #pragma unroll
                for (int hf = 0; hf < 2; hf++) {
                    float* d = s[ng * 2 + hf];
                    mma_bf16(d, qfh[ks], kh[hf], kh[hf + 2]);
                    mma_bf16(d, qfh[ks], kl[hf], kl[hf + 2]);
                    mma_bf16(d, qfl[ks], kh[hf], kh[hf + 2]);
                }
            }
        }

        // ---- scale + causal mask ----
        if (kt == nkt - 1) {   // diagonal tile
            #pragma unroll
            for (int i = 0; i < 16; i++) {
                int kk = kt * 128 + i * 8 + tc * 2;
                s[i][0] = (kk     <= r0) ? s[i][0] * 0.125f : -1e30f;
                s[i][1] = (kk + 1 <= r0) ? s[i][1] * 0.125f : -1e30f;
                s[i][2] = (kk     <= r1) ? s[i][2] * 0.125f : -1e30f;
                s[i][3] = (kk + 1 <= r1) ? s[i][3] * 0.125f : -1e30f;
            }
        } else {
            #pragma unroll
            for (int i = 0; i < 16; i++) {
                s[i][0] *= 0.125f; s[i][1] *= 0.125f;
                s[i][2] *= 0.125f; s[i][3] *= 0.125f;
            }
        }

        // ---- online softmax (rows r0, r1) ----
        float mx0 = -1e30f, mx1 = -1e30f;
        #pragma unroll
        for (int i = 0; i < 16; i++) {
            mx0 = fmaxf(mx0, fmaxf(s[i][0], s[i][1]));
            mx1 = fmaxf(mx1, fmaxf(s[i][2], s[i][3]));
        }
        mx0 = fmaxf(mx0, __shfl_xor_sync(0xffffffffu, mx0, 1));
        mx0 = fmaxf(mx0, __shfl_xor_sync(0xffffffffu, mx0, 2));
        mx1 = fmaxf(mx1, __shfl_xor_sync(0xffffffffu, mx1, 1));
        mx1 = fmaxf(mx1, __shfl_xor_sync(0xffffffffu, mx1, 2));
        float mn0 = fmaxf(mprev0, mx0), mn1 = fmaxf(mprev1, mx1);
        float cf0 = __expf(mprev0 - mn0), cf1 = __expf(mprev1 - mn1);
        mprev0 = mn0; mprev1 = mn1;

        float ls0 = 0.f, ls1 = 0.f;
        #pragma unroll
        for (int i = 0; i < 16; i++) {
            s[i][0] = __expf(s[i][0] - mn0); ls0 += s[i][0];
            s[i][1] = __expf(s[i][1] - mn0); ls0 += s[i][1];
            s[i][2] = __expf(s[i][2] - mn1); ls1 += s[i][2];
            s[i][3] = __expf(s[i][3] - mn1); ls1 += s[i][3];
        }
        ls0 += __shfl_xor_sync(0xffffffffu, ls0, 1);
        ls0 += __shfl_xor_sync(0xffffffffu, ls0, 2);
        ls1 += __shfl_xor_sync(0xffffffffu, ls1, 1);
        ls1 += __shfl_xor_sync(0xffffffffu, ls1, 2);
        lsum0 = lsum0 * cf0 + ls0;
        lsum1 = lsum1 * cf1 + ls1;
        #pragma unroll
        for (int i = 0; i < 8; i++) {
            oacc[i][0] *= cf0; oacc[i][1] *= cf0;
            oacc[i][2] *= cf1; oacc[i][3] *= cf1;
        }

        // ---- O += P @ V (3-term, P split hi/lo in registers) ----
        #pragma unroll
        for (int h2 = 0; h2 < 2; h2++) {
            #pragma unroll
            for (int ks = 0; ks < 4; ks++) {
                const float* sa = s[h2 * 8 + 2 * ks];
                const float* sc = s[h2 * 8 + 2 * ks + 1];
                __nv_bfloat162 h0 = __floats2bfloat162_rn(sa[0], sa[1]);
                __nv_bfloat162 h1 = __floats2bfloat162_rn(sa[2], sa[3]);
                __nv_bfloat162 h2v = __floats2bfloat162_rn(sc[0], sc[1]);
                __nv_bfloat162 h3 = __floats2bfloat162_rn(sc[2], sc[3]);
                uint32_t ph[4] = { bf2u(h0), bf2u(h1), bf2u(h2v), bf2u(h3) };
                __nv_bfloat162 e0 = __floats2bfloat162_rn(sa[0] - __low2float(h0), sa[1] - __high2float(h0));
                __nv_bfloat162 e1 = __floats2bfloat162_rn(sa[2] - __low2float(h1), sa[3] - __high2float(h1));
                __nv_bfloat162 e2 = __floats2bfloat162_rn(sc[0] - __low2float(h2v), sc[1] - __high2float(h2v));
                __nv_bfloat162 e3 = __floats2bfloat162_rn(sc[2] - __low2float(h3), sc[3] - __high2float(h3));
                uint32_t pl[4] = { bf2u(e0), bf2u(e1), bf2u(e2), bf2u(e3) };

                #pragma unroll
                for (int ng = 0; ng < 4; ng++) {
                    uint32_t o = sw128((uint32_t)(ng * 16 + frow) * 128 + ks * 32 + fcol)
                                 + h2 * 8192;
                    uint32_t vh4[4], vl4[4];
                    ldsm_x4(vh4[0], vh4[1], vh4[2], vh4[3], s0 + 32768 + o);
                    ldsm_x4(vl4[0], vl4[1], vl4[2], vl4[3], s0 + 49152 + o);
                    #pragma unroll
                    for (int hf = 0; hf < 2; hf++) {
                        float* d = oacc[ng * 2 + hf];
                        mma_bf16(d, ph, vh4[hf], vh4[hf + 2]);
                        mma_bf16(d, ph, vl4[hf], vl4[hf + 2]);
                        mma_bf16(d, pl, vh4[hf], vh4[hf + 2]);
                    }
                }
            }
        }

        __syncthreads();
        if (kt + 2 < nkt) issueKV(kt + 2, kt & 1);
        cp_commit();
    }

    // ---- epilogue ----
    float inv0 = 1.f / lsum0, inv1 = 1.f / lsum1;
    size_t row0 = (size_t)(b * T_SEQ + Q0 + w * 16 + g);
    #pragma unroll
    for (int i = 0; i < 8; i++) {
        int col = h * HDIM + i * 8 + tc * 2;
        float v0 = oacc[i][0] * inv0, v1 = oacc[i][1] * inv0;
        __nv_bfloat162 hv = __floats2bfloat162_rn(v0, v1);
        __nv_bfloat162 lv = __floats2bfloat162_rn(v0 - __low2float(hv), v1 - __high2float(hv));
        *(__nv_bfloat162*)(yh + row0 * C_EMB + col) = hv;
        *(__nv_bfloat162*)(yl + row0 * C_EMB + col) = lv;
        float v2 = oacc[i][2] * inv1, v3 = oacc[i][3] * inv1;
        hv = __floats2bfloat162_rn(v2, v3);
        lv = __floats2bfloat162_rn(v2 - __low2float(hv), v3 - __high2float(hv));
        *(__nv_bfloat162*)(yh + (row0 + 8) * C_EMB + col) = hv;
        *(__nv_bfloat162*)(yl + (row0 + 8) * C_EMB + col) = lv;
    }
}

// ---------------- launch ----------------
extern "C" void kernel_launch(void* const* d_in, const int* in_sizes, int n_in,
                              void* d_out, int out_size)
{
    const float* x      = (const float*)d_in[0];
    const float* W_attn = (const float*)d_in[1];
    const float* b_attn = (const float*)d_in[2];
    const float* W_proj = (const float*)d_in[3];
    const float* b_proj = (const float*)d_in[4];
    float* out = (float*)d_out;

    __nv_bfloat16 *qkvh, *qkvl, *vth, *vtl, *ah, *al, *bh, *bl;
    cudaGetSymbolAddress((void**)&qkvh, g_qkvh);
    cudaGetSymbolAddress((void**)&qkvl, g_qkvl);
    cudaGetSymbolAddress((void**)&vth, g_vth);
    cudaGetSymbolAddress((void**)&vtl, g_vtl);
    cudaGetSymbolAddress((void**)&ah, g_ah);
    cudaGetSymbolAddress((void**)&al, g_al);
    cudaGetSymbolAddress((void**)&bh, g_bh);
    cudaGetSymbolAddress((void**)&bl, g_bl);

    cudaFuncSetAttribute(gemm_hmma<true>,  cudaFuncAttributeMaxDynamicSharedMemorySize, SM_TOTAL);
    cudaFuncSetAttribute(gemm_hmma<false>, cudaFuncAttributeMaxDynamicSharedMemorySize, SM_TOTAL);
    cudaFuncSetAttribute(attn_hmma, cudaFuncAttributeMaxDynamicSharedMemorySize, A_SMEM);

    const int nx = BT * C_EMB;

    conv_hilo<<<nx / 4 / 256, 256>>>(x, ah, al, nx);
    conv_t_hilo<<<dim3(C3 / 32, C_EMB / 32), dim3(32, 8)>>>(W_attn, bh, bl, C_EMB, C3);
    gemm_hmma<true><<<dim3(C3 / GBN, BT / GBM), 256, SM_TOTAL>>>(
        ah, al, bh, bl, b_attn, nullptr, qkvh, qkvl, BT, C3, C_EMB);
    vtrans<<<dim3(T_SEQ / 32, HDIM / 32, BATCH * NHEAD), dim3(32, 8)>>>(qkvh, qkvl, vth, vtl);
    attn_hmma<<<dim3(T_SEQ / 128, NHEAD, BATCH), 256, A_SMEM>>>(qkvh, qkvl, vth, vtl, ah, al);
    conv_t_hilo<<<dim3(C_EMB / 32, C_EMB / 32), dim3(32, 8)>>>(W_proj, bh, bl, C_EMB, C_EMB);
    gemm_hmma<false><<<dim3(C_EMB / GBN, BT / GBM), 256, SM_TOTAL>>>(
        ah, al, bh, bl, b_proj, out, nullptr, nullptr, BT, C_EMB, C_EMB);
}

// round 6
// speedup vs baseline: 4.0729x; 1.4128x over previous
#include <cuda_runtime.h>
#include <cuda_fp16.h>
#include <cstdint>

#define BATCH   2
#define T_SEQ   2048
#define C_EMB   1024
#define NHEAD   16
#define HDIM    64
#define BT      (BATCH * T_SEQ)      // 4096
#define C3      (3 * C_EMB)          // 3072

// ---------------- scratch (device globals) ----------------
__device__ __half g_qkvh[(size_t)BT * C3];    // qkv hi (q,k,v)
__device__ __half g_qkvl[(size_t)BT * C3];    // qkv lo (only q-range used)
__device__ __half g_vt[(size_t)BATCH * NHEAD * HDIM * T_SEQ];   // V^T single
__device__ __half g_ah[(size_t)BT * C_EMB];   // activation hi (x, then y)
__device__ __half g_al[(size_t)BT * C_EMB];   // activation lo
__device__ __half g_b[(size_t)C3 * C_EMB];    // W^T single fp16

// ---------------- PTX helpers (base-target sm_80+ only) ----------------
static __device__ __forceinline__ uint32_t smem_u32(const void* p) {
    uint32_t a;
    asm("{ .reg .u64 t; cvta.to.shared.u64 t, %1; cvt.u32.u64 %0, t; }" : "=r"(a) : "l"(p));
    return a;
}
static __device__ __forceinline__ void cp_async16(uint32_t dst, const void* src) {
    asm volatile("cp.async.cg.shared.global [%0], [%1], 16;" :: "r"(dst), "l"(src) : "memory");
}
static __device__ __forceinline__ void cp_commit() {
    asm volatile("cp.async.commit_group;" ::: "memory");
}
static __device__ __forceinline__ void cp_wait2() {
    asm volatile("cp.async.wait_group 2;" ::: "memory");
}
static __device__ __forceinline__ void ldsm_x4(uint32_t& r0, uint32_t& r1, uint32_t& r2,
                                               uint32_t& r3, uint32_t addr) {
    asm volatile("ldmatrix.sync.aligned.m8n8.x4.shared.b16 {%0,%1,%2,%3}, [%4];"
                 : "=r"(r0), "=r"(r1), "=r"(r2), "=r"(r3) : "r"(addr));
}
static __device__ __forceinline__ void mma_f16(float* d, const uint32_t* a,
                                               uint32_t b0, uint32_t b1) {
    asm volatile(
        "mma.sync.aligned.m16n8k16.row.col.f32.f16.f16.f32 "
        "{%0,%1,%2,%3}, {%4,%5,%6,%7}, {%8,%9}, {%0,%1,%2,%3};"
        : "+f"(d[0]), "+f"(d[1]), "+f"(d[2]), "+f"(d[3])
        : "r"(a[0]), "r"(a[1]), "r"(a[2]), "r"(a[3]), "r"(b0), "r"(b1));
}
static __device__ __forceinline__ uint32_t sw128(uint32_t o) {
    return o ^ ((o >> 3) & 0x70);
}
static __device__ __forceinline__ uint32_t h2u(__half2 v) {
    return *reinterpret_cast<uint32_t*>(&v);
}

// ---------------- HMMA GEMM: C = (Ah+Al) @ B^T + bias ----------------
// A hi/lo fp16 [M,K] K-major; B single fp16 [N,K] K-major.
// CTA 128x256, warps 2Mx4N (warp tile 64x64), BK=64, 3-stage cp.async.
// Stage: Ah 16K | Al 16K | B 32K = 64 KB; 3 stages = 192 KB.
#define GBM 128
#define GBN 256
#define GBK 64
#define G_STG 65536
#define SM_TOTAL (3 * G_STG)

template <bool SPLIT>
__global__ __launch_bounds__(256, 1)
void gemm_f16(const __half* __restrict__ Ah, const __half* __restrict__ Al,
              const __half* __restrict__ B,
              const float* __restrict__ bias, float* __restrict__ C,
              __half* __restrict__ Ch, __half* __restrict__ Cl,
              int M, int N, int K)
{
    extern __shared__ char smem[];
    const uint32_t sbase = smem_u32(smem);
    const int t = threadIdx.x, lane = t & 31, w = t >> 5;
    const int wm = (w >> 2) * 64;
    const int wn = (w & 3) * 64;
    const int bm = blockIdx.y * GBM, bn = blockIdx.x * GBN;

    const int lr = t >> 3;
    const int lc = (t & 7) * 16;
    const size_t Kb = (size_t)K * 2;
    const char* pAh = (const char*)Ah + (size_t)(bm + lr) * Kb + lc;
    const char* pAl = (const char*)Al + (size_t)(bm + lr) * Kb + lc;
    const char* pB  = (const char*)B  + (size_t)(bn + lr) * Kb + lc;

    auto issue = [&](int c) {
        const uint32_t sb = sbase + (c % 3) * G_STG;
        const size_t go = (size_t)c * 128;
        #pragma unroll
        for (int rr = 0; rr < 4; rr++) {
            uint32_t so = sw128((uint32_t)(lr + rr * 32) * 128 + lc);
            size_t gr = (size_t)rr * 32 * Kb + go;
            cp_async16(sb + so,         pAh + gr);
            cp_async16(sb + 16384 + so, pAl + gr);
        }
        #pragma unroll
        for (int rr = 0; rr < 8; rr++) {
            uint32_t so = sw128((uint32_t)(lr + rr * 32) * 128 + lc);
            cp_async16(sb + 32768 + so, pB + (size_t)rr * 32 * Kb + go);
        }
    };

    float acc[4][8][4] = {};
    const int nc = K / GBK;

    issue(0); cp_commit();
    issue(1); cp_commit();
    issue(2); cp_commit();

    const int frow = lane & 15;
    const int fcol = (lane >> 4) * 16;

    for (int c = 0; c < nc; c++) {
        cp_wait2();
        __syncthreads();
        const uint32_t sb = sbase + (c % 3) * G_STG;

        #pragma unroll
        for (int ks = 0; ks < GBK / 16; ks++) {
            const int kb = ks * 32 + fcol;
            uint32_t ah[4][4], al[4][4];
            #pragma unroll
            for (int mt = 0; mt < 4; mt++) {
                uint32_t o = sw128((uint32_t)(wm + mt * 16 + frow) * 128 + kb);
                ldsm_x4(ah[mt][0], ah[mt][1], ah[mt][2], ah[mt][3], sb + o);
                ldsm_x4(al[mt][0], al[mt][1], al[mt][2], al[mt][3], sb + 16384 + o);
            }
            uint32_t bf[4][4];
            #pragma unroll
            for (int nt = 0; nt < 4; nt++) {
                uint32_t o = sw128((uint32_t)(wn + nt * 16 + frow) * 128 + kb);
                ldsm_x4(bf[nt][0], bf[nt][1], bf[nt][2], bf[nt][3], sb + 32768 + o);
            }
            // pass 1: Ah * B
            #pragma unroll
            for (int nt = 0; nt < 4; nt++)
                #pragma unroll
                for (int mt = 0; mt < 4; mt++)
                    #pragma unroll
                    for (int hf = 0; hf < 2; hf++)
                        mma_f16(acc[mt][nt * 2 + hf], ah[mt], bf[nt][hf], bf[nt][hf + 2]);
            // pass 2: Al * B
            #pragma unroll
            for (int nt = 0; nt < 4; nt++)
                #pragma unroll
                for (int mt = 0; mt < 4; mt++)
                    #pragma unroll
                    for (int hf = 0; hf < 2; hf++)
                        mma_f16(acc[mt][nt * 2 + hf], al[mt], bf[nt][hf], bf[nt][hf + 2]);
        }
        __syncthreads();
        if (c + 3 < nc) issue(c + 3);
        cp_commit();
    }

    const int g = lane >> 2, tc = lane & 3;
    #pragma unroll
    for (int mt = 0; mt < 4; mt++) {
        const int row0 = bm + wm + mt * 16 + g;
        #pragma unroll
        for (int j = 0; j < 8; j++) {
            const int col = bn + wn + j * 8 + tc * 2;
            float b0 = bias[col], b1 = bias[col + 1];
            float* d = acc[mt][j];
            float v00 = d[0] + b0, v01 = d[1] + b1;
            float v10 = d[2] + b0, v11 = d[3] + b1;
            if constexpr (SPLIT) {
                __half2 h0 = __floats2half2_rn(v00, v01);
                float2 f0 = __half22float2(h0);
                __half2 l0 = __floats2half2_rn(v00 - f0.x, v01 - f0.y);
                __half2 h1 = __floats2half2_rn(v10, v11);
                float2 f1 = __half22float2(h1);
                __half2 l1 = __floats2half2_rn(v10 - f1.x, v11 - f1.y);
                *(__half2*)(Ch + (size_t)row0 * N + col) = h0;
                *(__half2*)(Cl + (size_t)row0 * N + col) = l0;
                *(__half2*)(Ch + (size_t)(row0 + 8) * N + col) = h1;
                *(__half2*)(Cl + (size_t)(row0 + 8) * N + col) = l1;
            } else {
                *(float2*)(C + (size_t)row0 * N + col) = make_float2(v00, v01);
                *(float2*)(C + (size_t)(row0 + 8) * N + col) = make_float2(v10, v11);
            }
        }
    }
}

// ---------------- fp32 -> fp16 hi/lo split ----------------
__global__ void conv_hilo(const float* __restrict__ x, __half* __restrict__ h,
                          __half* __restrict__ l, int n)
{
    int i = (blockIdx.x * blockDim.x + threadIdx.x) * 4;
    if (i >= n) return;
    float4 v = *(const float4*)(x + i);
    __half2 h0 = __floats2half2_rn(v.x, v.y);
    __half2 h1 = __floats2half2_rn(v.z, v.w);
    float2 f0 = __half22float2(h0), f1 = __half22float2(h1);
    __half2 l0 = __floats2half2_rn(v.x - f0.x, v.y - f0.y);
    __half2 l1 = __floats2half2_rn(v.z - f1.x, v.w - f1.y);
    *(__half2*)(h + i)     = h0;
    *(__half2*)(h + i + 2) = h1;
    *(__half2*)(l + i)     = l0;
    *(__half2*)(l + i + 2) = l1;
}

// ---------------- W [K,N] -> W^T [N,K] single fp16 ----------------
__global__ void conv_t_f16(const float* __restrict__ W, __half* __restrict__ th,
                           int K, int N)
{
    __shared__ float tile[32][33];
    const int n0 = blockIdx.x * 32, k0 = blockIdx.y * 32;
    const int tx = threadIdx.x, ty = threadIdx.y;
    #pragma unroll
    for (int j = 0; j < 32; j += 8)
        tile[ty + j][tx] = W[(size_t)(k0 + ty + j) * N + n0 + tx];
    __syncthreads();
    #pragma unroll
    for (int j = 0; j < 32; j += 8)
        th[(size_t)(n0 + ty + j) * K + k0 + tx] = __float2half(tile[tx][ty + j]);
}

// ---------------- V part of qkv (fp16 hi) -> V^T [b][h][d][T] ----------------
__global__ void vtrans(const __half* __restrict__ qh, __half* __restrict__ vt)
{
    __shared__ __half tile[32][33];
    const int bh = blockIdx.z, b = bh >> 4, h = bh & 15;
    const int t0 = blockIdx.x * 32, d0 = blockIdx.y * 32;
    const int tx = threadIdx.x, ty = threadIdx.y;
    #pragma unroll
    for (int j = 0; j < 32; j += 8)
        tile[ty + j][tx] = qh[(size_t)(b * T_SEQ + t0 + ty + j) * C3 + 2 * C_EMB + h * HDIM + d0 + tx];
    __syncthreads();
    #pragma unroll
    for (int j = 0; j < 32; j += 8)
        vt[((size_t)(b * NHEAD + h) * HDIM + d0 + ty + j) * T_SEQ + t0 + tx] = tile[tx][ty + j];
}

// ---------------- HMMA flash attention (causal), fp16 2-term ----------------
// CTA: 128 q rows x (b,h); 8 warps x 16 rows; 128-key tiles, 3-stage pipeline.
// Q hi/lo 32K; stage: Kh 16K | V 16K = 32K; total 128 KB.
#define A_SQH 0
#define A_SQL 16384
#define A_SK  32768
#define A_STG 32768
#define A_SMEM (A_SK + 3 * A_STG)   // 131072

__global__ __launch_bounds__(256, 1)
void attn_f16(const __half* __restrict__ qkvh, const __half* __restrict__ qkvl,
              const __half* __restrict__ vt,
              __half* __restrict__ yh, __half* __restrict__ yl)
{
    extern __shared__ char smem[];
    const uint32_t sb = smem_u32(smem);
    const int t = threadIdx.x, lane = t & 31, w = t >> 5;
    const int qb = gridDim.x - 1 - blockIdx.x;
    const int h = blockIdx.y, b = blockIdx.z;
    const int Q0 = qb * 128;
    const int nkt = qb + 1;

    const int lr = t >> 3;
    const int lc = (t & 7) * 16;
    const char* qhb = (const char*)qkvh;
    const char* qlb = (const char*)qkvl;
    const char* vb  = (const char*)vt;

    auto issueQ = [&]() {
        #pragma unroll
        for (int rr = 0; rr < 4; rr++) {
            int row = lr + rr * 32;
            size_t g = ((size_t)(b * T_SEQ + Q0 + row) * C3 + h * HDIM) * 2 + lc;
            uint32_t so = sw128((uint32_t)row * 128 + lc);
            cp_async16(sb + A_SQH + so, qhb + g);
            cp_async16(sb + A_SQL + so, qlb + g);
        }
    };
    auto issueKV = [&](int kt) {
        uint32_t s0 = sb + A_SK + (kt % 3) * A_STG;
        #pragma unroll
        for (int rr = 0; rr < 4; rr++) {
            int row = lr + rr * 32;
            uint32_t so = sw128((uint32_t)row * 128 + lc);
            size_t gk = ((size_t)(b * T_SEQ + kt * 128 + row) * C3 + C_EMB + h * HDIM) * 2 + lc;
            cp_async16(s0 + so, qhb + gk);
        }
        #pragma unroll
        for (int j = 0; j < 2; j++) {
            #pragma unroll
            for (int rr = 0; rr < 2; rr++) {
                int row = lr + rr * 32;
                uint32_t so = sw128((uint32_t)row * 128 + lc) + j * 8192;
                size_t gv = (((size_t)(b * NHEAD + h) * HDIM + row) * T_SEQ
                             + kt * 128 + j * 64) * 2 + lc;
                cp_async16(s0 + 16384 + so, vb + gv);
            }
        }
    };

    issueQ(); issueKV(0); cp_commit();
    if (nkt > 1) issueKV(1);
    cp_commit();
    if (nkt > 2) issueKV(2);
    cp_commit();

    const int frow = lane & 15;
    const int fcol = (lane >> 4) * 16;
    const int g = lane >> 2, tc = lane & 3;

    cp_wait2();
    __syncthreads();

    uint32_t qfh[4][4], qfl[4][4];
    #pragma unroll
    for (int ks = 0; ks < 4; ks++) {
        uint32_t o = sw128((uint32_t)(w * 16 + frow) * 128 + ks * 32 + fcol);
        ldsm_x4(qfh[ks][0], qfh[ks][1], qfh[ks][2], qfh[ks][3], sb + A_SQH + o);
        ldsm_x4(qfl[ks][0], qfl[ks][1], qfl[ks][2], qfl[ks][3], sb + A_SQL + o);
    }

    float oacc[8][4] = {};
    float mprev0 = -1e30f, mprev1 = -1e30f;
    float lsum0 = 0.f, lsum1 = 0.f;
    const int r0 = Q0 + w * 16 + g;
    const int r1 = r0 + 8;

    for (int kt = 0; kt < nkt; kt++) {
        if (kt > 0) { cp_wait2(); __syncthreads(); }
        const uint32_t s0 = sb + A_SK + (kt % 3) * A_STG;

        // ---- S = Q K^T over 128 keys (Qh+Ql vs Kh) ----
        float s[16][4] = {};
        #pragma unroll
        for (int ks = 0; ks < 4; ks++) {
            #pragma unroll
            for (int ng = 0; ng < 8; ng++) {
                uint32_t o = sw128((uint32_t)(ng * 16 + frow) * 128 + ks * 32 + fcol);
                uint32_t kh[4];
                ldsm_x4(kh[0], kh[1], kh[2], kh[3], s0 + o);
                #pragma unroll
                for (int hf = 0; hf < 2; hf++) {
                    float* d = s[ng * 2 + hf];
                    mma_f16(d, qfh[ks], kh[hf], kh[hf + 2]);
                    mma_f16(d, qfl[ks], kh[hf], kh[hf + 2]);
                }
            }
        }

        // ---- scale + causal mask ----
        if (kt == nkt - 1) {
            #pragma unroll
            for (int i = 0; i < 16; i++) {
                int kk = kt * 128 + i * 8 + tc * 2;
                s[i][0] = (kk     <= r0) ? s[i][0] * 0.125f : -1e30f;
                s[i][1] = (kk + 1 <= r0) ? s[i][1] * 0.125f : -1e30f;
                s[i][2] = (kk     <= r1) ? s[i][2] * 0.125f : -1e30f;
                s[i][3] = (kk + 1 <= r1) ? s[i][3] * 0.125f : -1e30f;
            }
        } else {
            #pragma unroll
            for (int i = 0; i < 16; i++) {
                s[i][0] *= 0.125f; s[i][1] *= 0.125f;
                s[i][2] *= 0.125f; s[i][3] *= 0.125f;
            }
        }

        // ---- online softmax ----
        float mx0 = -1e30f, mx1 = -1e30f;
        #pragma unroll
        for (int i = 0; i < 16; i++) {
            mx0 = fmaxf(mx0, fmaxf(s[i][0], s[i][1]));
            mx1 = fmaxf(mx1, fmaxf(s[i][2], s[i][3]));
        }
        mx0 = fmaxf(mx0, __shfl_xor_sync(0xffffffffu, mx0, 1));
        mx0 = fmaxf(mx0, __shfl_xor_sync(0xffffffffu, mx0, 2));
        mx1 = fmaxf(mx1, __shfl_xor_sync(0xffffffffu, mx1, 1));
        mx1 = fmaxf(mx1, __shfl_xor_sync(0xffffffffu, mx1, 2));
        float mn0 = fmaxf(mprev0, mx0), mn1 = fmaxf(mprev1, mx1);
        float cf0 = __expf(mprev0 - mn0), cf1 = __expf(mprev1 - mn1);
        mprev0 = mn0; mprev1 = mn1;

        float ls0 = 0.f, ls1 = 0.f;
        #pragma unroll
        for (int i = 0; i < 16; i++) {
            s[i][0] = __expf(s[i][0] - mn0); ls0 += s[i][0];
            s[i][1] = __expf(s[i][1] - mn0); ls0 += s[i][1];
            s[i][2] = __expf(s[i][2] - mn1); ls1 += s[i][2];
            s[i][3] = __expf(s[i][3] - mn1); ls1 += s[i][3];
        }
        ls0 += __shfl_xor_sync(0xffffffffu, ls0, 1);
        ls0 += __shfl_xor_sync(0xffffffffu, ls0, 2);
        ls1 += __shfl_xor_sync(0xffffffffu, ls1, 1);
        ls1 += __shfl_xor_sync(0xffffffffu, ls1, 2);
        lsum0 = lsum0 * cf0 + ls0;
        lsum1 = lsum1 * cf1 + ls1;
        #pragma unroll
        for (int i = 0; i < 8; i++) {
            oacc[i][0] *= cf0; oacc[i][1] *= cf0;
            oacc[i][2] *= cf1; oacc[i][3] *= cf1;
        }

        // ---- O += (Ph+Pl) @ V ----
        #pragma unroll
        for (int h2 = 0; h2 < 2; h2++) {
            #pragma unroll
            for (int ks = 0; ks < 4; ks++) {
                const float* sa = s[h2 * 8 + 2 * ks];
                const float* sc = s[h2 * 8 + 2 * ks + 1];
                __half2 h0 = __floats2half2_rn(sa[0], sa[1]);
                __half2 h1 = __floats2half2_rn(sa[2], sa[3]);
                __half2 h2v = __floats2half2_rn(sc[0], sc[1]);
                __half2 h3 = __floats2half2_rn(sc[2], sc[3]);
                uint32_t ph[4] = { h2u(h0), h2u(h1), h2u(h2v), h2u(h3) };
                float2 f0 = __half22float2(h0), f1 = __half22float2(h1);
                float2 f2 = __half22float2(h2v), f3 = __half22float2(h3);
                __half2 e0 = __floats2half2_rn(sa[0] - f0.x, sa[1] - f0.y);
                __half2 e1 = __floats2half2_rn(sa[2] - f1.x, sa[3] - f1.y);
                __half2 e2 = __floats2half2_rn(sc[0] - f2.x, sc[1] - f2.y);
                __half2 e3 = __floats2half2_rn(sc[2] - f3.x, sc[3] - f3.y);
                uint32_t pl[4] = { h2u(e0), h2u(e1), h2u(e2), h2u(e3) };

                #pragma unroll
                for (int ng = 0; ng < 4; ng++) {
                    uint32_t o = sw128((uint32_t)(ng * 16 + frow) * 128 + ks * 32 + fcol)
                                 + h2 * 8192;
                    uint32_t v4[4];
                    ldsm_x4(v4[0], v4[1], v4[2], v4[3], s0 + 16384 + o);
                    #pragma unroll
                    for (int hf = 0; hf < 2; hf++) {
                        float* d = oacc[ng * 2 + hf];
                        mma_f16(d, ph, v4[hf], v4[hf + 2]);
                        mma_f16(d, pl, v4[hf], v4[hf + 2]);
                    }
                }
            }
        }

        __syncthreads();
        if (kt + 3 < nkt) issueKV(kt + 3);
        cp_commit();
    }

    // ---- epilogue ----
    float inv0 = 1.f / lsum0, inv1 = 1.f / lsum1;
    size_t row0 = (size_t)(b * T_SEQ + Q0 + w * 16 + g);
    #pragma unroll
    for (int i = 0; i < 8; i++) {
        int col = h * HDIM + i * 8 + tc * 2;
        float v0 = oacc[i][0] * inv0, v1 = oacc[i][1] * inv0;
        __half2 hv = __floats2half2_rn(v0, v1);
        float2 f = __half22float2(hv);
        __half2 lv = __floats2half2_rn(v0 - f.x, v1 - f.y);
        *(__half2*)(yh + row0 * C_EMB + col) = hv;
        *(__half2*)(yl + row0 * C_EMB + col) = lv;
        float v2 = oacc[i][2] * inv1, v3 = oacc[i][3] * inv1;
        hv = __floats2half2_rn(v2, v3);
        f = __half22float2(hv);
        lv = __floats2half2_rn(v2 - f.x, v3 - f.y);
        *(__half2*)(yh + (row0 + 8) * C_EMB + col) = hv;
        *(__half2*)(yl + (row0 + 8) * C_EMB + col) = lv;
    }
}

// ---------------- launch ----------------
extern "C" void kernel_launch(void* const* d_in, const int* in_sizes, int n_in,
                              void* d_out, int out_size)
{
    const float* x      = (const float*)d_in[0];
    const float* W_attn = (const float*)d_in[1];
    const float* b_attn = (const float*)d_in[2];
    const float* W_proj = (const float*)d_in[3];
    const float* b_proj = (const float*)d_in[4];
    float* out = (float*)d_out;

    __half *qkvh, *qkvl, *vt, *ah, *al, *bw;
    cudaGetSymbolAddress((void**)&qkvh, g_qkvh);
    cudaGetSymbolAddress((void**)&qkvl, g_qkvl);
    cudaGetSymbolAddress((void**)&vt, g_vt);
    cudaGetSymbolAddress((void**)&ah, g_ah);
    cudaGetSymbolAddress((void**)&al, g_al);
    cudaGetSymbolAddress((void**)&bw, g_b);

    cudaFuncSetAttribute(gemm_f16<true>,  cudaFuncAttributeMaxDynamicSharedMemorySize, SM_TOTAL);
    cudaFuncSetAttribute(gemm_f16<false>, cudaFuncAttributeMaxDynamicSharedMemorySize, SM_TOTAL);
    cudaFuncSetAttribute(attn_f16, cudaFuncAttributeMaxDynamicSharedMemorySize, A_SMEM);

    const int nx = BT * C_EMB;

    conv_hilo<<<nx / 4 / 256, 256>>>(x, ah, al, nx);
    conv_t_f16<<<dim3(C3 / 32, C_EMB / 32), dim3(32, 8)>>>(W_attn, bw, C_EMB, C3);
    gemm_f16<true><<<dim3(C3 / GBN, BT / GBM), 256, SM_TOTAL>>>(
        ah, al, bw, b_attn, nullptr, qkvh, qkvl, BT, C3, C_EMB);
    vtrans<<<dim3(T_SEQ / 32, HDIM / 32, BATCH * NHEAD), dim3(32, 8)>>>(qkvh, vt);
    attn_f16<<<dim3(T_SEQ / 128, NHEAD, BATCH), 256, A_SMEM>>>(qkvh, qkvl, vt, ah, al);
    conv_t_f16<<<dim3(C_EMB / 32, C_EMB / 32), dim3(32, 8)>>>(W_proj, bw, C_EMB, C_EMB);
    gemm_f16<false><<<dim3(C_EMB / GBN, BT / GBM), 256, SM_TOTAL>>>(
        ah, al, bw, b_proj, out, nullptr, nullptr, BT, C_EMB, C_EMB);
}

// round 7
// speedup vs baseline: 4.2121x; 1.0342x over previous
#include <cuda_runtime.h>
#include <cuda_fp16.h>
#include <cstdint>

#define BATCH   2
#define T_SEQ   2048
#define C_EMB   1024
#define NHEAD   16
#define HDIM    64
#define BT      (BATCH * T_SEQ)      // 4096
#define C3      (3 * C_EMB)          // 3072

// ---------------- scratch (device globals) ----------------
__device__ __half g_qkv[(size_t)BT * C3];                       // qkv fp16
__device__ __half g_vt[(size_t)BATCH * NHEAD * HDIM * T_SEQ];   // V^T
__device__ __half g_a[(size_t)BT * C_EMB];                      // activation (x, then y)
__device__ __half g_b[(size_t)C3 * C_EMB];                      // W^T fp16

// ---------------- PTX helpers (base-target sm_80+ only) ----------------
static __device__ __forceinline__ uint32_t smem_u32(const void* p) {
    uint32_t a;
    asm("{ .reg .u64 t; cvta.to.shared.u64 t, %1; cvt.u32.u64 %0, t; }" : "=r"(a) : "l"(p));
    return a;
}
static __device__ __forceinline__ void cp_async16(uint32_t dst, const void* src) {
    asm volatile("cp.async.cg.shared.global [%0], [%1], 16;" :: "r"(dst), "l"(src) : "memory");
}
static __device__ __forceinline__ void cp_commit() {
    asm volatile("cp.async.commit_group;" ::: "memory");
}
static __device__ __forceinline__ void cp_wait2() {
    asm volatile("cp.async.wait_group 2;" ::: "memory");
}
static __device__ __forceinline__ void ldsm_x4(uint32_t& r0, uint32_t& r1, uint32_t& r2,
                                               uint32_t& r3, uint32_t addr) {
    asm volatile("ldmatrix.sync.aligned.m8n8.x4.shared.b16 {%0,%1,%2,%3}, [%4];"
                 : "=r"(r0), "=r"(r1), "=r"(r2), "=r"(r3) : "r"(addr));
}
static __device__ __forceinline__ void mma_f16(float* d, const uint32_t* a,
                                               uint32_t b0, uint32_t b1) {
    asm volatile(
        "mma.sync.aligned.m16n8k16.row.col.f32.f16.f16.f32 "
        "{%0,%1,%2,%3}, {%4,%5,%6,%7}, {%8,%9}, {%0,%1,%2,%3};"
        : "+f"(d[0]), "+f"(d[1]), "+f"(d[2]), "+f"(d[3])
        : "r"(a[0]), "r"(a[1]), "r"(a[2]), "r"(a[3]), "r"(b0), "r"(b1));
}
static __device__ __forceinline__ uint32_t sw128(uint32_t o) {
    return o ^ ((o >> 3) & 0x70);
}
static __device__ __forceinline__ uint32_t h2u(__half2 v) {
    return *reinterpret_cast<uint32_t*>(&v);
}

// ---------------- HMMA GEMM: C = A @ B^T + bias (all single fp16) ----------------
// CTA 128x256, warps 2Mx4N (warp tile 64x64), BK=64, 3-stage cp.async.
// Stage: A 16K | B 32K = 48 KB; 3 stages = 144 KB.
#define GBM 128
#define GBN 256
#define GBK 64
#define G_STG 49152
#define SM_TOTAL (3 * G_STG)

template <bool HALF_OUT>
__global__ __launch_bounds__(256, 1)
void gemm_f16(const __half* __restrict__ A, const __half* __restrict__ B,
              const float* __restrict__ bias, float* __restrict__ C,
              __half* __restrict__ Ch, int M, int N, int K)
{
    extern __shared__ char smem[];
    const uint32_t sbase = smem_u32(smem);
    const int t = threadIdx.x, lane = t & 31, w = t >> 5;
    const int wm = (w >> 2) * 64;
    const int wn = (w & 3) * 64;
    const int bm = blockIdx.y * GBM, bn = blockIdx.x * GBN;

    const int lr = t >> 3;
    const int lc = (t & 7) * 16;
    const size_t Kb = (size_t)K * 2;
    const char* pA = (const char*)A + (size_t)(bm + lr) * Kb + lc;
    const char* pB = (const char*)B + (size_t)(bn + lr) * Kb + lc;

    auto issue = [&](int c) {
        const uint32_t sb = sbase + (c % 3) * G_STG;
        const size_t go = (size_t)c * 128;
        #pragma unroll
        for (int rr = 0; rr < 4; rr++) {
            uint32_t so = sw128((uint32_t)(lr + rr * 32) * 128 + lc);
            cp_async16(sb + so, pA + (size_t)rr * 32 * Kb + go);
        }
        #pragma unroll
        for (int rr = 0; rr < 8; rr++) {
            uint32_t so = sw128((uint32_t)(lr + rr * 32) * 128 + lc);
            cp_async16(sb + 16384 + so, pB + (size_t)rr * 32 * Kb + go);
        }
    };

    float acc[4][8][4] = {};
    const int nc = K / GBK;

    issue(0); cp_commit();
    issue(1); cp_commit();
    issue(2); cp_commit();

    const int frow = lane & 15;
    const int fcol = (lane >> 4) * 16;

    for (int c = 0; c < nc; c++) {
        cp_wait2();
        __syncthreads();
        const uint32_t sb = sbase + (c % 3) * G_STG;

        #pragma unroll
        for (int ks = 0; ks < GBK / 16; ks++) {
            const int kb = ks * 32 + fcol;
            uint32_t af[4][4];
            #pragma unroll
            for (int mt = 0; mt < 4; mt++) {
                uint32_t o = sw128((uint32_t)(wm + mt * 16 + frow) * 128 + kb);
                ldsm_x4(af[mt][0], af[mt][1], af[mt][2], af[mt][3], sb + o);
            }
            uint32_t bf[4][4];
            #pragma unroll
            for (int nt = 0; nt < 4; nt++) {
                uint32_t o = sw128((uint32_t)(wn + nt * 16 + frow) * 128 + kb);
                ldsm_x4(bf[nt][0], bf[nt][1], bf[nt][2], bf[nt][3], sb + 16384 + o);
            }
            #pragma unroll
            for (int nt = 0; nt < 4; nt++)
                #pragma unroll
                for (int mt = 0; mt < 4; mt++)
                    #pragma unroll
                    for (int hf = 0; hf < 2; hf++)
                        mma_f16(acc[mt][nt * 2 + hf], af[mt], bf[nt][hf], bf[nt][hf + 2]);
        }
        __syncthreads();
        if (c + 3 < nc) issue(c + 3);
        cp_commit();
    }

    const int g = lane >> 2, tc = lane & 3;
    #pragma unroll
    for (int mt = 0; mt < 4; mt++) {
        const int row0 = bm + wm + mt * 16 + g;
        #pragma unroll
        for (int j = 0; j < 8; j++) {
            const int col = bn + wn + j * 8 + tc * 2;
            float b0 = bias[col], b1 = bias[col + 1];
            float* d = acc[mt][j];
            float v00 = d[0] + b0, v01 = d[1] + b1;
            float v10 = d[2] + b0, v11 = d[3] + b1;
            if constexpr (HALF_OUT) {
                *(__half2*)(Ch + (size_t)row0 * N + col) = __floats2half2_rn(v00, v01);
                *(__half2*)(Ch + (size_t)(row0 + 8) * N + col) = __floats2half2_rn(v10, v11);
            } else {
                *(float2*)(C + (size_t)row0 * N + col) = make_float2(v00, v01);
                *(float2*)(C + (size_t)(row0 + 8) * N + col) = make_float2(v10, v11);
            }
        }
    }
}

// ---------------- fp32 -> fp16 ----------------
__global__ void conv_f16(const float* __restrict__ x, __half* __restrict__ h, int n)
{
    int i = (blockIdx.x * blockDim.x + threadIdx.x) * 4;
    if (i >= n) return;
    float4 v = *(const float4*)(x + i);
    *(__half2*)(h + i)     = __floats2half2_rn(v.x, v.y);
    *(__half2*)(h + i + 2) = __floats2half2_rn(v.z, v.w);
}

// ---------------- W [K,N] -> W^T [N,K] fp16 ----------------
__global__ void conv_t_f16(const float* __restrict__ W, __half* __restrict__ th,
                           int K, int N)
{
    __shared__ float tile[32][33];
    const int n0 = blockIdx.x * 32, k0 = blockIdx.y * 32;
    const int tx = threadIdx.x, ty = threadIdx.y;
    #pragma unroll
    for (int j = 0; j < 32; j += 8)
        tile[ty + j][tx] = W[(size_t)(k0 + ty + j) * N + n0 + tx];
    __syncthreads();
    #pragma unroll
    for (int j = 0; j < 32; j += 8)
        th[(size_t)(n0 + ty + j) * K + k0 + tx] = __float2half(tile[tx][ty + j]);
}

// ---------------- V part of qkv -> V^T [b][h][d][T] ----------------
__global__ void vtrans(const __half* __restrict__ qh, __half* __restrict__ vt)
{
    __shared__ __half tile[32][33];
    const int bh = blockIdx.z, b = bh >> 4, h = bh & 15;
    const int t0 = blockIdx.x * 32, d0 = blockIdx.y * 32;
    const int tx = threadIdx.x, ty = threadIdx.y;
    #pragma unroll
    for (int j = 0; j < 32; j += 8)
        tile[ty + j][tx] = qh[(size_t)(b * T_SEQ + t0 + ty + j) * C3 + 2 * C_EMB + h * HDIM + d0 + tx];
    __syncthreads();
    #pragma unroll
    for (int j = 0; j < 32; j += 8)
        vt[((size_t)(b * NHEAD + h) * HDIM + d0 + ty + j) * T_SEQ + t0 + tx] = tile[tx][ty + j];
}

// ---------------- HMMA flash attention (causal), single fp16 ----------------
// CTA: 128 q rows x (b,h); 8 warps x 16 rows; 128-key tiles, 3-stage pipeline.
// Q 16K; stage: K 16K | V 16K = 32K; total 112 KB.
#define A_SQ  0
#define A_SK  16384
#define A_STG 32768
#define A_SMEM (A_SK + 3 * A_STG)   // 114688

__global__ __launch_bounds__(256, 1)
void attn_f16(const __half* __restrict__ qkv, const __half* __restrict__ vt,
              __half* __restrict__ y)
{
    extern __shared__ char smem[];
    const uint32_t sb = smem_u32(smem);
    const int t = threadIdx.x, lane = t & 31, w = t >> 5;
    const int qb = gridDim.x - 1 - blockIdx.x;   // heavy blocks first
    const int h = blockIdx.y, b = blockIdx.z;
    const int Q0 = qb * 128;
    const int nkt = qb + 1;

    const int lr = t >> 3;
    const int lc = (t & 7) * 16;
    const char* qb8 = (const char*)qkv;
    const char* vb8 = (const char*)vt;

    auto issueQ = [&]() {
        #pragma unroll
        for (int rr = 0; rr < 4; rr++) {
            int row = lr + rr * 32;
            size_t g = ((size_t)(b * T_SEQ + Q0 + row) * C3 + h * HDIM) * 2 + lc;
            cp_async16(sb + A_SQ + sw128((uint32_t)row * 128 + lc), qb8 + g);
        }
    };
    auto issueKV = [&](int kt) {
        uint32_t s0 = sb + A_SK + (kt % 3) * A_STG;
        #pragma unroll
        for (int rr = 0; rr < 4; rr++) {
            int row = lr + rr * 32;
            uint32_t so = sw128((uint32_t)row * 128 + lc);
            size_t gk = ((size_t)(b * T_SEQ + kt * 128 + row) * C3 + C_EMB + h * HDIM) * 2 + lc;
            cp_async16(s0 + so, qb8 + gk);
        }
        #pragma unroll
        for (int j = 0; j < 2; j++) {
            #pragma unroll
            for (int rr = 0; rr < 2; rr++) {
                int row = lr + rr * 32;
                uint32_t so = sw128((uint32_t)row * 128 + lc) + j * 8192;
                size_t gv = (((size_t)(b * NHEAD + h) * HDIM + row) * T_SEQ
                             + kt * 128 + j * 64) * 2 + lc;
                cp_async16(s0 + 16384 + so, vb8 + gv);
            }
        }
    };

    issueQ(); issueKV(0); cp_commit();
    if (nkt > 1) issueKV(1);
    cp_commit();
    if (nkt > 2) issueKV(2);
    cp_commit();

    const int frow = lane & 15;
    const int fcol = (lane >> 4) * 16;
    const int g = lane >> 2, tc = lane & 3;

    cp_wait2();
    __syncthreads();

    uint32_t qf[4][4];
    #pragma unroll
    for (int ks = 0; ks < 4; ks++) {
        uint32_t o = sw128((uint32_t)(w * 16 + frow) * 128 + ks * 32 + fcol);
        ldsm_x4(qf[ks][0], qf[ks][1], qf[ks][2], qf[ks][3], sb + A_SQ + o);
    }

    float oacc[8][4] = {};
    float mprev0 = -1e30f, mprev1 = -1e30f;
    float lsum0 = 0.f, lsum1 = 0.f;
    const int r0 = Q0 + w * 16 + g;
    const int r1 = r0 + 8;

    for (int kt = 0; kt < nkt; kt++) {
        if (kt > 0) { cp_wait2(); __syncthreads(); }
        const uint32_t s0 = sb + A_SK + (kt % 3) * A_STG;
        const bool diag = (kt == nkt - 1);
        const int ngmax = diag ? (w + 1) : 8;   // causal skip (warp-uniform)

        // ---- S = Q K^T ----
        float s[16][4] = {};
        for (int ng = 0; ng < ngmax; ng++) {
            #pragma unroll
            for (int ks = 0; ks < 4; ks++) {
                uint32_t o = sw128((uint32_t)(ng * 16 + frow) * 128 + ks * 32 + fcol);
                uint32_t kh[4];
                ldsm_x4(kh[0], kh[1], kh[2], kh[3], s0 + o);
                #pragma unroll
                for (int hf = 0; hf < 2; hf++)
                    mma_f16(s[ng * 2 + hf], qf[ks], kh[hf], kh[hf + 2]);
            }
        }

        // ---- scale + causal mask (skipped groups get -1e30 here) ----
        if (diag) {
            #pragma unroll
            for (int i = 0; i < 16; i++) {
                int kk = kt * 128 + i * 8 + tc * 2;
                s[i][0] = (kk     <= r0) ? s[i][0] * 0.125f : -1e30f;
                s[i][1] = (kk + 1 <= r0) ? s[i][1] * 0.125f : -1e30f;
                s[i][2] = (kk     <= r1) ? s[i][2] * 0.125f : -1e30f;
                s[i][3] = (kk + 1 <= r1) ? s[i][3] * 0.125f : -1e30f;
            }
        } else {
            #pragma unroll
            for (int i = 0; i < 16; i++) {
                s[i][0] *= 0.125f; s[i][1] *= 0.125f;
                s[i][2] *= 0.125f; s[i][3] *= 0.125f;
            }
        }

        // ---- online softmax ----
        float mx0 = -1e30f, mx1 = -1e30f;
        #pragma unroll
        for (int i = 0; i < 16; i++) {
            mx0 = fmaxf(mx0, fmaxf(s[i][0], s[i][1]));
            mx1 = fmaxf(mx1, fmaxf(s[i][2], s[i][3]));
        }
        mx0 = fmaxf(mx0, __shfl_xor_sync(0xffffffffu, mx0, 1));
        mx0 = fmaxf(mx0, __shfl_xor_sync(0xffffffffu, mx0, 2));
        mx1 = fmaxf(mx1, __shfl_xor_sync(0xffffffffu, mx1, 1));
        mx1 = fmaxf(mx1, __shfl_xor_sync(0xffffffffu, mx1, 2));
        float mn0 = fmaxf(mprev0, mx0), mn1 = fmaxf(mprev1, mx1);
        float cf0 = __expf(mprev0 - mn0), cf1 = __expf(mprev1 - mn1);
        mprev0 = mn0; mprev1 = mn1;

        float ls0 = 0.f, ls1 = 0.f;
        #pragma unroll
        for (int i = 0; i < 16; i++) {
            s[i][0] = __expf(s[i][0] - mn0); ls0 += s[i][0];
            s[i][1] = __expf(s[i][1] - mn0); ls0 += s[i][1];
            s[i][2] = __expf(s[i][2] - mn1); ls1 += s[i][2];
            s[i][3] = __expf(s[i][3] - mn1); ls1 += s[i][3];
        }
        ls0 += __shfl_xor_sync(0xffffffffu, ls0, 1);
        ls0 += __shfl_xor_sync(0xffffffffu, ls0, 2);
        ls1 += __shfl_xor_sync(0xffffffffu, ls1, 1);
        ls1 += __shfl_xor_sync(0xffffffffu, ls1, 2);
        lsum0 = lsum0 * cf0 + ls0;
        lsum1 = lsum1 * cf1 + ls1;
        #pragma unroll
        for (int i = 0; i < 8; i++) {
            oacc[i][0] *= cf0; oacc[i][1] *= cf0;
            oacc[i][2] *= cf1; oacc[i][3] *= cf1;
        }

        // ---- O += P @ V (skipped key-groups have P == 0 exactly) ----
        const int kgmax = ngmax;   // same causal bound on key groups
        for (int kg = 0; kg < kgmax; kg++) {
            const int h2 = kg >> 2, ks = kg & 3;
            const float* sa = s[2 * kg];
            const float* sc = s[2 * kg + 1];
            uint32_t ph[4] = {
                h2u(__floats2half2_rn(sa[0], sa[1])),
                h2u(__floats2half2_rn(sa[2], sa[3])),
                h2u(__floats2half2_rn(sc[0], sc[1])),
                h2u(__floats2half2_rn(sc[2], sc[3]))
            };
            #pragma unroll
            for (int ng = 0; ng < 4; ng++) {
                uint32_t o = sw128((uint32_t)(ng * 16 + frow) * 128 + ks * 32 + fcol)
                             + h2 * 8192;
                uint32_t v4[4];
                ldsm_x4(v4[0], v4[1], v4[2], v4[3], s0 + 16384 + o);
                #pragma unroll
                for (int hf = 0; hf < 2; hf++)
                    mma_f16(oacc[ng * 2 + hf], ph, v4[hf], v4[hf + 2]);
            }
        }

        __syncthreads();
        if (kt + 3 < nkt) issueKV(kt + 3);
        cp_commit();
    }

    // ---- epilogue: y fp16 ----
    float inv0 = 1.f / lsum0, inv1 = 1.f / lsum1;
    size_t row0 = (size_t)(b * T_SEQ + Q0 + w * 16 + g);
    #pragma unroll
    for (int i = 0; i < 8; i++) {
        int col = h * HDIM + i * 8 + tc * 2;
        *(__half2*)(y + row0 * C_EMB + col) =
            __floats2half2_rn(oacc[i][0] * inv0, oacc[i][1] * inv0);
        *(__half2*)(y + (row0 + 8) * C_EMB + col) =
            __floats2half2_rn(oacc[i][2] * inv1, oacc[i][3] * inv1);
    }
}

// ---------------- launch ----------------
extern "C" void kernel_launch(void* const* d_in, const int* in_sizes, int n_in,
                              void* d_out, int out_size)
{
    const float* x      = (const float*)d_in[0];
    const float* W_attn = (const float*)d_in[1];
    const float* b_attn = (const float*)d_in[2];
    const float* W_proj = (const float*)d_in[3];
    const float* b_proj = (const float*)d_in[4];
    float* out = (float*)d_out;

    __half *qkv, *vt, *a, *bw;
    cudaGetSymbolAddress((void**)&qkv, g_qkv);
    cudaGetSymbolAddress((void**)&vt, g_vt);
    cudaGetSymbolAddress((void**)&a, g_a);
    cudaGetSymbolAddress((void**)&bw, g_b);

    cudaFuncSetAttribute(gemm_f16<true>,  cudaFuncAttributeMaxDynamicSharedMemorySize, SM_TOTAL);
    cudaFuncSetAttribute(gemm_f16<false>, cudaFuncAttributeMaxDynamicSharedMemorySize, SM_TOTAL);
    cudaFuncSetAttribute(attn_f16, cudaFuncAttributeMaxDynamicSharedMemorySize, A_SMEM);

    const int nx = BT * C_EMB;

    conv_f16<<<nx / 4 / 256, 256>>>(x, a, nx);
    conv_t_f16<<<dim3(C3 / 32, C_EMB / 32), dim3(32, 8)>>>(W_attn, bw, C_EMB, C3);
    gemm_f16<true><<<dim3(C3 / GBN, BT / GBM), 256, SM_TOTAL>>>(
        a, bw, b_attn, nullptr, qkv, BT, C3, C_EMB);
    vtrans<<<dim3(T_SEQ / 32, HDIM / 32, BATCH * NHEAD), dim3(32, 8)>>>(qkv, vt);
    attn_f16<<<dim3(T_SEQ / 128, NHEAD, BATCH), 256, A_SMEM>>>(qkv, vt, a);
    conv_t_f16<<<dim3(C_EMB / 32, C_EMB / 32), dim3(32, 8)>>>(W_proj, bw, C_EMB, C_EMB);
    gemm_f16<false><<<dim3(C_EMB / GBN, BT / GBM), 256, SM_TOTAL>>>(
        a, bw, b_proj, out, nullptr, BT, C_EMB, C_EMB);
}

// round 8
// speedup vs baseline: 4.4946x; 1.0671x over previous
#include <cuda_runtime.h>
#include <cuda_fp16.h>
#include <cstdint>

#define BATCH   2
#define T_SEQ   2048
#define C_EMB   1024
#define NHEAD   16
#define HDIM    64
#define BT      (BATCH * T_SEQ)      // 4096
#define C3      (3 * C_EMB)          // 3072

// ---------------- scratch (device globals) ----------------
__device__ __half g_qkv[(size_t)BT * C3];                       // qkv fp16
__device__ __half g_vt[(size_t)BATCH * NHEAD * HDIM * T_SEQ];   // V^T
__device__ __half g_a[(size_t)BT * C_EMB];                      // activation (x, then y)
__device__ __half g_b[(size_t)C3 * C_EMB];                      // W^T fp16

// ---------------- PTX helpers (base-target sm_80+ only) ----------------
static __device__ __forceinline__ uint32_t smem_u32(const void* p) {
    uint32_t a;
    asm("{ .reg .u64 t; cvta.to.shared.u64 t, %1; cvt.u32.u64 %0, t; }" : "=r"(a) : "l"(p));
    return a;
}
static __device__ __forceinline__ void cp_async16(uint32_t dst, const void* src) {
    asm volatile("cp.async.cg.shared.global [%0], [%1], 16;" :: "r"(dst), "l"(src) : "memory");
}
static __device__ __forceinline__ void cp_commit() {
    asm volatile("cp.async.commit_group;" ::: "memory");
}
static __device__ __forceinline__ void cp_wait1() {
    asm volatile("cp.async.wait_group 1;" ::: "memory");
}
static __device__ __forceinline__ void cp_wait2() {
    asm volatile("cp.async.wait_group 2;" ::: "memory");
}
static __device__ __forceinline__ void ldsm_x4(uint32_t& r0, uint32_t& r1, uint32_t& r2,
                                               uint32_t& r3, uint32_t addr) {
    asm volatile("ldmatrix.sync.aligned.m8n8.x4.shared.b16 {%0,%1,%2,%3}, [%4];"
                 : "=r"(r0), "=r"(r1), "=r"(r2), "=r"(r3) : "r"(addr));
}
static __device__ __forceinline__ void mma_f16(float* d, const uint32_t* a,
                                               uint32_t b0, uint32_t b1) {
    asm volatile(
        "mma.sync.aligned.m16n8k16.row.col.f32.f16.f16.f32 "
        "{%0,%1,%2,%3}, {%4,%5,%6,%7}, {%8,%9}, {%0,%1,%2,%3};"
        : "+f"(d[0]), "+f"(d[1]), "+f"(d[2]), "+f"(d[3])
        : "r"(a[0]), "r"(a[1]), "r"(a[2]), "r"(a[3]), "r"(b0), "r"(b1));
}
static __device__ __forceinline__ uint32_t sw128(uint32_t o) {
    return o ^ ((o >> 3) & 0x70);
}
static __device__ __forceinline__ uint32_t h2u(__half2 v) {
    return *reinterpret_cast<uint32_t*>(&v);
}

// ---------------- HMMA GEMM: C = A @ B^T + bias (single fp16) ----------------
// CTA 128x128, 8 warps (4Mx2N, warp tile 32x64), BK=64, 3-stage, 2 CTAs/SM.
// Stage: A 16K | B 16K = 32 KB; 3 stages = 96 KB.
#define GBM 128
#define GBN 128
#define GBK 64
#define G_STG 32768
#define SM_TOTAL (3 * G_STG)

template <bool HALF_OUT>
__global__ __launch_bounds__(256, 2)
void gemm_f16(const __half* __restrict__ A, const __half* __restrict__ B,
              const float* __restrict__ bias, float* __restrict__ C,
              __half* __restrict__ Ch, int M, int N, int K)
{
    extern __shared__ char smem[];
    const uint32_t sbase = smem_u32(smem);
    const int t = threadIdx.x, lane = t & 31, w = t >> 5;
    const int wm = (w >> 1) * 32;       // 4 M-groups
    const int wn = (w & 1) * 64;        // 2 N-groups
    const int bm = blockIdx.y * GBM, bn = blockIdx.x * GBN;

    const int lr = t >> 3;              // 0..31
    const int lc = (t & 7) * 16;
    const size_t Kb = (size_t)K * 2;
    const char* pA = (const char*)A + (size_t)(bm + lr) * Kb + lc;
    const char* pB = (const char*)B + (size_t)(bn + lr) * Kb + lc;

    auto issue = [&](int c) {
        const uint32_t sb = sbase + (c % 3) * G_STG;
        const size_t go = (size_t)c * 128;
        #pragma unroll
        for (int rr = 0; rr < 4; rr++) {
            uint32_t so = sw128((uint32_t)(lr + rr * 32) * 128 + lc);
            cp_async16(sb + so,         pA + (size_t)rr * 32 * Kb + go);
            cp_async16(sb + 16384 + so, pB + (size_t)rr * 32 * Kb + go);
        }
    };

    float acc[2][8][4] = {};
    const int nc = K / GBK;

    issue(0); cp_commit();
    issue(1); cp_commit();
    issue(2); cp_commit();

    const int frow = lane & 15;
    const int fcol = (lane >> 4) * 16;

    for (int c = 0; c < nc; c++) {
        cp_wait2();
        __syncthreads();
        const uint32_t sb = sbase + (c % 3) * G_STG;

        #pragma unroll
        for (int ks = 0; ks < GBK / 16; ks++) {
            const int kb = ks * 32 + fcol;
            uint32_t af[2][4];
            #pragma unroll
            for (int mt = 0; mt < 2; mt++) {
                uint32_t o = sw128((uint32_t)(wm + mt * 16 + frow) * 128 + kb);
                ldsm_x4(af[mt][0], af[mt][1], af[mt][2], af[mt][3], sb + o);
            }
            uint32_t bf[4][4];
            #pragma unroll
            for (int nt = 0; nt < 4; nt++) {
                uint32_t o = sw128((uint32_t)(wn + nt * 16 + frow) * 128 + kb);
                ldsm_x4(bf[nt][0], bf[nt][1], bf[nt][2], bf[nt][3], sb + 16384 + o);
            }
            #pragma unroll
            for (int nt = 0; nt < 4; nt++)
                #pragma unroll
                for (int mt = 0; mt < 2; mt++)
                    #pragma unroll
                    for (int hf = 0; hf < 2; hf++)
                        mma_f16(acc[mt][nt * 2 + hf], af[mt], bf[nt][hf], bf[nt][hf + 2]);
        }
        __syncthreads();
        if (c + 3 < nc) issue(c + 3);
        cp_commit();
    }

    const int g = lane >> 2, tc = lane & 3;
    #pragma unroll
    for (int mt = 0; mt < 2; mt++) {
        const int row0 = bm + wm + mt * 16 + g;
        #pragma unroll
        for (int j = 0; j < 8; j++) {
            const int col = bn + wn + j * 8 + tc * 2;
            float b0 = bias[col], b1 = bias[col + 1];
            float* d = acc[mt][j];
            float v00 = d[0] + b0, v01 = d[1] + b1;
            float v10 = d[2] + b0, v11 = d[3] + b1;
            if constexpr (HALF_OUT) {
                *(__half2*)(Ch + (size_t)row0 * N + col) = __floats2half2_rn(v00, v01);
                *(__half2*)(Ch + (size_t)(row0 + 8) * N + col) = __floats2half2_rn(v10, v11);
            } else {
                *(float2*)(C + (size_t)row0 * N + col) = make_float2(v00, v01);
                *(float2*)(C + (size_t)(row0 + 8) * N + col) = make_float2(v10, v11);
            }
        }
    }
}

// ---------------- fp32 -> fp16 ----------------
__global__ void conv_f16(const float* __restrict__ x, __half* __restrict__ h, int n)
{
    int i = (blockIdx.x * blockDim.x + threadIdx.x) * 4;
    if (i >= n) return;
    float4 v = *(const float4*)(x + i);
    *(__half2*)(h + i)     = __floats2half2_rn(v.x, v.y);
    *(__half2*)(h + i + 2) = __floats2half2_rn(v.z, v.w);
}

// ---------------- W [K,N] -> W^T [N,K] fp16 ----------------
__global__ void conv_t_f16(const float* __restrict__ W, __half* __restrict__ th,
                           int K, int N)
{
    __shared__ float tile[32][33];
    const int n0 = blockIdx.x * 32, k0 = blockIdx.y * 32;
    const int tx = threadIdx.x, ty = threadIdx.y;
    #pragma unroll
    for (int j = 0; j < 32; j += 8)
        tile[ty + j][tx] = W[(size_t)(k0 + ty + j) * N + n0 + tx];
    __syncthreads();
    #pragma unroll
    for (int j = 0; j < 32; j += 8)
        th[(size_t)(n0 + ty + j) * K + k0 + tx] = __float2half(tile[tx][ty + j]);
}

// ---------------- V part of qkv -> V^T [b][h][d][T] ----------------
__global__ void vtrans(const __half* __restrict__ qh, __half* __restrict__ vt)
{
    __shared__ __half tile[32][33];
    const int bh = blockIdx.z, b = bh >> 4, h = bh & 15;
    const int t0 = blockIdx.x * 32, d0 = blockIdx.y * 32;
    const int tx = threadIdx.x, ty = threadIdx.y;
    #pragma unroll
    for (int j = 0; j < 32; j += 8)
        tile[ty + j][tx] = qh[(size_t)(b * T_SEQ + t0 + ty + j) * C3 + 2 * C_EMB + h * HDIM + d0 + tx];
    __syncthreads();
    #pragma unroll
    for (int j = 0; j < 32; j += 8)
        vt[((size_t)(b * NHEAD + h) * HDIM + d0 + ty + j) * T_SEQ + t0 + tx] = tile[tx][ty + j];
}

// ---------------- HMMA flash attention (causal), single fp16 ----------------
// CTA: 64 q rows x (b,h); 4 warps x 16 rows; 128-key tiles, 2-stage pipeline.
// Q 8K; stage: K 16K | V 16K = 32K; total 72 KB -> 3 CTAs/SM.
#define A_SQ  0
#define A_SK  8192
#define A_STG 32768
#define A_SMEM (A_SK + 2 * A_STG)   // 73728

__global__ __launch_bounds__(128, 3)
void attn_f16(const __half* __restrict__ qkv, const __half* __restrict__ vt,
              __half* __restrict__ y)
{
    extern __shared__ char smem[];
    const uint32_t sb = smem_u32(smem);
    const int t = threadIdx.x, lane = t & 31, w = t >> 5;   // w in 0..3
    const int qb = gridDim.x - 1 - blockIdx.x;   // heavy blocks first
    const int h = blockIdx.y, b = blockIdx.z;
    const int Q0 = qb * 64;
    const int nkt = (Q0 >> 7) + 1;               // 128-key tiles

    const int lr = t >> 3;          // 0..15
    const int lc = (t & 7) * 16;
    const char* qb8 = (const char*)qkv;
    const char* vb8 = (const char*)vt;

    auto issueQ = [&]() {
        #pragma unroll
        for (int rr = 0; rr < 4; rr++) {
            int row = lr + rr * 16;
            size_t g = ((size_t)(b * T_SEQ + Q0 + row) * C3 + h * HDIM) * 2 + lc;
            cp_async16(sb + A_SQ + sw128((uint32_t)row * 128 + lc), qb8 + g);
        }
    };
    auto issueKV = [&](int kt) {
        uint32_t s0 = sb + A_SK + (kt & 1) * A_STG;
        #pragma unroll
        for (int rr = 0; rr < 8; rr++) {
            int row = lr + rr * 16;
            uint32_t so = sw128((uint32_t)row * 128 + lc);
            size_t gk = ((size_t)(b * T_SEQ + kt * 128 + row) * C3 + C_EMB + h * HDIM) * 2 + lc;
            cp_async16(s0 + so, qb8 + gk);
        }
        #pragma unroll
        for (int j = 0; j < 2; j++) {
            #pragma unroll
            for (int rr = 0; rr < 4; rr++) {
                int row = lr + rr * 16;
                uint32_t so = sw128((uint32_t)row * 128 + lc) + j * 8192;
                size_t gv = (((size_t)(b * NHEAD + h) * HDIM + row) * T_SEQ
                             + kt * 128 + j * 64) * 2 + lc;
                cp_async16(s0 + 16384 + so, vb8 + gv);
            }
        }
    };

    issueQ(); issueKV(0); cp_commit();
    if (nkt > 1) issueKV(1);
    cp_commit();

    const int frow = lane & 15;
    const int fcol = (lane >> 4) * 16;
    const int g = lane >> 2, tc = lane & 3;

    cp_wait1();
    __syncthreads();

    uint32_t qf[4][4];
    #pragma unroll
    for (int ks = 0; ks < 4; ks++) {
        uint32_t o = sw128((uint32_t)(w * 16 + frow) * 128 + ks * 32 + fcol);
        ldsm_x4(qf[ks][0], qf[ks][1], qf[ks][2], qf[ks][3], sb + A_SQ + o);
    }

    float oacc[8][4] = {};
    float mprev0 = -1e30f, mprev1 = -1e30f;
    float lsum0 = 0.f, lsum1 = 0.f;
    const int r0 = Q0 + w * 16 + g;
    const int r1 = r0 + 8;

    for (int kt = 0; kt < nkt; kt++) {
        if (kt > 0) { cp_wait1(); __syncthreads(); }
        const uint32_t s0 = sb + A_SK + (kt & 1) * A_STG;
        const bool diag = (kt == nkt - 1);
        // causal key-group bound (warp-uniform): groups of 16 keys
        int ngmax = 8;
        if (diag) {
            ngmax = ((Q0 & 127) >> 4) + w + 1;
            if (ngmax > 8) ngmax = 8;
        }

        // ---- S = Q K^T ----
        float s[16][4] = {};
        for (int ng = 0; ng < ngmax; ng++) {
            #pragma unroll
            for (int ks = 0; ks < 4; ks++) {
                uint32_t o = sw128((uint32_t)(ng * 16 + frow) * 128 + ks * 32 + fcol);
                uint32_t kh[4];
                ldsm_x4(kh[0], kh[1], kh[2], kh[3], s0 + o);
                #pragma unroll
                for (int hf = 0; hf < 2; hf++)
                    mma_f16(s[ng * 2 + hf], qf[ks], kh[hf], kh[hf + 2]);
            }
        }

        // ---- scale + causal mask (skipped groups get -1e30) ----
        if (diag) {
            #pragma unroll
            for (int i = 0; i < 16; i++) {
                int kk = kt * 128 + i * 8 + tc * 2;
                s[i][0] = (kk     <= r0) ? s[i][0] * 0.125f : -1e30f;
                s[i][1] = (kk + 1 <= r0) ? s[i][1] * 0.125f : -1e30f;
                s[i][2] = (kk     <= r1) ? s[i][2] * 0.125f : -1e30f;
                s[i][3] = (kk + 1 <= r1) ? s[i][3] * 0.125f : -1e30f;
            }
        } else {
            #pragma unroll
            for (int i = 0; i < 16; i++) {
                s[i][0] *= 0.125f; s[i][1] *= 0.125f;
                s[i][2] *= 0.125f; s[i][3] *= 0.125f;
            }
        }

        // ---- online softmax ----
        float mx0 = -1e30f, mx1 = -1e30f;
        #pragma unroll
        for (int i = 0; i < 16; i++) {
            mx0 = fmaxf(mx0, fmaxf(s[i][0], s[i][1]));
            mx1 = fmaxf(mx1, fmaxf(s[i][2], s[i][3]));
        }
        mx0 = fmaxf(mx0, __shfl_xor_sync(0xffffffffu, mx0, 1));
        mx0 = fmaxf(mx0, __shfl_xor_sync(0xffffffffu, mx0, 2));
        mx1 = fmaxf(mx1, __shfl_xor_sync(0xffffffffu, mx1, 1));
        mx1 = fmaxf(mx1, __shfl_xor_sync(0xffffffffu, mx1, 2));
        float mn0 = fmaxf(mprev0, mx0), mn1 = fmaxf(mprev1, mx1);
        float cf0 = __expf(mprev0 - mn0), cf1 = __expf(mprev1 - mn1);
        mprev0 = mn0; mprev1 = mn1;

        float ls0 = 0.f, ls1 = 0.f;
        #pragma unroll
        for (int i = 0; i < 16; i++) {
            s[i][0] = __expf(s[i][0] - mn0); ls0 += s[i][0];
            s[i][1] = __expf(s[i][1] - mn0); ls0 += s[i][1];
            s[i][2] = __expf(s[i][2] - mn1); ls1 += s[i][2];
            s[i][3] = __expf(s[i][3] - mn1); ls1 += s[i][3];
        }
        ls0 += __shfl_xor_sync(0xffffffffu, ls0, 1);
        ls0 += __shfl_xor_sync(0xffffffffu, ls0, 2);
        ls1 += __shfl_xor_sync(0xffffffffu, ls1, 1);
        ls1 += __shfl_xor_sync(0xffffffffu, ls1, 2);
        lsum0 = lsum0 * cf0 + ls0;
        lsum1 = lsum1 * cf1 + ls1;
        #pragma unroll
        for (int i = 0; i < 8; i++) {
            oacc[i][0] *= cf0; oacc[i][1] *= cf0;
            oacc[i][2] *= cf1; oacc[i][3] *= cf1;
        }

        // ---- O += P @ V (skipped key-groups have P == 0 exactly) ----
        const int kgmax = ngmax;
        for (int kg = 0; kg < kgmax; kg++) {
            const int h2 = kg >> 2, ks = kg & 3;
            const float* sa = s[2 * kg];
            const float* sc = s[2 * kg + 1];
            uint32_t ph[4] = {
                h2u(__floats2half2_rn(sa[0], sa[1])),
                h2u(__floats2half2_rn(sa[2], sa[3])),
                h2u(__floats2half2_rn(sc[0], sc[1])),
                h2u(__floats2half2_rn(sc[2], sc[3]))
            };
            #pragma unroll
            for (int ng = 0; ng < 4; ng++) {
                uint32_t o = sw128((uint32_t)(ng * 16 + frow) * 128 + ks * 32 + fcol)
                             + h2 * 8192;
                uint32_t v4[4];
                ldsm_x4(v4[0], v4[1], v4[2], v4[3], s0 + 16384 + o);
                #pragma unroll
                for (int hf = 0; hf < 2; hf++)
                    mma_f16(oacc[ng * 2 + hf], ph, v4[hf], v4[hf + 2]);
            }
        }

        __syncthreads();
        if (kt + 2 < nkt) issueKV(kt + 2);
        cp_commit();
    }

    // ---- epilogue: y fp16 ----
    float inv0 = 1.f / lsum0, inv1 = 1.f / lsum1;
    size_t row0 = (size_t)(b * T_SEQ + Q0 + w * 16 + g);
    #pragma unroll
    for (int i = 0; i < 8; i++) {
        int col = h * HDIM + i * 8 + tc * 2;
        *(__half2*)(y + row0 * C_EMB + col) =
            __floats2half2_rn(oacc[i][0] * inv0, oacc[i][1] * inv0);
        *(__half2*)(y + (row0 + 8) * C_EMB + col) =
            __floats2half2_rn(oacc[i][2] * inv1, oacc[i][3] * inv1);
    }
}

// ---------------- launch ----------------
extern "C" void kernel_launch(void* const* d_in, const int* in_sizes, int n_in,
                              void* d_out, int out_size)
{
    const float* x      = (const float*)d_in[0];
    const float* W_attn = (const float*)d_in[1];
    const float* b_attn = (const float*)d_in[2];
    const float* W_proj = (const float*)d_in[3];
    const float* b_proj = (const float*)d_in[4];
    float* out = (float*)d_out;

    __half *qkv, *vt, *a, *bw;
    cudaGetSymbolAddress((void**)&qkv, g_qkv);
    cudaGetSymbolAddress((void**)&vt, g_vt);
    cudaGetSymbolAddress((void**)&a, g_a);
    cudaGetSymbolAddress((void**)&bw, g_b);

    cudaFuncSetAttribute(gemm_f16<true>,  cudaFuncAttributeMaxDynamicSharedMemorySize, SM_TOTAL);
    cudaFuncSetAttribute(gemm_f16<false>, cudaFuncAttributeMaxDynamicSharedMemorySize, SM_TOTAL);
    cudaFuncSetAttribute(attn_f16, cudaFuncAttributeMaxDynamicSharedMemorySize, A_SMEM);

    const int nx = BT * C_EMB;

    conv_f16<<<nx / 4 / 256, 256>>>(x, a, nx);
    conv_t_f16<<<dim3(C3 / 32, C_EMB / 32), dim3(32, 8)>>>(W_attn, bw, C_EMB, C3);
    gemm_f16<true><<<dim3(C3 / GBN, BT / GBM), 256, SM_TOTAL>>>(
        a, bw, b_attn, nullptr, qkv, BT, C3, C_EMB);
    vtrans<<<dim3(T_SEQ / 32, HDIM / 32, BATCH * NHEAD), dim3(32, 8)>>>(qkv, vt);
    attn_f16<<<dim3(T_SEQ / 64, NHEAD, BATCH), 128, A_SMEM>>>(qkv, vt, a);
    conv_t_f16<<<dim3(C_EMB / 32, C_EMB / 32), dim3(32, 8)>>>(W_proj, bw, C_EMB, C_EMB);
    gemm_f16<false><<<dim3(C_EMB / GBN, BT / GBM), 256, SM_TOTAL>>>(
        a, bw, b_proj, out, nullptr, BT, C_EMB, C_EMB);
}

// round 9
// speedup vs baseline: 6.1033x; 1.3579x over previous
#include <cuda_runtime.h>
#include <cuda_fp16.h>
#include <cstdint>

#define BATCH   2
#define T_SEQ   2048
#define C_EMB   1024
#define NHEAD   16
#define HDIM    64
#define BT      (BATCH * T_SEQ)      // 4096
#define C3      (3 * C_EMB)          // 3072

// ---------------- scratch (device globals) ----------------
__device__ __half g_qkv[(size_t)BT * C3];                       // qkv fp16
__device__ __half g_vt[(size_t)BATCH * NHEAD * HDIM * T_SEQ];   // V^T
__device__ __half g_a[(size_t)BT * C_EMB];                      // activation (x, then y)
__device__ __half g_b[(size_t)C3 * C_EMB];                      // W^T fp16

// ---------------- PTX helpers (base-target sm_80+ only) ----------------
static __device__ __forceinline__ uint32_t smem_u32(const void* p) {
    uint32_t a;
    asm("{ .reg .u64 t; cvta.to.shared.u64 t, %1; cvt.u32.u64 %0, t; }" : "=r"(a) : "l"(p));
    return a;
}
static __device__ __forceinline__ void cp_async16(uint32_t dst, const void* src) {
    asm volatile("cp.async.cg.shared.global [%0], [%1], 16;" :: "r"(dst), "l"(src) : "memory");
}
static __device__ __forceinline__ void cp_commit() {
    asm volatile("cp.async.commit_group;" ::: "memory");
}
static __device__ __forceinline__ void cp_wait1() {
    asm volatile("cp.async.wait_group 1;" ::: "memory");
}
static __device__ __forceinline__ void cp_wait2() {
    asm volatile("cp.async.wait_group 2;" ::: "memory");
}
static __device__ __forceinline__ void ldsm_x4(uint32_t& r0, uint32_t& r1, uint32_t& r2,
                                               uint32_t& r3, uint32_t addr) {
    asm volatile("ldmatrix.sync.aligned.m8n8.x4.shared.b16 {%0,%1,%2,%3}, [%4];"
                 : "=r"(r0), "=r"(r1), "=r"(r2), "=r"(r3) : "r"(addr));
}
static __device__ __forceinline__ void mma_f16(float* d, const uint32_t* a,
                                               uint32_t b0, uint32_t b1) {
    asm volatile(
        "mma.sync.aligned.m16n8k16.row.col.f32.f16.f16.f32 "
        "{%0,%1,%2,%3}, {%4,%5,%6,%7}, {%8,%9}, {%0,%1,%2,%3};"
        : "+f"(d[0]), "+f"(d[1]), "+f"(d[2]), "+f"(d[3])
        : "r"(a[0]), "r"(a[1]), "r"(a[2]), "r"(a[3]), "r"(b0), "r"(b1));
}
static __device__ __forceinline__ uint32_t sw128(uint32_t o) {
    return o ^ ((o >> 3) & 0x70);
}
static __device__ __forceinline__ uint32_t h2u(__half2 v) {
    return *reinterpret_cast<uint32_t*>(&v);
}

// ---------------- HMMA GEMM: C = A @ B^T + bias (single fp16) ----------------
// CTA 128x128, 8 warps (4Mx2N, warp tile 32x64), BK=64, 3-stage, 2 CTAs/SM.
#define GBM 128
#define GBN 128
#define GBK 64
#define G_STG 32768
#define SM_TOTAL (3 * G_STG)

template <bool HALF_OUT>
__global__ __launch_bounds__(256, 2)
void gemm_f16(const __half* __restrict__ A, const __half* __restrict__ B,
              const float* __restrict__ bias, float* __restrict__ C,
              __half* __restrict__ Ch, int M, int N, int K)
{
    extern __shared__ char smem[];
    const uint32_t sbase = smem_u32(smem);
    const int t = threadIdx.x, lane = t & 31, w = t >> 5;
    const int wm = (w >> 1) * 32;
    const int wn = (w & 1) * 64;
    const int bm = blockIdx.y * GBM, bn = blockIdx.x * GBN;

    const int lr = t >> 3;
    const int lc = (t & 7) * 16;
    const size_t Kb = (size_t)K * 2;
    const char* pA = (const char*)A + (size_t)(bm + lr) * Kb + lc;
    const char* pB = (const char*)B + (size_t)(bn + lr) * Kb + lc;

    auto issue = [&](int c) {
        const uint32_t sb = sbase + (c % 3) * G_STG;
        const size_t go = (size_t)c * 128;
        #pragma unroll
        for (int rr = 0; rr < 4; rr++) {
            uint32_t so = sw128((uint32_t)(lr + rr * 32) * 128 + lc);
            cp_async16(sb + so,         pA + (size_t)rr * 32 * Kb + go);
            cp_async16(sb + 16384 + so, pB + (size_t)rr * 32 * Kb + go);
        }
    };

    float acc[2][8][4] = {};
    const int nc = K / GBK;

    issue(0); cp_commit();
    issue(1); cp_commit();
    issue(2); cp_commit();

    const int frow = lane & 15;
    const int fcol = (lane >> 4) * 16;

    for (int c = 0; c < nc; c++) {
        cp_wait2();
        __syncthreads();
        const uint32_t sb = sbase + (c % 3) * G_STG;

        #pragma unroll
        for (int ks = 0; ks < GBK / 16; ks++) {
            const int kb = ks * 32 + fcol;
            uint32_t af[2][4];
            #pragma unroll
            for (int mt = 0; mt < 2; mt++) {
                uint32_t o = sw128((uint32_t)(wm + mt * 16 + frow) * 128 + kb);
                ldsm_x4(af[mt][0], af[mt][1], af[mt][2], af[mt][3], sb + o);
            }
            uint32_t bf[4][4];
            #pragma unroll
            for (int nt = 0; nt < 4; nt++) {
                uint32_t o = sw128((uint32_t)(wn + nt * 16 + frow) * 128 + kb);
                ldsm_x4(bf[nt][0], bf[nt][1], bf[nt][2], bf[nt][3], sb + 16384 + o);
            }
            #pragma unroll
            for (int nt = 0; nt < 4; nt++)
                #pragma unroll
                for (int mt = 0; mt < 2; mt++)
                    #pragma unroll
                    for (int hf = 0; hf < 2; hf++)
                        mma_f16(acc[mt][nt * 2 + hf], af[mt], bf[nt][hf], bf[nt][hf + 2]);
        }
        __syncthreads();
        if (c + 3 < nc) issue(c + 3);
        cp_commit();
    }

    const int g = lane >> 2, tc = lane & 3;
    #pragma unroll
    for (int mt = 0; mt < 2; mt++) {
        const int row0 = bm + wm + mt * 16 + g;
        #pragma unroll
        for (int j = 0; j < 8; j++) {
            const int col = bn + wn + j * 8 + tc * 2;
            float b0 = bias[col], b1 = bias[col + 1];
            float* d = acc[mt][j];
            float v00 = d[0] + b0, v01 = d[1] + b1;
            float v10 = d[2] + b0, v11 = d[3] + b1;
            if constexpr (HALF_OUT) {
                *(__half2*)(Ch + (size_t)row0 * N + col) = __floats2half2_rn(v00, v01);
                *(__half2*)(Ch + (size_t)(row0 + 8) * N + col) = __floats2half2_rn(v10, v11);
            } else {
                *(float2*)(C + (size_t)row0 * N + col) = make_float2(v00, v01);
                *(float2*)(C + (size_t)(row0 + 8) * N + col) = make_float2(v10, v11);
            }
        }
    }
}

// ---------------- fp32 -> fp16 ----------------
__global__ void conv_f16(const float* __restrict__ x, __half* __restrict__ h, int n)
{
    int i = (blockIdx.x * blockDim.x + threadIdx.x) * 4;
    if (i >= n) return;
    float4 v = *(const float4*)(x + i);
    *(__half2*)(h + i)     = __floats2half2_rn(v.x, v.y);
    *(__half2*)(h + i + 2) = __floats2half2_rn(v.z, v.w);
}

// ---------------- W [K,N] -> W^T [N,K] fp16 ----------------
__global__ void conv_t_f16(const float* __restrict__ W, __half* __restrict__ th,
                           int K, int N)
{
    __shared__ float tile[32][33];
    const int n0 = blockIdx.x * 32, k0 = blockIdx.y * 32;
    const int tx = threadIdx.x, ty = threadIdx.y;
    #pragma unroll
    for (int j = 0; j < 32; j += 8)
        tile[ty + j][tx] = W[(size_t)(k0 + ty + j) * N + n0 + tx];
    __syncthreads();
    #pragma unroll
    for (int j = 0; j < 32; j += 8)
        th[(size_t)(n0 + ty + j) * K + k0 + tx] = __float2half(tile[tx][ty + j]);
}

// ---------------- V part of qkv -> V^T [b][h][d][T] ----------------
__global__ void vtrans(const __half* __restrict__ qh, __half* __restrict__ vt)
{
    __shared__ __half tile[32][33];
    const int bh = blockIdx.z, b = bh >> 4, h = bh & 15;
    const int t0 = blockIdx.x * 32, d0 = blockIdx.y * 32;
    const int tx = threadIdx.x, ty = threadIdx.y;
    #pragma unroll
    for (int j = 0; j < 32; j += 8)
        tile[ty + j][tx] = qh[(size_t)(b * T_SEQ + t0 + ty + j) * C3 + 2 * C_EMB + h * HDIM + d0 + tx];
    __syncthreads();
    #pragma unroll
    for (int j = 0; j < 32; j += 8)
        vt[((size_t)(b * NHEAD + h) * HDIM + d0 + ty + j) * T_SEQ + t0 + tx] = tile[tx][ty + j];
}

// ---------------- HMMA flash attention (causal), single fp16 ----------------
// CTA: 64 q rows x (b,h); 4 warps x 16 rows; 128-key tiles, 2-stage pipeline.
// Causal-skip loops are fully unrolled with predicates so the S register
// array keeps STATIC indexing (no local-memory demotion).
#define A_SQ  0
#define A_SK  8192
#define A_STG 32768
#define A_SMEM (A_SK + 2 * A_STG)   // 73728

__global__ __launch_bounds__(128, 3)
void attn_f16(const __half* __restrict__ qkv, const __half* __restrict__ vt,
              __half* __restrict__ y)
{
    extern __shared__ char smem[];
    const uint32_t sb = smem_u32(smem);
    const int t = threadIdx.x, lane = t & 31, w = t >> 5;   // w in 0..3
    const int qb = gridDim.x - 1 - blockIdx.x;   // heavy blocks first
    const int h = blockIdx.y, b = blockIdx.z;
    const int Q0 = qb * 64;
    const int nkt = (Q0 >> 7) + 1;               // 128-key tiles

    const int lr = t >> 3;          // 0..15
    const int lc = (t & 7) * 16;
    const char* qb8 = (const char*)qkv;
    const char* vb8 = (const char*)vt;

    auto issueQ = [&]() {
        #pragma unroll
        for (int rr = 0; rr < 4; rr++) {
            int row = lr + rr * 16;
            size_t g = ((size_t)(b * T_SEQ + Q0 + row) * C3 + h * HDIM) * 2 + lc;
            cp_async16(sb + A_SQ + sw128((uint32_t)row * 128 + lc), qb8 + g);
        }
    };
    auto issueKV = [&](int kt) {
        uint32_t s0 = sb + A_SK + (kt & 1) * A_STG;
        #pragma unroll
        for (int rr = 0; rr < 8; rr++) {
            int row = lr + rr * 16;
            uint32_t so = sw128((uint32_t)row * 128 + lc);
            size_t gk = ((size_t)(b * T_SEQ + kt * 128 + row) * C3 + C_EMB + h * HDIM) * 2 + lc;
            cp_async16(s0 + so, qb8 + gk);
        }
        #pragma unroll
        for (int j = 0; j < 2; j++) {
            #pragma unroll
            for (int rr = 0; rr < 4; rr++) {
                int row = lr + rr * 16;
                uint32_t so = sw128((uint32_t)row * 128 + lc) + j * 8192;
                size_t gv = (((size_t)(b * NHEAD + h) * HDIM + row) * T_SEQ
                             + kt * 128 + j * 64) * 2 + lc;
                cp_async16(s0 + 16384 + so, vb8 + gv);
            }
        }
    };

    issueQ(); issueKV(0); cp_commit();
    if (nkt > 1) issueKV(1);
    cp_commit();

    const int frow = lane & 15;
    const int fcol = (lane >> 4) * 16;
    const int g = lane >> 2, tc = lane & 3;

    cp_wait1();
    __syncthreads();

    uint32_t qf[4][4];
    #pragma unroll
    for (int ks = 0; ks < 4; ks++) {
        uint32_t o = sw128((uint32_t)(w * 16 + frow) * 128 + ks * 32 + fcol);
        ldsm_x4(qf[ks][0], qf[ks][1], qf[ks][2], qf[ks][3], sb + A_SQ + o);
    }

    float oacc[8][4] = {};
    float mprev0 = -1e30f, mprev1 = -1e30f;
    float lsum0 = 0.f, lsum1 = 0.f;
    const int r0 = Q0 + w * 16 + g;
    const int r1 = r0 + 8;

    for (int kt = 0; kt < nkt; kt++) {
        if (kt > 0) { cp_wait1(); __syncthreads(); }
        const uint32_t s0 = sb + A_SK + (kt & 1) * A_STG;
        const bool diag = (kt == nkt - 1);
        // causal key-group bound (warp-uniform): groups of 16 keys
        int ngmax = 8;
        if (diag) {
            ngmax = ((Q0 & 127) >> 4) + w + 1;
            if (ngmax > 8) ngmax = 8;
        }

        // ---- S = Q K^T  (STATIC unroll + predicate: keeps s[] in registers) ----
        float s[16][4] = {};
        #pragma unroll
        for (int ng = 0; ng < 8; ng++) {
            if (ng < ngmax) {
                #pragma unroll
                for (int ks = 0; ks < 4; ks++) {
                    uint32_t o = sw128((uint32_t)(ng * 16 + frow) * 128 + ks * 32 + fcol);
                    uint32_t kh[4];
                    ldsm_x4(kh[0], kh[1], kh[2], kh[3], s0 + o);
                    #pragma unroll
                    for (int hf = 0; hf < 2; hf++)
                        mma_f16(s[ng * 2 + hf], qf[ks], kh[hf], kh[hf + 2]);
                }
            }
        }

        // ---- scale + causal mask (skipped groups get -1e30) ----
        if (diag) {
            #pragma unroll
            for (int i = 0; i < 16; i++) {
                int kk = kt * 128 + i * 8 + tc * 2;
                s[i][0] = (kk     <= r0) ? s[i][0] * 0.125f : -1e30f;
                s[i][1] = (kk + 1 <= r0) ? s[i][1] * 0.125f : -1e30f;
                s[i][2] = (kk     <= r1) ? s[i][2] * 0.125f : -1e30f;
                s[i][3] = (kk + 1 <= r1) ? s[i][3] * 0.125f : -1e30f;
            }
        } else {
            #pragma unroll
            for (int i = 0; i < 16; i++) {
                s[i][0] *= 0.125f; s[i][1] *= 0.125f;
                s[i][2] *= 0.125f; s[i][3] *= 0.125f;
            }
        }

        // ---- online softmax ----
        float mx0 = -1e30f, mx1 = -1e30f;
        #pragma unroll
        for (int i = 0; i < 16; i++) {
            mx0 = fmaxf(mx0, fmaxf(s[i][0], s[i][1]));
            mx1 = fmaxf(mx1, fmaxf(s[i][2], s[i][3]));
        }
        mx0 = fmaxf(mx0, __shfl_xor_sync(0xffffffffu, mx0, 1));
        mx0 = fmaxf(mx0, __shfl_xor_sync(0xffffffffu, mx0, 2));
        mx1 = fmaxf(mx1, __shfl_xor_sync(0xffffffffu, mx1, 1));
        mx1 = fmaxf(mx1, __shfl_xor_sync(0xffffffffu, mx1, 2));
        float mn0 = fmaxf(mprev0, mx0), mn1 = fmaxf(mprev1, mx1);
        float cf0 = __expf(mprev0 - mn0), cf1 = __expf(mprev1 - mn1);
        mprev0 = mn0; mprev1 = mn1;

        float ls0 = 0.f, ls1 = 0.f;
        #pragma unroll
        for (int i = 0; i < 16; i++) {
            s[i][0] = __expf(s[i][0] - mn0); ls0 += s[i][0];
            s[i][1] = __expf(s[i][1] - mn0); ls0 += s[i][1];
            s[i][2] = __expf(s[i][2] - mn1); ls1 += s[i][2];
            s[i][3] = __expf(s[i][3] - mn1); ls1 += s[i][3];
        }
        ls0 += __shfl_xor_sync(0xffffffffu, ls0, 1);
        ls0 += __shfl_xor_sync(0xffffffffu, ls0, 2);
        ls1 += __shfl_xor_sync(0xffffffffu, ls1, 1);
        ls1 += __shfl_xor_sync(0xffffffffu, ls1, 2);
        lsum0 = lsum0 * cf0 + ls0;
        lsum1 = lsum1 * cf1 + ls1;
        #pragma unroll
        for (int i = 0; i < 8; i++) {
            oacc[i][0] *= cf0; oacc[i][1] *= cf0;
            oacc[i][2] *= cf1; oacc[i][3] *= cf1;
        }

        // ---- O += P @ V  (STATIC unroll + predicate; skipped groups P == 0) ----
        #pragma unroll
        for (int kg = 0; kg < 8; kg++) {
            if (kg < ngmax) {
                const int h2 = kg >> 2, ks = kg & 3;
                const float* sa = s[2 * kg];
                const float* sc = s[2 * kg + 1];
                uint32_t ph[4] = {
                    h2u(__floats2half2_rn(sa[0], sa[1])),
                    h2u(__floats2half2_rn(sa[2], sa[3])),
                    h2u(__floats2half2_rn(sc[0], sc[1])),
                    h2u(__floats2half2_rn(sc[2], sc[3]))
                };
                #pragma unroll
                for (int ng = 0; ng < 4; ng++) {
                    uint32_t o = sw128((uint32_t)(ng * 16 + frow) * 128 + ks * 32 + fcol)
                                 + h2 * 8192;
                    uint32_t v4[4];
                    ldsm_x4(v4[0], v4[1], v4[2], v4[3], s0 + 16384 + o);
                    #pragma unroll
                    for (int hf = 0; hf < 2; hf++)
                        mma_f16(oacc[ng * 2 + hf], ph, v4[hf], v4[hf + 2]);
                }
            }
        }

        __syncthreads();
        if (kt + 2 < nkt) issueKV(kt + 2);
        cp_commit();
    }

    // ---- epilogue: y fp16 ----
    float inv0 = 1.f / lsum0, inv1 = 1.f / lsum1;
    size_t row0 = (size_t)(b * T_SEQ + Q0 + w * 16 + g);
    #pragma unroll
    for (int i = 0; i < 8; i++) {
        int col = h * HDIM + i * 8 + tc * 2;
        *(__half2*)(y + row0 * C_EMB + col) =
            __floats2half2_rn(oacc[i][0] * inv0, oacc[i][1] * inv0);
        *(__half2*)(y + (row0 + 8) * C_EMB + col) =
            __floats2half2_rn(oacc[i][2] * inv1, oacc[i][3] * inv1);
    }
}

// ---------------- launch ----------------
extern "C" void kernel_launch(void* const* d_in, const int* in_sizes, int n_in,
                              void* d_out, int out_size)
{
    const float* x      = (const float*)d_in[0];
    const float* W_attn = (const float*)d_in[1];
    const float* b_attn = (const float*)d_in[2];
    const float* W_proj = (const float*)d_in[3];
    const float* b_proj = (const float*)d_in[4];
    float* out = (float*)d_out;

    __half *qkv, *vt, *a, *bw;
    cudaGetSymbolAddress((void**)&qkv, g_qkv);
    cudaGetSymbolAddress((void**)&vt, g_vt);
    cudaGetSymbolAddress((void**)&a, g_a);
    cudaGetSymbolAddress((void**)&bw, g_b);

    cudaFuncSetAttribute(gemm_f16<true>,  cudaFuncAttributeMaxDynamicSharedMemorySize, SM_TOTAL);
    cudaFuncSetAttribute(gemm_f16<false>, cudaFuncAttributeMaxDynamicSharedMemorySize, SM_TOTAL);
    cudaFuncSetAttribute(attn_f16, cudaFuncAttributeMaxDynamicSharedMemorySize, A_SMEM);

    const int nx = BT * C_EMB;

    conv_f16<<<nx / 4 / 256, 256>>>(x, a, nx);
    conv_t_f16<<<dim3(C3 / 32, C_EMB / 32), dim3(32, 8)>>>(W_attn, bw, C_EMB, C3);
    gemm_f16<true><<<dim3(C3 / GBN, BT / GBM), 256, SM_TOTAL>>>(
        a, bw, b_attn, nullptr, qkv, BT, C3, C_EMB);
    vtrans<<<dim3(T_SEQ / 32, HDIM / 32, BATCH * NHEAD), dim3(32, 8)>>>(qkv, vt);
    attn_f16<<<dim3(T_SEQ / 64, NHEAD, BATCH), 128, A_SMEM>>>(qkv, vt, a);
    conv_t_f16<<<dim3(C_EMB / 32, C_EMB / 32), dim3(32, 8)>>>(W_proj, bw, C_EMB, C_EMB);
    gemm_f16<false><<<dim3(C_EMB / GBN, BT / GBM), 256, SM_TOTAL>>>(
        a, bw, b_proj, out, nullptr, BT, C_EMB, C_EMB);
}

// round 10
// speedup vs baseline: 6.4279x; 1.0532x over previous
#include <cuda_runtime.h>
#include <cuda_fp16.h>
#include <cstdint>

#define BATCH   2
#define T_SEQ   2048
#define C_EMB   1024
#define NHEAD   16
#define HDIM    64
#define BT      (BATCH * T_SEQ)      // 4096
#define C3      (3 * C_EMB)          // 3072

// 0.125 * log2(e)  — folds softmax scale into the exp2 domain
#define SCALE2  0.18033688011112043f

// ---------------- scratch (device globals) ----------------
__device__ __half g_qkv[(size_t)BT * C3];                       // qkv fp16
__device__ __half g_vt[(size_t)BATCH * NHEAD * HDIM * T_SEQ];   // V^T
__device__ __half g_a[(size_t)BT * C_EMB];                      // activation (x, then y)
__device__ __half g_b[(size_t)C3 * C_EMB];                      // W_attn^T fp16
__device__ __half g_b2[(size_t)C_EMB * C_EMB];                  // W_proj^T fp16

// ---------------- PTX helpers (base-target sm_80+ only) ----------------
static __device__ __forceinline__ uint32_t smem_u32(const void* p) {
    uint32_t a;
    asm("{ .reg .u64 t; cvta.to.shared.u64 t, %1; cvt.u32.u64 %0, t; }" : "=r"(a) : "l"(p));
    return a;
}
static __device__ __forceinline__ void cp_async16(uint32_t dst, const void* src) {
    asm volatile("cp.async.cg.shared.global [%0], [%1], 16;" :: "r"(dst), "l"(src) : "memory");
}
static __device__ __forceinline__ void cp_commit() {
    asm volatile("cp.async.commit_group;" ::: "memory");
}
static __device__ __forceinline__ void cp_wait1() {
    asm volatile("cp.async.wait_group 1;" ::: "memory");
}
static __device__ __forceinline__ void cp_wait2() {
    asm volatile("cp.async.wait_group 2;" ::: "memory");
}
static __device__ __forceinline__ void ldsm_x4(uint32_t& r0, uint32_t& r1, uint32_t& r2,
                                               uint32_t& r3, uint32_t addr) {
    asm volatile("ldmatrix.sync.aligned.m8n8.x4.shared.b16 {%0,%1,%2,%3}, [%4];"
                 : "=r"(r0), "=r"(r1), "=r"(r2), "=r"(r3) : "r"(addr));
}
static __device__ __forceinline__ void mma_f16(float* d, const uint32_t* a,
                                               uint32_t b0, uint32_t b1) {
    asm volatile(
        "mma.sync.aligned.m16n8k16.row.col.f32.f16.f16.f32 "
        "{%0,%1,%2,%3}, {%4,%5,%6,%7}, {%8,%9}, {%0,%1,%2,%3};"
        : "+f"(d[0]), "+f"(d[1]), "+f"(d[2]), "+f"(d[3])
        : "r"(a[0]), "r"(a[1]), "r"(a[2]), "r"(a[3]), "r"(b0), "r"(b1));
}
static __device__ __forceinline__ float ex2f(float x) {
    float r;
    asm("ex2.approx.f32 %0, %1;" : "=f"(r) : "f"(x));
    return r;
}
static __device__ __forceinline__ uint32_t sw128(uint32_t o) {
    return o ^ ((o >> 3) & 0x70);
}
static __device__ __forceinline__ uint32_t h2u(__half2 v) {
    return *reinterpret_cast<uint32_t*>(&v);
}

// ---------------- HMMA GEMM: C = A @ B^T + bias (single fp16) ----------------
// CTA 128x128, 8 warps (4Mx2N, warp tile 32x64), BK=64, 3-stage, 2 CTAs/SM.
#define GBM 128
#define GBN 128
#define GBK 64
#define G_STG 32768
#define SM_TOTAL (3 * G_STG)

template <bool HALF_OUT>
__global__ __launch_bounds__(256, 2)
void gemm_f16(const __half* __restrict__ A, const __half* __restrict__ B,
              const float* __restrict__ bias, float* __restrict__ C,
              __half* __restrict__ Ch, int M, int N, int K)
{
    extern __shared__ char smem[];
    const uint32_t sbase = smem_u32(smem);
    const int t = threadIdx.x, lane = t & 31, w = t >> 5;
    const int wm = (w >> 1) * 32;
    const int wn = (w & 1) * 64;
    const int bm = blockIdx.y * GBM, bn = blockIdx.x * GBN;

    const int lr = t >> 3;
    const int lc = (t & 7) * 16;
    const size_t Kb = (size_t)K * 2;
    const char* pA = (const char*)A + (size_t)(bm + lr) * Kb + lc;
    const char* pB = (const char*)B + (size_t)(bn + lr) * Kb + lc;

    auto issue = [&](int c) {
        const uint32_t sb = sbase + (c % 3) * G_STG;
        const size_t go = (size_t)c * 128;
        #pragma unroll
        for (int rr = 0; rr < 4; rr++) {
            uint32_t so = sw128((uint32_t)(lr + rr * 32) * 128 + lc);
            cp_async16(sb + so,         pA + (size_t)rr * 32 * Kb + go);
            cp_async16(sb + 16384 + so, pB + (size_t)rr * 32 * Kb + go);
        }
    };

    float acc[2][8][4] = {};
    const int nc = K / GBK;

    issue(0); cp_commit();
    issue(1); cp_commit();
    issue(2); cp_commit();

    const int frow = lane & 15;
    const int fcol = (lane >> 4) * 16;

    for (int c = 0; c < nc; c++) {
        cp_wait2();
        __syncthreads();
        const uint32_t sb = sbase + (c % 3) * G_STG;

        #pragma unroll
        for (int ks = 0; ks < GBK / 16; ks++) {
            const int kb = ks * 32 + fcol;
            uint32_t af[2][4];
            #pragma unroll
            for (int mt = 0; mt < 2; mt++) {
                uint32_t o = sw128((uint32_t)(wm + mt * 16 + frow) * 128 + kb);
                ldsm_x4(af[mt][0], af[mt][1], af[mt][2], af[mt][3], sb + o);
            }
            uint32_t bf[4][4];
            #pragma unroll
            for (int nt = 0; nt < 4; nt++) {
                uint32_t o = sw128((uint32_t)(wn + nt * 16 + frow) * 128 + kb);
                ldsm_x4(bf[nt][0], bf[nt][1], bf[nt][2], bf[nt][3], sb + 16384 + o);
            }
            #pragma unroll
            for (int nt = 0; nt < 4; nt++)
                #pragma unroll
                for (int mt = 0; mt < 2; mt++)
                    #pragma unroll
                    for (int hf = 0; hf < 2; hf++)
                        mma_f16(acc[mt][nt * 2 + hf], af[mt], bf[nt][hf], bf[nt][hf + 2]);
        }
        __syncthreads();
        if (c + 3 < nc) issue(c + 3);
        cp_commit();
    }

    const int g = lane >> 2, tc = lane & 3;
    #pragma unroll
    for (int mt = 0; mt < 2; mt++) {
        const int row0 = bm + wm + mt * 16 + g;
        #pragma unroll
        for (int j = 0; j < 8; j++) {
            const int col = bn + wn + j * 8 + tc * 2;
            float b0 = bias[col], b1 = bias[col + 1];
            float* d = acc[mt][j];
            float v00 = d[0] + b0, v01 = d[1] + b1;
            float v10 = d[2] + b0, v11 = d[3] + b1;
            if constexpr (HALF_OUT) {
                *(__half2*)(Ch + (size_t)row0 * N + col) = __floats2half2_rn(v00, v01);
                *(__half2*)(Ch + (size_t)(row0 + 8) * N + col) = __floats2half2_rn(v10, v11);
            } else {
                *(float2*)(C + (size_t)row0 * N + col) = make_float2(v00, v01);
                *(float2*)(C + (size_t)(row0 + 8) * N + col) = make_float2(v10, v11);
            }
        }
    }
}

// ---------------- fp32 -> fp16 ----------------
__global__ void conv_f16(const float* __restrict__ x, __half* __restrict__ h, int n)
{
    int i = (blockIdx.x * blockDim.x + threadIdx.x) * 4;
    if (i >= n) return;
    float4 v = *(const float4*)(x + i);
    *(__half2*)(h + i)     = __floats2half2_rn(v.x, v.y);
    *(__half2*)(h + i + 2) = __floats2half2_rn(v.z, v.w);
}

// ---------------- both weight transposes in ONE launch ----------------
// blockIdx.x < 96: W_attn [1024,3072] -> g_b;  else: W_proj [1024,1024] -> g_b2
__global__ void conv_t_both(const float* __restrict__ Wa, const float* __restrict__ Wp,
                            __half* __restrict__ ba, __half* __restrict__ bp)
{
    __shared__ float tile[32][33];
    const int bx = blockIdx.x;
    const float* W;
    __half* outp;
    int N, n0;
    if (bx < 96) { W = Wa; outp = ba; N = C3;    n0 = bx * 32; }
    else         { W = Wp; outp = bp; N = C_EMB; n0 = (bx - 96) * 32; }
    const int k0 = blockIdx.y * 32;
    const int tx = threadIdx.x, ty = threadIdx.y;
    #pragma unroll
    for (int j = 0; j < 32; j += 8)
        tile[ty + j][tx] = W[(size_t)(k0 + ty + j) * N + n0 + tx];
    __syncthreads();
    #pragma unroll
    for (int j = 0; j < 32; j += 8)
        outp[(size_t)(n0 + ty + j) * C_EMB + k0 + tx] = __float2half(tile[tx][ty + j]);
}

// ---------------- V part of qkv -> V^T [b][h][d][T] ----------------
__global__ void vtrans(const __half* __restrict__ qh, __half* __restrict__ vt)
{
    __shared__ __half tile[32][33];
    const int bh = blockIdx.z, b = bh >> 4, h = bh & 15;
    const int t0 = blockIdx.x * 32, d0 = blockIdx.y * 32;
    const int tx = threadIdx.x, ty = threadIdx.y;
    #pragma unroll
    for (int j = 0; j < 32; j += 8)
        tile[ty + j][tx] = qh[(size_t)(b * T_SEQ + t0 + ty + j) * C3 + 2 * C_EMB + h * HDIM + d0 + tx];
    __syncthreads();
    #pragma unroll
    for (int j = 0; j < 32; j += 8)
        vt[((size_t)(b * NHEAD + h) * HDIM + d0 + ty + j) * T_SEQ + t0 + tx] = tile[tx][ty + j];
}

// ---------------- HMMA flash attention (causal), single fp16 ----------------
// CTA: 64 q rows x (b,h); 4 warps x 16 rows; 128-key tiles, 2-stage pipeline.
// Row-sum computed by the tensor core via a constant ones-row block (2 KB).
// Softmax scale folded into exp2 domain (ex2.approx).
#define A_SQ   0
#define A_ONES 8192
#define A_SK   10240
#define A_STG  32768
#define A_SMEM (A_SK + 2 * A_STG)   // 75776 -> 3 CTAs/SM

__global__ __launch_bounds__(128, 3)
void attn_f16(const __half* __restrict__ qkv, const __half* __restrict__ vt,
              __half* __restrict__ y)
{
    extern __shared__ char smem[];
    const uint32_t sb = smem_u32(smem);
    const int t = threadIdx.x, lane = t & 31, w = t >> 5;   // w in 0..3
    const int qb = gridDim.x - 1 - blockIdx.x;   // heavy blocks first
    const int h = blockIdx.y, b = blockIdx.z;
    const int Q0 = qb * 64;
    const int nkt = (Q0 >> 7) + 1;               // 128-key tiles

    const int lr = t >> 3;          // 0..15
    const int lc = (t & 7) * 16;
    const char* qb8 = (const char*)qkv;
    const char* vb8 = (const char*)vt;

    // init ones block (row 0 of the 16x128B region = 1.0h, rest 0)
    {
        uint32_t v = (t < 8) ? 0x3C003C00u : 0u;
        *(uint4*)(smem + A_ONES + t * 16) = make_uint4(v, v, v, v);
    }

    auto issueQ = [&]() {
        #pragma unroll
        for (int rr = 0; rr < 4; rr++) {
            int row = lr + rr * 16;
            size_t g = ((size_t)(b * T_SEQ + Q0 + row) * C3 + h * HDIM) * 2 + lc;
            cp_async16(sb + A_SQ + sw128((uint32_t)row * 128 + lc), qb8 + g);
        }
    };
    auto issueKV = [&](int kt) {
        uint32_t s0 = sb + A_SK + (kt & 1) * A_STG;
        #pragma unroll
        for (int rr = 0; rr < 8; rr++) {
            int row = lr + rr * 16;
            uint32_t so = sw128((uint32_t)row * 128 + lc);
            size_t gk = ((size_t)(b * T_SEQ + kt * 128 + row) * C3 + C_EMB + h * HDIM) * 2 + lc;
            cp_async16(s0 + so, qb8 + gk);
        }
        #pragma unroll
        for (int j = 0; j < 2; j++) {
            #pragma unroll
            for (int rr = 0; rr < 4; rr++) {
                int row = lr + rr * 16;
                uint32_t so = sw128((uint32_t)row * 128 + lc) + j * 8192;
                size_t gv = (((size_t)(b * NHEAD + h) * HDIM + row) * T_SEQ
                             + kt * 128 + j * 64) * 2 + lc;
                cp_async16(s0 + 16384 + so, vb8 + gv);
            }
        }
    };

    issueQ(); issueKV(0); cp_commit();
    if (nkt > 1) issueKV(1);
    cp_commit();

    const int frow = lane & 15;
    const int fcol = (lane >> 4) * 16;
    const int g = lane >> 2, tc = lane & 3;

    cp_wait1();
    __syncthreads();

    uint32_t qf[4][4];
    #pragma unroll
    for (int ks = 0; ks < 4; ks++) {
        uint32_t o = sw128((uint32_t)(w * 16 + frow) * 128 + ks * 32 + fcol);
        ldsm_x4(qf[ks][0], qf[ks][1], qf[ks][2], qf[ks][3], sb + A_SQ + o);
    }
    // ones B-fragment (constant across all k-tiles; hoisted)
    uint32_t of[4];
    ldsm_x4(of[0], of[1], of[2], of[3], sb + A_ONES + sw128((uint32_t)frow * 128 + fcol));

    float oacc[8][4] = {};
    float sumacc[4] = {};               // col 64 = running row-sum of P
    float mprev0 = -1e30f, mprev1 = -1e30f;
    const int r0 = Q0 + w * 16 + g;
    const int r1 = r0 + 8;

    for (int kt = 0; kt < nkt; kt++) {
        if (kt > 0) { cp_wait1(); __syncthreads(); }
        const uint32_t s0 = sb + A_SK + (kt & 1) * A_STG;
        const bool diag = (kt == nkt - 1);
        int ngmax = 8;
        if (diag) {
            ngmax = ((Q0 & 127) >> 4) + w + 1;
            if (ngmax > 8) ngmax = 8;
        }

        // ---- S = Q K^T  (static unroll + predicate) ----
        float s[16][4] = {};
        #pragma unroll
        for (int ng = 0; ng < 8; ng++) {
            if (ng < ngmax) {
                #pragma unroll
                for (int ks = 0; ks < 4; ks++) {
                    uint32_t o = sw128((uint32_t)(ng * 16 + frow) * 128 + ks * 32 + fcol);
                    uint32_t kh[4];
                    ldsm_x4(kh[0], kh[1], kh[2], kh[3], s0 + o);
                    #pragma unroll
                    for (int hf = 0; hf < 2; hf++)
                        mma_f16(s[ng * 2 + hf], qf[ks], kh[hf], kh[hf + 2]);
                }
            }
        }

        // ---- scale into exp2 domain + causal mask ----
        if (diag) {
            #pragma unroll
            for (int i = 0; i < 16; i++) {
                int kk = kt * 128 + i * 8 + tc * 2;
                s[i][0] = (kk     <= r0) ? s[i][0] * SCALE2 : -1e30f;
                s[i][1] = (kk + 1 <= r0) ? s[i][1] * SCALE2 : -1e30f;
                s[i][2] = (kk     <= r1) ? s[i][2] * SCALE2 : -1e30f;
                s[i][3] = (kk + 1 <= r1) ? s[i][3] * SCALE2 : -1e30f;
            }
        } else {
            #pragma unroll
            for (int i = 0; i < 16; i++) {
                s[i][0] *= SCALE2; s[i][1] *= SCALE2;
                s[i][2] *= SCALE2; s[i][3] *= SCALE2;
            }
        }

        // ---- online softmax (exp2 domain; sum via tensor core) ----
        float mx0 = -1e30f, mx1 = -1e30f;
        #pragma unroll
        for (int i = 0; i < 16; i++) {
            mx0 = fmaxf(mx0, fmaxf(s[i][0], s[i][1]));
            mx1 = fmaxf(mx1, fmaxf(s[i][2], s[i][3]));
        }
        mx0 = fmaxf(mx0, __shfl_xor_sync(0xffffffffu, mx0, 1));
        mx0 = fmaxf(mx0, __shfl_xor_sync(0xffffffffu, mx0, 2));
        mx1 = fmaxf(mx1, __shfl_xor_sync(0xffffffffu, mx1, 1));
        mx1 = fmaxf(mx1, __shfl_xor_sync(0xffffffffu, mx1, 2));
        float mn0 = fmaxf(mprev0, mx0), mn1 = fmaxf(mprev1, mx1);
        float cf0 = ex2f(mprev0 - mn0), cf1 = ex2f(mprev1 - mn1);
        mprev0 = mn0; mprev1 = mn1;

        #pragma unroll
        for (int i = 0; i < 16; i++) {
            s[i][0] = ex2f(s[i][0] - mn0);
            s[i][1] = ex2f(s[i][1] - mn0);
            s[i][2] = ex2f(s[i][2] - mn1);
            s[i][3] = ex2f(s[i][3] - mn1);
        }
        #pragma unroll
        for (int i = 0; i < 8; i++) {
            oacc[i][0] *= cf0; oacc[i][1] *= cf0;
            oacc[i][2] *= cf1; oacc[i][3] *= cf1;
        }
        sumacc[0] *= cf0; sumacc[1] *= cf0;
        sumacc[2] *= cf1; sumacc[3] *= cf1;

        // ---- O += P @ V; sum += P @ ones  (static unroll + predicate) ----
        #pragma unroll
        for (int kg = 0; kg < 8; kg++) {
            if (kg < ngmax) {
                const int h2 = kg >> 2, ks = kg & 3;
                const float* sa = s[2 * kg];
                const float* sc = s[2 * kg + 1];
                uint32_t ph[4] = {
                    h2u(__floats2half2_rn(sa[0], sa[1])),
                    h2u(__floats2half2_rn(sa[2], sa[3])),
                    h2u(__floats2half2_rn(sc[0], sc[1])),
                    h2u(__floats2half2_rn(sc[2], sc[3]))
                };
                #pragma unroll
                for (int ng = 0; ng < 4; ng++) {
                    uint32_t o = sw128((uint32_t)(ng * 16 + frow) * 128 + ks * 32 + fcol)
                                 + h2 * 8192;
                    uint32_t v4[4];
                    ldsm_x4(v4[0], v4[1], v4[2], v4[3], s0 + 16384 + o);
                    #pragma unroll
                    for (int hf = 0; hf < 2; hf++)
                        mma_f16(oacc[ng * 2 + hf], ph, v4[hf], v4[hf + 2]);
                }
                mma_f16(sumacc, ph, of[0], of[2]);   // row-sum column
            }
        }

        __syncthreads();
        if (kt + 2 < nkt) issueKV(kt + 2);
        cp_commit();
    }

    // ---- epilogue: broadcast row-sum from tc==0 lane, divide, store fp16 ----
    float sum0 = __shfl_sync(0xffffffffu, sumacc[0], lane & ~3);
    float sum1 = __shfl_sync(0xffffffffu, sumacc[2], lane & ~3);
    float inv0 = 1.f / sum0, inv1 = 1.f / sum1;
    size_t row0 = (size_t)(b * T_SEQ + Q0 + w * 16 + g);
    #pragma unroll
    for (int i = 0; i < 8; i++) {
        int col = h * HDIM + i * 8 + tc * 2;
        *(__half2*)(y + row0 * C_EMB + col) =
            __floats2half2_rn(oacc[i][0] * inv0, oacc[i][1] * inv0);
        *(__half2*)(y + (row0 + 8) * C_EMB + col) =
            __floats2half2_rn(oacc[i][2] * inv1, oacc[i][3] * inv1);
    }
}

// ---------------- launch ----------------
extern "C" void kernel_launch(void* const* d_in, const int* in_sizes, int n_in,
                              void* d_out, int out_size)
{
    const float* x      = (const float*)d_in[0];
    const float* W_attn = (const float*)d_in[1];
    const float* b_attn = (const float*)d_in[2];
    const float* W_proj = (const float*)d_in[3];
    const float* b_proj = (const float*)d_in[4];
    float* out = (float*)d_out;

    __half *qkv, *vt, *a, *bw, *bw2;
    cudaGetSymbolAddress((void**)&qkv, g_qkv);
    cudaGetSymbolAddress((void**)&vt, g_vt);
    cudaGetSymbolAddress((void**)&a, g_a);
    cudaGetSymbolAddress((void**)&bw, g_b);
    cudaGetSymbolAddress((void**)&bw2, g_b2);

    cudaFuncSetAttribute(gemm_f16<true>,  cudaFuncAttributeMaxDynamicSharedMemorySize, SM_TOTAL);
    cudaFuncSetAttribute(gemm_f16<false>, cudaFuncAttributeMaxDynamicSharedMemorySize, SM_TOTAL);
    cudaFuncSetAttribute(attn_f16, cudaFuncAttributeMaxDynamicSharedMemorySize, A_SMEM);

    const int nx = BT * C_EMB;

    conv_f16<<<nx / 4 / 256, 256>>>(x, a, nx);
    conv_t_both<<<dim3(96 + 32, C_EMB / 32), dim3(32, 8)>>>(W_attn, W_proj, bw, bw2);
    gemm_f16<true><<<dim3(C3 / GBN, BT / GBM), 256, SM_TOTAL>>>(
        a, bw, b_attn, nullptr, qkv, BT, C3, C_EMB);
    vtrans<<<dim3(T_SEQ / 32, HDIM / 32, BATCH * NHEAD), dim3(32, 8)>>>(qkv, vt);
    attn_f16<<<dim3(T_SEQ / 64, NHEAD, BATCH), 128, A_SMEM>>>(qkv, vt, a);
    gemm_f16<false><<<dim3(C_EMB / GBN, BT / GBM), 256, SM_TOTAL>>>(
        a, bw2, b_proj, out, nullptr, BT, C_EMB, C_EMB);
}

// round 11
// speedup vs baseline: 7.0572x; 1.0979x over previous
#include <cuda_runtime.h>
#include <cuda_fp16.h>
#include <cstdint>

#define BATCH   2
#define T_SEQ   2048
#define C_EMB   1024
#define NHEAD   16
#define HDIM    64
#define BT      (BATCH * T_SEQ)      // 4096
#define C3      (3 * C_EMB)          // 3072

// 0.125 * log2(e)  — folds softmax scale into the exp2 domain
#define SCALE2  0.18033688011112043f

// ---------------- scratch (device globals) ----------------
__device__ __half g_qkv[(size_t)BT * C3];                       // qkv fp16
__device__ __half g_vt[(size_t)BATCH * NHEAD * HDIM * T_SEQ];   // V^T
__device__ __half g_a[(size_t)BT * C_EMB];                      // activation (x, then y)
__device__ __half g_b[(size_t)C3 * C_EMB];                      // W_attn^T fp16
__device__ __half g_b2[(size_t)C_EMB * C_EMB];                  // W_proj^T fp16

// ---------------- PTX helpers (base-target sm_80+ only) ----------------
static __device__ __forceinline__ uint32_t smem_u32(const void* p) {
    uint32_t a;
    asm("{ .reg .u64 t; cvta.to.shared.u64 t, %1; cvt.u32.u64 %0, t; }" : "=r"(a) : "l"(p));
    return a;
}
static __device__ __forceinline__ void cp_async16(uint32_t dst, const void* src) {
    asm volatile("cp.async.cg.shared.global [%0], [%1], 16;" :: "r"(dst), "l"(src) : "memory");
}
static __device__ __forceinline__ void cp_commit() {
    asm volatile("cp.async.commit_group;" ::: "memory");
}
static __device__ __forceinline__ void cp_wait1() {
    asm volatile("cp.async.wait_group 1;" ::: "memory");
}
static __device__ __forceinline__ void cp_wait2() {
    asm volatile("cp.async.wait_group 2;" ::: "memory");
}
static __device__ __forceinline__ void ldsm_x4(uint32_t& r0, uint32_t& r1, uint32_t& r2,
                                               uint32_t& r3, uint32_t addr) {
    asm volatile("ldmatrix.sync.aligned.m8n8.x4.shared.b16 {%0,%1,%2,%3}, [%4];"
                 : "=r"(r0), "=r"(r1), "=r"(r2), "=r"(r3) : "r"(addr));
}
static __device__ __forceinline__ void mma_f16(float* d, const uint32_t* a,
                                               uint32_t b0, uint32_t b1) {
    asm volatile(
        "mma.sync.aligned.m16n8k16.row.col.f32.f16.f16.f32 "
        "{%0,%1,%2,%3}, {%4,%5,%6,%7}, {%8,%9}, {%0,%1,%2,%3};"
        : "+f"(d[0]), "+f"(d[1]), "+f"(d[2]), "+f"(d[3])
        : "r"(a[0]), "r"(a[1]), "r"(a[2]), "r"(a[3]), "r"(b0), "r"(b1));
}
static __device__ __forceinline__ float ex2f(float x) {
    float r;
    asm("ex2.approx.f32 %0, %1;" : "=f"(r) : "f"(x));
    return r;
}
static __device__ __forceinline__ uint32_t ex2h2(__half2 x) {
    uint32_t r;
    uint32_t xi = *reinterpret_cast<uint32_t*>(&x);
    asm("ex2.approx.f16x2 %0, %1;" : "=r"(r) : "r"(xi));
    return r;
}
static __device__ __forceinline__ uint32_t sw128(uint32_t o) {
    return o ^ ((o >> 3) & 0x70);
}

// ---------------- HMMA GEMM: C = A @ B^T + bias (single fp16) ----------------
// CTA 128x128, 8 warps (4Mx2N, warp tile 32x64), BK=64, 3-stage, 2 CTAs/SM.
#define GBM 128
#define GBN 128
#define GBK 64
#define G_STG 32768
#define SM_TOTAL (3 * G_STG)

template <bool HALF_OUT>
__global__ __launch_bounds__(256, 2)
void gemm_f16(const __half* __restrict__ A, const __half* __restrict__ B,
              const float* __restrict__ bias, float* __restrict__ C,
              __half* __restrict__ Ch, int M, int N, int K)
{
    extern __shared__ char smem[];
    const uint32_t sbase = smem_u32(smem);
    const int t = threadIdx.x, lane = t & 31, w = t >> 5;
    const int wm = (w >> 1) * 32;
    const int wn = (w & 1) * 64;
    const int bm = blockIdx.y * GBM, bn = blockIdx.x * GBN;

    const int lr = t >> 3;
    const int lc = (t & 7) * 16;
    const size_t Kb = (size_t)K * 2;
    const char* pA = (const char*)A + (size_t)(bm + lr) * Kb + lc;
    const char* pB = (const char*)B + (size_t)(bn + lr) * Kb + lc;

    auto issue = [&](int c) {
        const uint32_t sb = sbase + (c % 3) * G_STG;
        const size_t go = (size_t)c * 128;
        #pragma unroll
        for (int rr = 0; rr < 4; rr++) {
            uint32_t so = sw128((uint32_t)(lr + rr * 32) * 128 + lc);
            cp_async16(sb + so,         pA + (size_t)rr * 32 * Kb + go);
            cp_async16(sb + 16384 + so, pB + (size_t)rr * 32 * Kb + go);
        }
    };

    float acc[2][8][4] = {};
    const int nc = K / GBK;

    issue(0); cp_commit();
    issue(1); cp_commit();
    issue(2); cp_commit();

    const int frow = lane & 15;
    const int fcol = (lane >> 4) * 16;

    for (int c = 0; c < nc; c++) {
        cp_wait2();
        __syncthreads();
        const uint32_t sb = sbase + (c % 3) * G_STG;

        #pragma unroll
        for (int ks = 0; ks < GBK / 16; ks++) {
            const int kb = ks * 32 + fcol;
            uint32_t af[2][4];
            #pragma unroll
            for (int mt = 0; mt < 2; mt++) {
                uint32_t o = sw128((uint32_t)(wm + mt * 16 + frow) * 128 + kb);
                ldsm_x4(af[mt][0], af[mt][1], af[mt][2], af[mt][3], sb + o);
            }
            uint32_t bf[4][4];
            #pragma unroll
            for (int nt = 0; nt < 4; nt++) {
                uint32_t o = sw128((uint32_t)(wn + nt * 16 + frow) * 128 + kb);
                ldsm_x4(bf[nt][0], bf[nt][1], bf[nt][2], bf[nt][3], sb + 16384 + o);
            }
            #pragma unroll
            for (int nt = 0; nt < 4; nt++)
                #pragma unroll
                for (int mt = 0; mt < 2; mt++)
                    #pragma unroll
                    for (int hf = 0; hf < 2; hf++)
                        mma_f16(acc[mt][nt * 2 + hf], af[mt], bf[nt][hf], bf[nt][hf + 2]);
        }
        __syncthreads();
        if (c + 3 < nc) issue(c + 3);
        cp_commit();
    }

    const int g = lane >> 2, tc = lane & 3;
    #pragma unroll
    for (int mt = 0; mt < 2; mt++) {
        const int row0 = bm + wm + mt * 16 + g;
        #pragma unroll
        for (int j = 0; j < 8; j++) {
            const int col = bn + wn + j * 8 + tc * 2;
            float b0 = bias[col], b1 = bias[col + 1];
            float* d = acc[mt][j];
            float v00 = d[0] + b0, v01 = d[1] + b1;
            float v10 = d[2] + b0, v11 = d[3] + b1;
            if constexpr (HALF_OUT) {
                *(__half2*)(Ch + (size_t)row0 * N + col) = __floats2half2_rn(v00, v01);
                *(__half2*)(Ch + (size_t)(row0 + 8) * N + col) = __floats2half2_rn(v10, v11);
            } else {
                *(float2*)(C + (size_t)row0 * N + col) = make_float2(v00, v01);
                *(float2*)(C + (size_t)(row0 + 8) * N + col) = make_float2(v10, v11);
            }
        }
    }
}

// ---------------- fp32 -> fp16 ----------------
__global__ void conv_f16(const float* __restrict__ x, __half* __restrict__ h, int n)
{
    int i = (blockIdx.x * blockDim.x + threadIdx.x) * 4;
    if (i >= n) return;
    float4 v = *(const float4*)(x + i);
    *(__half2*)(h + i)     = __floats2half2_rn(v.x, v.y);
    *(__half2*)(h + i + 2) = __floats2half2_rn(v.z, v.w);
}

// ---------------- both weight transposes in ONE launch ----------------
__global__ void conv_t_both(const float* __restrict__ Wa, const float* __restrict__ Wp,
                            __half* __restrict__ ba, __half* __restrict__ bp)
{
    __shared__ float tile[32][33];
    const int bx = blockIdx.x;
    const float* W;
    __half* outp;
    int N, n0;
    if (bx < 96) { W = Wa; outp = ba; N = C3;    n0 = bx * 32; }
    else         { W = Wp; outp = bp; N = C_EMB; n0 = (bx - 96) * 32; }
    const int k0 = blockIdx.y * 32;
    const int tx = threadIdx.x, ty = threadIdx.y;
    #pragma unroll
    for (int j = 0; j < 32; j += 8)
        tile[ty + j][tx] = W[(size_t)(k0 + ty + j) * N + n0 + tx];
    __syncthreads();
    #pragma unroll
    for (int j = 0; j < 32; j += 8)
        outp[(size_t)(n0 + ty + j) * C_EMB + k0 + tx] = __float2half(tile[tx][ty + j]);
}

// ---------------- V part of qkv -> V^T [b][h][d][T] ----------------
__global__ void vtrans(const __half* __restrict__ qh, __half* __restrict__ vt)
{
    __shared__ __half tile[32][33];
    const int bh = blockIdx.z, b = bh >> 4, h = bh & 15;
    const int t0 = blockIdx.x * 32, d0 = blockIdx.y * 32;
    const int tx = threadIdx.x, ty = threadIdx.y;
    #pragma unroll
    for (int j = 0; j < 32; j += 8)
        tile[ty + j][tx] = qh[(size_t)(b * T_SEQ + t0 + ty + j) * C3 + 2 * C_EMB + h * HDIM + d0 + tx];
    __syncthreads();
    #pragma unroll
    for (int j = 0; j < 32; j += 8)
        vt[((size_t)(b * NHEAD + h) * HDIM + d0 + ty + j) * T_SEQ + t0 + tx] = tile[tx][ty + j];
}

// ---------------- HMMA flash attention (causal), single fp16 ----------------
// CTA: 64 q rows x (b,h); 4 warps x 16 rows; 128-key tiles, 2-stage pipeline.
// P computed with ex2.approx.f16x2 (MUFU halved; output IS the MMA fragment).
// Row-sum via tensor core (ones block); scale folded with FFMA into exp2 arg.
#define A_SQ   0
#define A_ONES 8192
#define A_SK   10240
#define A_STG  32768
#define A_SMEM (A_SK + 2 * A_STG)   // 75776 -> 3 CTAs/SM

__global__ __launch_bounds__(128, 3)
void attn_f16(const __half* __restrict__ qkv, const __half* __restrict__ vt,
              __half* __restrict__ y)
{
    extern __shared__ char smem[];
    const uint32_t sb = smem_u32(smem);
    const int t = threadIdx.x, lane = t & 31, w = t >> 5;   // w in 0..3
    const int qb = gridDim.x - 1 - blockIdx.x;   // heavy blocks first
    const int h = blockIdx.y, b = blockIdx.z;
    const int Q0 = qb * 64;
    const int nkt = (Q0 >> 7) + 1;               // 128-key tiles

    const int lr = t >> 3;          // 0..15
    const int lc = (t & 7) * 16;
    const char* qb8 = (const char*)qkv;
    const char* vb8 = (const char*)vt;

    // init ones block (row 0 = 1.0h across 64 halves, rest 0)
    {
        uint32_t v = (t < 8) ? 0x3C003C00u : 0u;
        *(uint4*)(smem + A_ONES + t * 16) = make_uint4(v, v, v, v);
    }

    auto issueQ = [&]() {
        #pragma unroll
        for (int rr = 0; rr < 4; rr++) {
            int row = lr + rr * 16;
            size_t g = ((size_t)(b * T_SEQ + Q0 + row) * C3 + h * HDIM) * 2 + lc;
            cp_async16(sb + A_SQ + sw128((uint32_t)row * 128 + lc), qb8 + g);
        }
    };
    auto issueKV = [&](int kt) {
        uint32_t s0 = sb + A_SK + (kt & 1) * A_STG;
        #pragma unroll
        for (int rr = 0; rr < 8; rr++) {
            int row = lr + rr * 16;
            uint32_t so = sw128((uint32_t)row * 128 + lc);
            size_t gk = ((size_t)(b * T_SEQ + kt * 128 + row) * C3 + C_EMB + h * HDIM) * 2 + lc;
            cp_async16(s0 + so, qb8 + gk);
        }
        #pragma unroll
        for (int j = 0; j < 2; j++) {
            #pragma unroll
            for (int rr = 0; rr < 4; rr++) {
                int row = lr + rr * 16;
                uint32_t so = sw128((uint32_t)row * 128 + lc) + j * 8192;
                size_t gv = (((size_t)(b * NHEAD + h) * HDIM + row) * T_SEQ
                             + kt * 128 + j * 64) * 2 + lc;
                cp_async16(s0 + 16384 + so, vb8 + gv);
            }
        }
    };

    issueQ(); issueKV(0); cp_commit();
    if (nkt > 1) issueKV(1);
    cp_commit();

    const int frow = lane & 15;
    const int fcol = (lane >> 4) * 16;
    const int g = lane >> 2, tc = lane & 3;

    cp_wait1();
    __syncthreads();

    uint32_t qf[4][4];
    #pragma unroll
    for (int ks = 0; ks < 4; ks++) {
        uint32_t o = sw128((uint32_t)(w * 16 + frow) * 128 + ks * 32 + fcol);
        ldsm_x4(qf[ks][0], qf[ks][1], qf[ks][2], qf[ks][3], sb + A_SQ + o);
    }
    // ones B-fragment (constant; hoisted)
    uint32_t of[4];
    ldsm_x4(of[0], of[1], of[2], of[3], sb + A_ONES + sw128((uint32_t)frow * 128 + fcol));

    float oacc[8][4] = {};
    float sumacc[4] = {};
    float mprev0 = -1e30f, mprev1 = -1e30f;
    const int r0 = Q0 + w * 16 + g;
    const int r1 = r0 + 8;

    for (int kt = 0; kt < nkt; kt++) {
        if (kt > 0) { cp_wait1(); __syncthreads(); }
        const uint32_t s0 = sb + A_SK + (kt & 1) * A_STG;
        const bool diag = (kt == nkt - 1);
        int ngmax = 8;
        if (diag) {
            ngmax = ((Q0 & 127) >> 4) + w + 1;
            if (ngmax > 8) ngmax = 8;
        }

        // ---- S = Q K^T  (static unroll + predicate) ----
        float s[16][4] = {};
        #pragma unroll
        for (int ng = 0; ng < 8; ng++) {
            if (ng < ngmax) {
                #pragma unroll
                for (int ks = 0; ks < 4; ks++) {
                    uint32_t o = sw128((uint32_t)(ng * 16 + frow) * 128 + ks * 32 + fcol);
                    uint32_t kh[4];
                    ldsm_x4(kh[0], kh[1], kh[2], kh[3], s0 + o);
                    #pragma unroll
                    for (int hf = 0; hf < 2; hf++)
                        mma_f16(s[ng * 2 + hf], qf[ks], kh[hf], kh[hf + 2]);
                }
            }
        }

        // ---- causal mask: pure selection (scale folded into FFMA below) ----
        if (diag) {
            #pragma unroll
            for (int i = 0; i < 16; i++) {
                int kk = kt * 128 + i * 8 + tc * 2;
                if (kk     > r0) s[i][0] = -1e30f;
                if (kk + 1 > r0) s[i][1] = -1e30f;
                if (kk     > r1) s[i][2] = -1e30f;
                if (kk + 1 > r1) s[i][3] = -1e30f;
            }
        }

        // ---- online softmax (raw-domain max; scaled-domain running state) ----
        float mx0 = -1e30f, mx1 = -1e30f;
        #pragma unroll
        for (int i = 0; i < 16; i++) {
            mx0 = fmaxf(mx0, fmaxf(s[i][0], s[i][1]));
            mx1 = fmaxf(mx1, fmaxf(s[i][2], s[i][3]));
        }
        mx0 = fmaxf(mx0, __shfl_xor_sync(0xffffffffu, mx0, 1));
        mx0 = fmaxf(mx0, __shfl_xor_sync(0xffffffffu, mx0, 2));
        mx1 = fmaxf(mx1, __shfl_xor_sync(0xffffffffu, mx1, 1));
        mx1 = fmaxf(mx1, __shfl_xor_sync(0xffffffffu, mx1, 2));
        float mn0 = fmaxf(mprev0, mx0 * SCALE2), mn1 = fmaxf(mprev1, mx1 * SCALE2);
        float cf0 = ex2f(mprev0 - mn0), cf1 = ex2f(mprev1 - mn1);
        mprev0 = mn0; mprev1 = mn1;

        // ---- P = ex2.f16x2(fma(s, SCALE2, -mn))  — packed fragments directly ----
        uint32_t ph2[16][2];
        #pragma unroll
        for (int i = 0; i < 16; i++) {
            float a0 = fmaf(s[i][0], SCALE2, -mn0);
            float a1 = fmaf(s[i][1], SCALE2, -mn0);
            float a2 = fmaf(s[i][2], SCALE2, -mn1);
            float a3 = fmaf(s[i][3], SCALE2, -mn1);
            ph2[i][0] = ex2h2(__floats2half2_rn(a0, a1));
            ph2[i][1] = ex2h2(__floats2half2_rn(a2, a3));
        }

        #pragma unroll
        for (int i = 0; i < 8; i++) {
            oacc[i][0] *= cf0; oacc[i][1] *= cf0;
            oacc[i][2] *= cf1; oacc[i][3] *= cf1;
        }
        sumacc[0] *= cf0; sumacc[1] *= cf0;
        sumacc[2] *= cf1; sumacc[3] *= cf1;

        // ---- O += P @ V; sum += P @ ones  (static unroll + predicate) ----
        #pragma unroll
        for (int kg = 0; kg < 8; kg++) {
            if (kg < ngmax) {
                const int h2i = kg >> 2, ks = kg & 3;
                uint32_t ph[4] = { ph2[2 * kg][0], ph2[2 * kg][1],
                                   ph2[2 * kg + 1][0], ph2[2 * kg + 1][1] };
                #pragma unroll
                for (int ng = 0; ng < 4; ng++) {
                    uint32_t o = sw128((uint32_t)(ng * 16 + frow) * 128 + ks * 32 + fcol)
                                 + h2i * 8192;
                    uint32_t v4[4];
                    ldsm_x4(v4[0], v4[1], v4[2], v4[3], s0 + 16384 + o);
                    #pragma unroll
                    for (int hf = 0; hf < 2; hf++)
                        mma_f16(oacc[ng * 2 + hf], ph, v4[hf], v4[hf + 2]);
                }
                mma_f16(sumacc, ph, of[0], of[2]);   // row-sum column
            }
        }

        __syncthreads();
        if (kt + 2 < nkt) issueKV(kt + 2);
        cp_commit();
    }

    // ---- epilogue: broadcast row-sum from tc==0 lane, divide, store fp16 ----
    float sum0 = __shfl_sync(0xffffffffu, sumacc[0], lane & ~3);
    float sum1 = __shfl_sync(0xffffffffu, sumacc[2], lane & ~3);
    float inv0 = 1.f / sum0, inv1 = 1.f / sum1;
    size_t row0 = (size_t)(b * T_SEQ + Q0 + w * 16 + g);
    #pragma unroll
    for (int i = 0; i < 8; i++) {
        int col = h * HDIM + i * 8 + tc * 2;
        *(__half2*)(y + row0 * C_EMB + col) =
            __floats2half2_rn(oacc[i][0] * inv0, oacc[i][1] * inv0);
        *(__half2*)(y + (row0 + 8) * C_EMB + col) =
            __floats2half2_rn(oacc[i][2] * inv1, oacc[i][3] * inv1);
    }
}

// ---------------- launch ----------------
extern "C" void kernel_launch(void* const* d_in, const int* in_sizes, int n_in,
                              void* d_out, int out_size)
{
    const float* x      = (const float*)d_in[0];
    const float* W_attn = (const float*)d_in[1];
    const float* b_attn = (const float*)d_in[2];
    const float* W_proj = (const float*)d_in[3];
    const float* b_proj = (const float*)d_in[4];
    float* out = (float*)d_out;

    __half *qkv, *vt, *a, *bw, *bw2;
    cudaGetSymbolAddress((void**)&qkv, g_qkv);
    cudaGetSymbolAddress((void**)&vt, g_vt);
    cudaGetSymbolAddress((void**)&a, g_a);
    cudaGetSymbolAddress((void**)&bw, g_b);
    cudaGetSymbolAddress((void**)&bw2, g_b2);

    cudaFuncSetAttribute(gemm_f16<true>,  cudaFuncAttributeMaxDynamicSharedMemorySize, SM_TOTAL);
    cudaFuncSetAttribute(gemm_f16<false>, cudaFuncAttributeMaxDynamicSharedMemorySize, SM_TOTAL);
    cudaFuncSetAttribute(attn_f16, cudaFuncAttributeMaxDynamicSharedMemorySize, A_SMEM);

    const int nx = BT * C_EMB;

    conv_f16<<<nx / 4 / 256, 256>>>(x, a, nx);
    conv_t_both<<<dim3(96 + 32, C_EMB / 32), dim3(32, 8)>>>(W_attn, W_proj, bw, bw2);
    gemm_f16<true><<<dim3(C3 / GBN, BT / GBM), 256, SM_TOTAL>>>(
        a, bw, b_attn, nullptr, qkv, BT, C3, C_EMB);
    vtrans<<<dim3(T_SEQ / 32, HDIM / 32, BATCH * NHEAD), dim3(32, 8)>>>(qkv, vt);
    attn_f16<<<dim3(T_SEQ / 64, NHEAD, BATCH), 128, A_SMEM>>>(qkv, vt, a);
    gemm_f16<false><<<dim3(C_EMB / GBN, BT / GBM), 256, SM_TOTAL>>>(
        a, bw2, b_proj, out, nullptr, BT, C_EMB, C_EMB);
}

// round 12
// speedup vs baseline: 7.4972x; 1.0623x over previous
#include <cuda_runtime.h>
#include <cuda_fp16.h>
#include <cstdint>

#define BATCH   2
#define T_SEQ   2048
#define C_EMB   1024
#define NHEAD   16
#define HDIM    64
#define BT      (BATCH * T_SEQ)      // 4096
#define C3      (3 * C_EMB)          // 3072

// 0.125 * log2(e)  — folds softmax scale into the exp2 domain
#define SCALE2  0.18033688011112043f

// ---------------- scratch (device globals) ----------------
__device__ __half g_qkv[(size_t)BT * C3];                       // q,k used; v region unused
__device__ __half g_vt[(size_t)BATCH * NHEAD * HDIM * T_SEQ];   // V^T (written by gemm1)
__device__ __half g_a[(size_t)BT * C_EMB];                      // activation (x, then y)
__device__ __half g_b[(size_t)C3 * C_EMB];                      // W_attn^T fp16
__device__ __half g_b2[(size_t)C_EMB * C_EMB];                  // W_proj^T fp16

// ---------------- PTX helpers (base-target sm_80+ only) ----------------
static __device__ __forceinline__ uint32_t smem_u32(const void* p) {
    uint32_t a;
    asm("{ .reg .u64 t; cvta.to.shared.u64 t, %1; cvt.u32.u64 %0, t; }" : "=r"(a) : "l"(p));
    return a;
}
static __device__ __forceinline__ void cp_async16(uint32_t dst, const void* src) {
    asm volatile("cp.async.cg.shared.global [%0], [%1], 16;" :: "r"(dst), "l"(src) : "memory");
}
static __device__ __forceinline__ void cp_commit() {
    asm volatile("cp.async.commit_group;" ::: "memory");
}
static __device__ __forceinline__ void cp_wait1() {
    asm volatile("cp.async.wait_group 1;" ::: "memory");
}
static __device__ __forceinline__ void cp_wait2() {
    asm volatile("cp.async.wait_group 2;" ::: "memory");
}
static __device__ __forceinline__ void ldsm_x4(uint32_t& r0, uint32_t& r1, uint32_t& r2,
                                               uint32_t& r3, uint32_t addr) {
    asm volatile("ldmatrix.sync.aligned.m8n8.x4.shared.b16 {%0,%1,%2,%3}, [%4];"
                 : "=r"(r0), "=r"(r1), "=r"(r2), "=r"(r3) : "r"(addr));
}
static __device__ __forceinline__ void mma_f16(float* d, const uint32_t* a,
                                               uint32_t b0, uint32_t b1) {
    asm volatile(
        "mma.sync.aligned.m16n8k16.row.col.f32.f16.f16.f32 "
        "{%0,%1,%2,%3}, {%4,%5,%6,%7}, {%8,%9}, {%0,%1,%2,%3};"
        : "+f"(d[0]), "+f"(d[1]), "+f"(d[2]), "+f"(d[3])
        : "r"(a[0]), "r"(a[1]), "r"(a[2]), "r"(a[3]), "r"(b0), "r"(b1));
}
static __device__ __forceinline__ float ex2f(float x) {
    float r;
    asm("ex2.approx.f32 %0, %1;" : "=f"(r) : "f"(x));
    return r;
}
static __device__ __forceinline__ uint32_t ex2h2(__half2 x) {
    uint32_t r;
    uint32_t xi = *reinterpret_cast<uint32_t*>(&x);
    asm("ex2.approx.f16x2 %0, %1;" : "=r"(r) : "r"(xi));
    return r;
}
static __device__ __forceinline__ uint32_t sw128(uint32_t o) {
    return o ^ ((o >> 3) & 0x70);
}

// ---------------- HMMA GEMM: C = A @ B^T + bias (single fp16) ----------------
// CTA 128x128, 8 warps (4Mx2N, warp tile 32x64), BK=64, 3-stage, 2 CTAs/SM.
// VSPLIT (gemm1 only): N-blocks >= 2*C_EMB are the V third of qkv -> written
// TRANSPOSED into vt[b][h][d][T] instead of qkv (vtrans fused away).
#define GBM 128
#define GBN 128
#define GBK 64
#define G_STG 32768
#define SM_TOTAL (3 * G_STG)

template <bool HALF_OUT, bool VSPLIT>
__global__ __launch_bounds__(256, 2)
void gemm_f16(const __half* __restrict__ A, const __half* __restrict__ B,
              const float* __restrict__ bias, float* __restrict__ C,
              __half* __restrict__ Ch, __half* __restrict__ vt,
              int M, int N, int K)
{
    extern __shared__ char smem[];
    const uint32_t sbase = smem_u32(smem);
    const int t = threadIdx.x, lane = t & 31, w = t >> 5;
    const int wm = (w >> 1) * 32;
    const int wn = (w & 1) * 64;
    const int bm = blockIdx.y * GBM, bn = blockIdx.x * GBN;

    const int lr = t >> 3;
    const int lc = (t & 7) * 16;
    const size_t Kb = (size_t)K * 2;
    const char* pA = (const char*)A + (size_t)(bm + lr) * Kb + lc;
    const char* pB = (const char*)B + (size_t)(bn + lr) * Kb + lc;

    auto issue = [&](int c) {
        const uint32_t sb = sbase + (c % 3) * G_STG;
        const size_t go = (size_t)c * 128;
        #pragma unroll
        for (int rr = 0; rr < 4; rr++) {
            uint32_t so = sw128((uint32_t)(lr + rr * 32) * 128 + lc);
            cp_async16(sb + so,         pA + (size_t)rr * 32 * Kb + go);
            cp_async16(sb + 16384 + so, pB + (size_t)rr * 32 * Kb + go);
        }
    };

    float acc[2][8][4] = {};
    const int nc = K / GBK;

    issue(0); cp_commit();
    issue(1); cp_commit();
    issue(2); cp_commit();

    const int frow = lane & 15;
    const int fcol = (lane >> 4) * 16;

    for (int c = 0; c < nc; c++) {
        cp_wait2();
        __syncthreads();
        const uint32_t sb = sbase + (c % 3) * G_STG;

        #pragma unroll
        for (int ks = 0; ks < GBK / 16; ks++) {
            const int kb = ks * 32 + fcol;
            uint32_t af[2][4];
            #pragma unroll
            for (int mt = 0; mt < 2; mt++) {
                uint32_t o = sw128((uint32_t)(wm + mt * 16 + frow) * 128 + kb);
                ldsm_x4(af[mt][0], af[mt][1], af[mt][2], af[mt][3], sb + o);
            }
            uint32_t bf[4][4];
            #pragma unroll
            for (int nt = 0; nt < 4; nt++) {
                uint32_t o = sw128((uint32_t)(wn + nt * 16 + frow) * 128 + kb);
                ldsm_x4(bf[nt][0], bf[nt][1], bf[nt][2], bf[nt][3], sb + 16384 + o);
            }
            #pragma unroll
            for (int nt = 0; nt < 4; nt++)
                #pragma unroll
                for (int mt = 0; mt < 2; mt++)
                    #pragma unroll
                    for (int hf = 0; hf < 2; hf++)
                        mma_f16(acc[mt][nt * 2 + hf], af[mt], bf[nt][hf], bf[nt][hf + 2]);
        }
        __syncthreads();
        if (c + 3 < nc) issue(c + 3);
        cp_commit();
    }

    const int g = lane >> 2, tc = lane & 3;
    const bool isV = VSPLIT && (bn >= 2 * C_EMB);
    #pragma unroll
    for (int mt = 0; mt < 2; mt++) {
        const int row0 = bm + wm + mt * 16 + g;
        #pragma unroll
        for (int j = 0; j < 8; j++) {
            const int col = bn + wn + j * 8 + tc * 2;
            float b0 = bias[col], b1 = bias[col + 1];
            float* d = acc[mt][j];
            float v00 = d[0] + b0, v01 = d[1] + b1;
            float v10 = d[2] + b0, v11 = d[3] + b1;
            if constexpr (VSPLIT) {
                if (isV) {
                    // transposed V write: vt[b][h][d][t]
                    const int vcol = col - 2 * C_EMB;
                    const int hh = vcol >> 6, dd = vcol & 63;
                    const int bb = row0 >> 11, tt = row0 & 2047;
                    size_t base = ((size_t)(bb * NHEAD + hh) * HDIM + dd) * T_SEQ + tt;
                    vt[base]             = __float2half(v00);   // (dd,   tt)
                    vt[base + T_SEQ]     = __float2half(v01);   // (dd+1, tt)
                    vt[base + 8]         = __float2half(v10);   // (dd,   tt+8)
                    vt[base + T_SEQ + 8] = __float2half(v11);   // (dd+1, tt+8)
                    continue;
                }
            }
            if constexpr (HALF_OUT) {
                *(__half2*)(Ch + (size_t)row0 * N + col) = __floats2half2_rn(v00, v01);
                *(__half2*)(Ch + (size_t)(row0 + 8) * N + col) = __floats2half2_rn(v10, v11);
            } else {
                *(float2*)(C + (size_t)row0 * N + col) = make_float2(v00, v01);
                *(float2*)(C + (size_t)(row0 + 8) * N + col) = make_float2(v10, v11);
            }
        }
    }
}

// ---------------- merged conversion kernel ----------------
// blocks [0, 4096):            x fp32 -> fp16 (g_a)
// blocks [4096, 4096+128*32):  W_attn / W_proj transpose -> fp16
__global__ void conv_all(const float* __restrict__ x, __half* __restrict__ a,
                         const float* __restrict__ Wa, const float* __restrict__ Wp,
                         __half* __restrict__ ba, __half* __restrict__ bp)
{
    __shared__ float tile[32][33];
    const int t = threadIdx.x;
    if (blockIdx.x < 4096) {
        int i = (blockIdx.x * 256 + t) * 4;
        float4 v = *(const float4*)(x + i);
        *(__half2*)(a + i)     = __floats2half2_rn(v.x, v.y);
        *(__half2*)(a + i + 2) = __floats2half2_rn(v.z, v.w);
        return;
    }
    const int bid = blockIdx.x - 4096;
    const int bxT = bid & 127;          // 0..127 (96 attn + 32 proj)
    const int k0  = (bid >> 7) * 32;    // 0..31 -> k offset
    const float* W;
    __half* outp;
    int N, n0;
    if (bxT < 96) { W = Wa; outp = ba; N = C3;    n0 = bxT * 32; }
    else          { W = Wp; outp = bp; N = C_EMB; n0 = (bxT - 96) * 32; }
    const int tx = t & 31, ty = t >> 5;   // 32 x 8
    #pragma unroll
    for (int j = 0; j < 32; j += 8)
        tile[ty + j][tx] = W[(size_t)(k0 + ty + j) * N + n0 + tx];
    __syncthreads();
    #pragma unroll
    for (int j = 0; j < 32; j += 8)
        outp[(size_t)(n0 + ty + j) * C_EMB + k0 + tx] = __float2half(tile[tx][ty + j]);
}

// ---------------- HMMA flash attention (causal), single fp16 ----------------
// CTA: 64 q rows x (b,h); 4 warps x 16 rows; 128-key tiles, 2-stage pipeline.
// P via ex2.approx.f16x2; row-sum via tensor core ones block.
#define A_SQ   0
#define A_ONES 8192
#define A_SK   10240
#define A_STG  32768
#define A_SMEM (A_SK + 2 * A_STG)   // 75776 -> 3 CTAs/SM

__global__ __launch_bounds__(128, 3)
void attn_f16(const __half* __restrict__ qkv, const __half* __restrict__ vt,
              __half* __restrict__ y)
{
    extern __shared__ char smem[];
    const uint32_t sb = smem_u32(smem);
    const int t = threadIdx.x, lane = t & 31, w = t >> 5;   // w in 0..3
    const int qb = gridDim.x - 1 - blockIdx.x;   // heavy blocks first
    const int h = blockIdx.y, b = blockIdx.z;
    const int Q0 = qb * 64;
    const int nkt = (Q0 >> 7) + 1;               // 128-key tiles

    const int lr = t >> 3;          // 0..15
    const int lc = (t & 7) * 16;
    const char* qb8 = (const char*)qkv;
    const char* vb8 = (const char*)vt;

    // init ones block (row 0 = 1.0h across 64 halves, rest 0)
    {
        uint32_t v = (t < 8) ? 0x3C003C00u : 0u;
        *(uint4*)(smem + A_ONES + t * 16) = make_uint4(v, v, v, v);
    }

    auto issueQ = [&]() {
        #pragma unroll
        for (int rr = 0; rr < 4; rr++) {
            int row = lr + rr * 16;
            size_t g = ((size_t)(b * T_SEQ + Q0 + row) * C3 + h * HDIM) * 2 + lc;
            cp_async16(sb + A_SQ + sw128((uint32_t)row * 128 + lc), qb8 + g);
        }
    };
    auto issueKV = [&](int kt) {
        uint32_t s0 = sb + A_SK + (kt & 1) * A_STG;
        #pragma unroll
        for (int rr = 0; rr < 8; rr++) {
            int row = lr + rr * 16;
            uint32_t so = sw128((uint32_t)row * 128 + lc);
            size_t gk = ((size_t)(b * T_SEQ + kt * 128 + row) * C3 + C_EMB + h * HDIM) * 2 + lc;
            cp_async16(s0 + so, qb8 + gk);
        }
        #pragma unroll
        for (int j = 0; j < 2; j++) {
            #pragma unroll
            for (int rr = 0; rr < 4; rr++) {
                int row = lr + rr * 16;
                uint32_t so = sw128((uint32_t)row * 128 + lc) + j * 8192;
                size_t gv = (((size_t)(b * NHEAD + h) * HDIM + row) * T_SEQ
                             + kt * 128 + j * 64) * 2 + lc;
                cp_async16(s0 + 16384 + so, vb8 + gv);
            }
        }
    };

    issueQ(); issueKV(0); cp_commit();
    if (nkt > 1) issueKV(1);
    cp_commit();

    const int frow = lane & 15;
    const int fcol = (lane >> 4) * 16;
    const int g = lane >> 2, tc = lane & 3;

    cp_wait1();
    __syncthreads();

    uint32_t qf[4][4];
    #pragma unroll
    for (int ks = 0; ks < 4; ks++) {
        uint32_t o = sw128((uint32_t)(w * 16 + frow) * 128 + ks * 32 + fcol);
        ldsm_x4(qf[ks][0], qf[ks][1], qf[ks][2], qf[ks][3], sb + A_SQ + o);
    }
    uint32_t of[4];
    ldsm_x4(of[0], of[1], of[2], of[3], sb + A_ONES + sw128((uint32_t)frow * 128 + fcol));

    float oacc[8][4] = {};
    float sumacc[4] = {};
    float mprev0 = -1e30f, mprev1 = -1e30f;
    const int r0 = Q0 + w * 16 + g;
    const int r1 = r0 + 8;

    for (int kt = 0; kt < nkt; kt++) {
        if (kt > 0) { cp_wait1(); __syncthreads(); }
        const uint32_t s0 = sb + A_SK + (kt & 1) * A_STG;
        const bool diag = (kt == nkt - 1);
        int ngmax = 8;
        if (diag) {
            ngmax = ((Q0 & 127) >> 4) + w + 1;
            if (ngmax > 8) ngmax = 8;
        }

        // ---- S = Q K^T  (static unroll + predicate) ----
        float s[16][4] = {};
        #pragma unroll
        for (int ng = 0; ng < 8; ng++) {
            if (ng < ngmax) {
                #pragma unroll
                for (int ks = 0; ks < 4; ks++) {
                    uint32_t o = sw128((uint32_t)(ng * 16 + frow) * 128 + ks * 32 + fcol);
                    uint32_t kh[4];
                    ldsm_x4(kh[0], kh[1], kh[2], kh[3], s0 + o);
                    #pragma unroll
                    for (int hf = 0; hf < 2; hf++)
                        mma_f16(s[ng * 2 + hf], qf[ks], kh[hf], kh[hf + 2]);
                }
            }
        }

        // ---- causal mask ----
        if (diag) {
            #pragma unroll
            for (int i = 0; i < 16; i++) {
                int kk = kt * 128 + i * 8 + tc * 2;
                if (kk     > r0) s[i][0] = -1e30f;
                if (kk + 1 > r0) s[i][1] = -1e30f;
                if (kk     > r1) s[i][2] = -1e30f;
                if (kk + 1 > r1) s[i][3] = -1e30f;
            }
        }

        // ---- online softmax ----
        float mx0 = -1e30f, mx1 = -1e30f;
        #pragma unroll
        for (int i = 0; i < 16; i++) {
            mx0 = fmaxf(mx0, fmaxf(s[i][0], s[i][1]));
            mx1 = fmaxf(mx1, fmaxf(s[i][2], s[i][3]));
        }
        mx0 = fmaxf(mx0, __shfl_xor_sync(0xffffffffu, mx0, 1));
        mx0 = fmaxf(mx0, __shfl_xor_sync(0xffffffffu, mx0, 2));
        mx1 = fmaxf(mx1, __shfl_xor_sync(0xffffffffu, mx1, 1));
        mx1 = fmaxf(mx1, __shfl_xor_sync(0xffffffffu, mx1, 2));
        float mn0 = fmaxf(mprev0, mx0 * SCALE2), mn1 = fmaxf(mprev1, mx1 * SCALE2);
        float cf0 = ex2f(mprev0 - mn0), cf1 = ex2f(mprev1 - mn1);
        mprev0 = mn0; mprev1 = mn1;

        // ---- P = ex2.f16x2(fma(s, SCALE2, -mn)) ----
        uint32_t ph2[16][2];
        #pragma unroll
        for (int i = 0; i < 16; i++) {
            float a0 = fmaf(s[i][0], SCALE2, -mn0);
            float a1 = fmaf(s[i][1], SCALE2, -mn0);
            float a2 = fmaf(s[i][2], SCALE2, -mn1);
            float a3 = fmaf(s[i][3], SCALE2, -mn1);
            ph2[i][0] = ex2h2(__floats2half2_rn(a0, a1));
            ph2[i][1] = ex2h2(__floats2half2_rn(a2, a3));
        }

        #pragma unroll
        for (int i = 0; i < 8; i++) {
            oacc[i][0] *= cf0; oacc[i][1] *= cf0;
            oacc[i][2] *= cf1; oacc[i][3] *= cf1;
        }
        sumacc[0] *= cf0; sumacc[1] *= cf0;
        sumacc[2] *= cf1; sumacc[3] *= cf1;

        // ---- O += P @ V; sum += P @ ones ----
        #pragma unroll
        for (int kg = 0; kg < 8; kg++) {
            if (kg < ngmax) {
                const int h2i = kg >> 2, ks = kg & 3;
                uint32_t ph[4] = { ph2[2 * kg][0], ph2[2 * kg][1],
                                   ph2[2 * kg + 1][0], ph2[2 * kg + 1][1] };
                #pragma unroll
                for (int ng = 0; ng < 4; ng++) {
                    uint32_t o = sw128((uint32_t)(ng * 16 + frow) * 128 + ks * 32 + fcol)
                                 + h2i * 8192;
                    uint32_t v4[4];
                    ldsm_x4(v4[0], v4[1], v4[2], v4[3], s0 + 16384 + o);
                    #pragma unroll
                    for (int hf = 0; hf < 2; hf++)
                        mma_f16(oacc[ng * 2 + hf], ph, v4[hf], v4[hf + 2]);
                }
                mma_f16(sumacc, ph, of[0], of[2]);
            }
        }

        __syncthreads();
        if (kt + 2 < nkt) issueKV(kt + 2);
        cp_commit();
    }

    // ---- epilogue ----
    float sum0 = __shfl_sync(0xffffffffu, sumacc[0], lane & ~3);
    float sum1 = __shfl_sync(0xffffffffu, sumacc[2], lane & ~3);
    float inv0 = 1.f / sum0, inv1 = 1.f / sum1;
    size_t row0 = (size_t)(b * T_SEQ + Q0 + w * 16 + g);
    #pragma unroll
    for (int i = 0; i < 8; i++) {
        int col = h * HDIM + i * 8 + tc * 2;
        *(__half2*)(y + row0 * C_EMB + col) =
            __floats2half2_rn(oacc[i][0] * inv0, oacc[i][1] * inv0);
        *(__half2*)(y + (row0 + 8) * C_EMB + col) =
            __floats2half2_rn(oacc[i][2] * inv1, oacc[i][3] * inv1);
    }
}

// ---------------- launch ----------------
extern "C" void kernel_launch(void* const* d_in, const int* in_sizes, int n_in,
                              void* d_out, int out_size)
{
    const float* x      = (const float*)d_in[0];
    const float* W_attn = (const float*)d_in[1];
    const float* b_attn = (const float*)d_in[2];
    const float* W_proj = (const float*)d_in[3];
    const float* b_proj = (const float*)d_in[4];
    float* out = (float*)d_out;

    __half *qkv, *vt, *a, *bw, *bw2;
    cudaGetSymbolAddress((void**)&qkv, g_qkv);
    cudaGetSymbolAddress((void**)&vt, g_vt);
    cudaGetSymbolAddress((void**)&a, g_a);
    cudaGetSymbolAddress((void**)&bw, g_b);
    cudaGetSymbolAddress((void**)&bw2, g_b2);

    cudaFuncSetAttribute((const void*)gemm_f16<true, true>,
                         cudaFuncAttributeMaxDynamicSharedMemorySize, SM_TOTAL);
    cudaFuncSetAttribute((const void*)gemm_f16<false, false>,
                         cudaFuncAttributeMaxDynamicSharedMemorySize, SM_TOTAL);
    cudaFuncSetAttribute((const void*)attn_f16,
                         cudaFuncAttributeMaxDynamicSharedMemorySize, A_SMEM);

    // 1) x->fp16 + both weight transposes (one launch)
    conv_all<<<4096 + 128 * 32, 256>>>(x, a, W_attn, W_proj, bw, bw2);
    // 2) qkv = x @ W_attn + b_attn; V third written transposed into vt
    gemm_f16<true, true><<<dim3(C3 / GBN, BT / GBM), 256, SM_TOTAL>>>(
        a, bw, b_attn, nullptr, qkv, vt, BT, C3, C_EMB);
    // 3) attention
    attn_f16<<<dim3(T_SEQ / 64, NHEAD, BATCH), 128, A_SMEM>>>(qkv, vt, a);
    // 4) out = y @ W_proj + b_proj
    gemm_f16<false, false><<<dim3(C_EMB / GBN, BT / GBM), 256, SM_TOTAL>>>(
        a, bw2, b_proj, out, nullptr, nullptr, BT, C_EMB, C_EMB);
}